// round 1
// baseline (speedup 1.0000x reference)
#include <cuda_runtime.h>
#include <math.h>

#define BATCH 128

// ---------------- scratch (static device globals; no runtime allocation) ----
__device__ float g_A[33554432];            // 134 MB max: conv1 out [128,64,64,64]
__device__ float g_B[8388608];             // 33.5 MB max: pool1 out [128,64,32,32]
__device__ float g_X[16 * 128 * 592];      // MLP input
__device__ float g_H[16 * 128 * 600];      // MLP hidden
__device__ float g_P1[16 * 128 * 10];      // pass-1 predictions
__device__ float g_mean[128];
__device__ float g_var[128];

// neighbor table for the fixed 4x4 grid (exact port of Brain.neighbors ordering)
// -1 = empty slot (mask 0)
__device__ const int c_nidx[16][8] = {
    {1, 4, 5, -1, -1, -1, -1, -1},
    {0, 2, 5, 4, 6, -1, -1, -1},
    {1, 3, 6, 5, 7, -1, -1, -1},
    {2, 7, 6, -1, -1, -1, -1, -1},
    {0, 5, 8, 1, 9, -1, -1, -1},
    {1, 4, 6, 9, 0, 2, 8, 10},
    {2, 5, 7, 10, 1, 3, 9, 11},
    {3, 6, 11, 2, 10, -1, -1, -1},
    {4, 9, 12, 5, 13, -1, -1, -1},
    {5, 8, 10, 13, 4, 6, 12, 14},
    {6, 9, 11, 14, 5, 7, 13, 15},
    {7, 10, 15, 6, 14, -1, -1, -1},
    {8, 13, 9, -1, -1, -1, -1, -1},
    {9, 12, 14, 8, 10, -1, -1, -1},
    {10, 13, 15, 9, 11, -1, -1, -1},
    {11, 14, 10, -1, -1, -1, -1, -1},
};

// ---------------- implicit-GEMM 3x3 SAME conv (NCHW) -----------------------
// O[co, n] = sum_k W[co,k] * im2col[k, n],  k = ci*9 + dy*3 + dx,
// n = b*HW + y*W + x.  BM=BN=64, BK=16, 256 threads, 4x4 microtile.
__global__ __launch_bounds__(256) void conv3x3_gemm(
    const float* __restrict__ in, const float* __restrict__ wgt,
    const float* __restrict__ bias, float* __restrict__ out,
    int Cin, int Cout, int H, int W, int hwsh, int wsh, int do_relu)
{
    const int K = Cin * 9;
    const int HW = H * W;
    __shared__ __align__(16) float As[16][68];
    __shared__ __align__(16) float Bs[16][68];

    const int tid = threadIdx.x;
    const int m0 = blockIdx.y * 64;
    const int n0 = blockIdx.x * 64;
    const int tm = tid >> 4;
    const int tn = tid & 15;

    float acc[4][4] = {};

    for (int k0 = 0; k0 < K; k0 += 16) {
        // load A tile (weights), coalesced along K
        #pragma unroll
        for (int i = 0; i < 4; i++) {
            int lin = tid + i * 256;
            int kk = lin & 15;
            int mm = lin >> 4;
            int gm = m0 + mm, gk = k0 + kk;
            As[kk][mm] = (gk < K) ? wgt[gm * K + gk] : 0.f;
        }
        // load B tile (im2col gather), coalesced along n (x direction)
        #pragma unroll
        for (int i = 0; i < 4; i++) {
            int lin = tid + i * 256;
            int nn = lin & 63;
            int kk = lin >> 6;
            int gk = k0 + kk;
            float v = 0.f;
            if (gk < K) {
                int ci = gk / 9;
                int f  = gk - ci * 9;
                int gn = n0 + nn;
                int b  = gn >> hwsh;
                int p  = gn & (HW - 1);
                int y  = (p >> wsh) + f / 3 - 1;
                int x  = (p & (W - 1)) + f % 3 - 1;
                if ((unsigned)y < (unsigned)H && (unsigned)x < (unsigned)W)
                    v = in[((b * Cin + ci) * H + y) * W + x];
            }
            Bs[kk][nn] = v;
        }
        __syncthreads();

        #pragma unroll
        for (int kk = 0; kk < 16; kk++) {
            float4 a4 = *(const float4*)&As[kk][tm * 4];
            float4 b4 = *(const float4*)&Bs[kk][tn * 4];
            float av[4] = {a4.x, a4.y, a4.z, a4.w};
            float bv[4] = {b4.x, b4.y, b4.z, b4.w};
            #pragma unroll
            for (int i = 0; i < 4; i++)
                #pragma unroll
                for (int j = 0; j < 4; j++)
                    acc[i][j] = fmaf(av[i], bv[j], acc[i][j]);
        }
        __syncthreads();
    }

    #pragma unroll
    for (int i = 0; i < 4; i++) {
        int co = m0 + tm * 4 + i;
        float bval = bias[co];
        #pragma unroll
        for (int j = 0; j < 4; j++) {
            int gn = n0 + tn * 4 + j;
            int b  = gn >> hwsh;
            int p  = gn & (HW - 1);
            float v = acc[i][j] + bval;
            if (do_relu) v = fmaxf(v, 0.f);
            out[(b * Cout + co) * HW + p] = v;
        }
    }
}

// ---------------- BatchNorm (training-mode batch stats) --------------------
__global__ void bn_stats(const float* __restrict__ x, float* __restrict__ mean,
                         float* __restrict__ var, int C, int HW, int hwsh)
{
    int c = blockIdx.x;
    __shared__ double ss[256], sq[256];
    double s = 0.0, q = 0.0;
    int cnt = BATCH * HW;
    for (int j = threadIdx.x; j < cnt; j += 256) {
        int b = j >> hwsh;
        int p = j & (HW - 1);
        float v = x[(b * C + c) * HW + p];
        s += (double)v;
        q += (double)v * (double)v;
    }
    ss[threadIdx.x] = s; sq[threadIdx.x] = q;
    __syncthreads();
    for (int st = 128; st > 0; st >>= 1) {
        if (threadIdx.x < st) {
            ss[threadIdx.x] += ss[threadIdx.x + st];
            sq[threadIdx.x] += sq[threadIdx.x + st];
        }
        __syncthreads();
    }
    if (threadIdx.x == 0) {
        double m = ss[0] / cnt;
        mean[c] = (float)m;
        var[c]  = (float)(sq[0] / cnt - m * m);
    }
}

__global__ void bn_apply_relu(float* __restrict__ x,
                              const float* __restrict__ g, const float* __restrict__ b,
                              const float* __restrict__ mean, const float* __restrict__ var,
                              int total, int hwsh, int cmask)
{
    for (int i = blockIdx.x * blockDim.x + threadIdx.x; i < total;
         i += gridDim.x * blockDim.x) {
        int c = (i >> hwsh) & cmask;
        float scale = g[c] * rsqrtf(var[c] + 1e-5f);
        float shift = b[c] - mean[c] * scale;
        float v = fmaf(x[i], scale, shift);
        x[i] = fmaxf(v, 0.f);
    }
}

// ---------------- MaxPool2d(kernel=3, stride=2, padding=1) -----------------
__global__ void maxpool3s2(const float* __restrict__ in, float* __restrict__ out,
                           int total, int H, int W, int owsh)
{
    int OW = W >> 1;
    for (int i = blockIdx.x * blockDim.x + threadIdx.x; i < total;
         i += gridDim.x * blockDim.x) {
        int ox = i & (OW - 1);
        int t  = i >> owsh;
        int oy = t & (OW - 1);
        int bc = t >> owsh;
        const float* src = in + (long long)bc * H * W;
        float m = -INFINITY;
        #pragma unroll
        for (int dy = 0; dy < 3; dy++) {
            int y = 2 * oy - 1 + dy;
            if ((unsigned)y >= (unsigned)H) continue;
            #pragma unroll
            for (int dx = 0; dx < 3; dx++) {
                int x = 2 * ox - 1 + dx;
                if ((unsigned)x >= (unsigned)W) continue;
                m = fmaxf(m, src[y * W + x]);
            }
        }
        out[i] = m;
    }
}

// ---------------- MLP stage 1: X[16,128,592] @ W1[16,592,600] + b1, tanh ----
__global__ __launch_bounds__(256) void gemm_bias_tanh(
    const float* __restrict__ A, const float* __restrict__ Bw,
    const float* __restrict__ bias, float* __restrict__ C)
{
    const int M = 128, N = 600, K = 592;
    const int node = blockIdx.z;
    A    += node * M * K;
    Bw   += node * K * N;
    bias += node * N;
    C    += node * M * N;

    __shared__ __align__(16) float As[16][68];
    __shared__ __align__(16) float Bs[16][68];

    const int tid = threadIdx.x;
    const int m0 = blockIdx.y * 64;
    const int n0 = blockIdx.x * 64;
    const int tm = tid >> 4;
    const int tn = tid & 15;

    float acc[4][4] = {};

    for (int k0 = 0; k0 < K; k0 += 16) {   // K=592 is a multiple of 16
        #pragma unroll
        for (int i = 0; i < 4; i++) {
            int lin = tid + i * 256;
            int kk = lin & 15;
            int mm = lin >> 4;
            As[kk][mm] = A[(m0 + mm) * K + k0 + kk];
        }
        #pragma unroll
        for (int i = 0; i < 4; i++) {
            int lin = tid + i * 256;
            int nn = lin & 63;
            int kk = lin >> 6;
            int gn = n0 + nn;
            Bs[kk][nn] = (gn < N) ? Bw[(k0 + kk) * N + gn] : 0.f;
        }
        __syncthreads();
        #pragma unroll
        for (int kk = 0; kk < 16; kk++) {
            float4 a4 = *(const float4*)&As[kk][tm * 4];
            float4 b4 = *(const float4*)&Bs[kk][tn * 4];
            float av[4] = {a4.x, a4.y, a4.z, a4.w};
            float bv[4] = {b4.x, b4.y, b4.z, b4.w};
            #pragma unroll
            for (int i = 0; i < 4; i++)
                #pragma unroll
                for (int j = 0; j < 4; j++)
                    acc[i][j] = fmaf(av[i], bv[j], acc[i][j]);
        }
        __syncthreads();
    }

    #pragma unroll
    for (int i = 0; i < 4; i++) {
        int m = m0 + tm * 4 + i;
        #pragma unroll
        for (int j = 0; j < 4; j++) {
            int gn = n0 + tn * 4 + j;
            if (gn < N)
                C[m * N + gn] = tanhf(acc[i][j] + bias[gn]);
        }
    }
}

// ---------------- MLP stage 2 + softmax: one warp per (node, b) ------------
__global__ void mlp2_softmax(const float* __restrict__ h, const float* __restrict__ W2,
                             const float* __restrict__ b2, float* __restrict__ out)
{
    int nb = blockIdx.x;            // 0..2047
    int node = nb >> 7;
    int b    = nb & 127;
    int lane = threadIdx.x;

    const float* hrow = h  + (node * 128 + b) * 600;
    const float* w    = W2 + node * 600 * 10;

    float acc[10];
    #pragma unroll
    for (int o = 0; o < 10; o++) acc[o] = 0.f;

    for (int i = lane; i < 600; i += 32) {
        float hv = hrow[i];
        const float* wr = w + i * 10;
        #pragma unroll
        for (int o = 0; o < 10; o++)
            acc[o] = fmaf(hv, wr[o], acc[o]);
    }
    #pragma unroll
    for (int o = 0; o < 10; o++)
        #pragma unroll
        for (int s = 16; s > 0; s >>= 1)
            acc[o] += __shfl_down_sync(0xffffffffu, acc[o], s);

    if (lane == 0) {
        float lg[10];
        float mx = -INFINITY;
        #pragma unroll
        for (int o = 0; o < 10; o++) {
            lg[o] = acc[o] + b2[node * 10 + o];
            mx = fmaxf(mx, lg[o]);
        }
        float se = 0.f;
        #pragma unroll
        for (int o = 0; o < 10; o++) { lg[o] = expf(lg[o] - mx); se += lg[o]; }
        float inv = 1.f / se;
        #pragma unroll
        for (int o = 0; o < 10; o++)
            out[(node * 128 + b) * 10 + o] = lg[o] * inv;
    }
}

// ---------------- head glue kernels ----------------------------------------
// X[n,b,0:80] = 0 ; X[n,b,80+c] = conv7[b, c, node n]   (conv7 in g_A, HW=16)
__global__ void build_X1(const float* __restrict__ conv7, float* __restrict__ X, int total)
{
    for (int i = blockIdx.x * blockDim.x + threadIdx.x; i < total;
         i += gridDim.x * blockDim.x) {
        int c = i % 592;
        int t = i / 592;
        int b = t & 127;
        int n = t >> 7;
        X[i] = (c < 80) ? 0.f : conv7[((b * 512 + (c - 80)) << 4) + n];
    }
}

// overwrite first 80 cols with gathered neighbor predictions (mask-padded)
__global__ void build_X2(const float* __restrict__ P1, float* __restrict__ X, int total)
{
    for (int i = blockIdx.x * blockDim.x + threadIdx.x; i < total;
         i += gridDim.x * blockDim.x) {
        int j = i % 80;
        int t = i / 80;
        int b = t & 127;
        int n = t >> 7;
        int s   = j / 10;
        int cls = j - s * 10;
        int nb  = c_nidx[n][s];
        float v = (nb >= 0) ? P1[(nb * 128 + b) * 10 + cls] : 0.f;
        X[(n * 128 + b) * 592 + j] = v;
    }
}

// out[0:1280] = (mean over 16 nodes of preds2)^2 ; preds2 lives at out+1280
__global__ void final_mean_sq(const float* __restrict__ preds2, float* __restrict__ out)
{
    int t = blockIdx.x * blockDim.x + threadIdx.x;
    if (t >= 1280) return;
    int b = t / 10, c = t - (t / 10) * 10;
    float s = 0.f;
    #pragma unroll
    for (int n = 0; n < 16; n++)
        s += preds2[(n * 128 + b) * 10 + c];
    s *= (1.f / 16.f);
    out[t] = s * s;
}

// ---------------- launcher ---------------------------------------------------
extern "C" void kernel_launch(void* const* d_in, const int* in_sizes, int n_in,
                              void* d_out, int out_size)
{
    const float* x     = (const float*)d_in[0];
    const float* cw1   = (const float*)d_in[1];
    const float* cb1   = (const float*)d_in[2];
    const float* bn1g  = (const float*)d_in[3];
    const float* bn1b  = (const float*)d_in[4];
    const float* cw2   = (const float*)d_in[5];
    const float* cb2   = (const float*)d_in[6];
    const float* bn2g  = (const float*)d_in[7];
    const float* bn2b  = (const float*)d_in[8];
    const float* cw3   = (const float*)d_in[9];
    const float* cb3   = (const float*)d_in[10];
    const float* cw4   = (const float*)d_in[11];
    const float* cb4   = (const float*)d_in[12];
    const float* cw5   = (const float*)d_in[13];
    const float* cb5   = (const float*)d_in[14];
    const float* cw6   = (const float*)d_in[15];
    const float* cb6   = (const float*)d_in[16];
    const float* cw7   = (const float*)d_in[17];
    const float* cb7   = (const float*)d_in[18];
    const float* W1    = (const float*)d_in[19];
    const float* b1    = (const float*)d_in[20];
    const float* W2    = (const float*)d_in[21];
    const float* b2    = (const float*)d_in[22];
    float* out = (float*)d_out;

    float *A, *Bb, *X, *H, *P1, *mean, *var;
    cudaGetSymbolAddress((void**)&A,    g_A);
    cudaGetSymbolAddress((void**)&Bb,   g_B);
    cudaGetSymbolAddress((void**)&X,    g_X);
    cudaGetSymbolAddress((void**)&H,    g_H);
    cudaGetSymbolAddress((void**)&P1,   g_P1);
    cudaGetSymbolAddress((void**)&mean, g_mean);
    cudaGetSymbolAddress((void**)&var,  g_var);

    // ---- conv1 (3->64, 64x64) + BN + ReLU + pool -> 32x32
    conv3x3_gemm<<<dim3(524288 / 64, 1), 256>>>(x, cw1, cb1, A, 3, 64, 64, 64, 12, 6, 0);
    bn_stats<<<64, 256>>>(A, mean, var, 64, 4096, 12);
    bn_apply_relu<<<32768, 256>>>(A, bn1g, bn1b, mean, var, 33554432, 12, 63);
    maxpool3s2<<<16384, 256>>>(A, Bb, 8388608, 64, 64, 5);

    // ---- conv2 (64->128, 32x32) + BN + ReLU + pool -> 16x16
    conv3x3_gemm<<<dim3(131072 / 64, 2), 256>>>(Bb, cw2, cb2, A, 64, 128, 32, 32, 10, 5, 0);
    bn_stats<<<128, 256>>>(A, mean, var, 128, 1024, 10);
    bn_apply_relu<<<16384, 256>>>(A, bn2g, bn2b, mean, var, 16777216, 10, 127);
    maxpool3s2<<<8192, 256>>>(A, Bb, 4194304, 32, 32, 4);

    // ---- conv3 (128->256, 16x16) relu
    conv3x3_gemm<<<dim3(32768 / 64, 4), 256>>>(Bb, cw3, cb3, A, 128, 256, 16, 16, 8, 4, 1);
    // ---- conv4 (256->256, 16x16) relu + pool -> 8x8
    conv3x3_gemm<<<dim3(32768 / 64, 4), 256>>>(A, cw4, cb4, Bb, 256, 256, 16, 16, 8, 4, 1);
    maxpool3s2<<<4096, 256>>>(Bb, A, 2097152, 16, 16, 3);

    // ---- conv5 (256->512, 8x8) relu
    conv3x3_gemm<<<dim3(8192 / 64, 8), 256>>>(A, cw5, cb5, Bb, 256, 512, 8, 8, 6, 3, 1);
    // ---- conv6 (512->512, 8x8) relu + pool -> 4x4
    conv3x3_gemm<<<dim3(8192 / 64, 8), 256>>>(Bb, cw6, cb6, A, 512, 512, 8, 8, 6, 3, 1);
    maxpool3s2<<<2048, 256>>>(A, Bb, 1048576, 8, 8, 2);

    // ---- conv7 (512->512, 4x4) relu  -> feats source in A
    conv3x3_gemm<<<dim3(2048 / 64, 8), 256>>>(Bb, cw7, cb7, A, 512, 512, 4, 4, 4, 2, 1);

    // ---- head: pass 1 (zero neighbor slots)
    build_X1<<<4736, 256>>>(A, X, 16 * 128 * 592);
    gemm_bias_tanh<<<dim3(10, 2, 16), 256>>>(X, W1, b1, H);
    mlp2_softmax<<<2048, 32>>>(H, W2, b2, P1);

    // ---- head: pass 2 (gathered neighbor predictions)
    build_X2<<<640, 256>>>(P1, X, 16 * 128 * 80);
    gemm_bias_tanh<<<dim3(10, 2, 16), 256>>>(X, W1, b1, H);
    mlp2_softmax<<<2048, 32>>>(H, W2, b2, out + 1280);   // preds2 -> out[1280:]

    // ---- squared mean over nodes -> out[0:1280]
    final_mean_sq<<<5, 256>>>(out + 1280, out);
}

// round 2
// speedup vs baseline: 1.2198x; 1.2198x over previous
#include <cuda_runtime.h>
#include <math.h>

#define BATCH 128

// ---------------- scratch (static device globals; no runtime allocation) ----
__device__ float g_A[33554432];            // 134 MB max: conv1 out [128,64,64,64]
__device__ float g_B[8388608];             // 33.5 MB max: pool1 out [128,64,32,32]
__device__ float g_X[16 * 128 * 592];      // MLP input
__device__ float g_H[16 * 128 * 600];      // MLP hidden
__device__ float g_P1[16 * 128 * 10];      // pass-1 predictions
__device__ float g_mean[128];
__device__ float g_var[128];

// neighbor table for the fixed 4x4 grid (exact port of Brain.neighbors ordering)
__device__ const int c_nidx[16][8] = {
    {1, 4, 5, -1, -1, -1, -1, -1},
    {0, 2, 5, 4, 6, -1, -1, -1},
    {1, 3, 6, 5, 7, -1, -1, -1},
    {2, 7, 6, -1, -1, -1, -1, -1},
    {0, 5, 8, 1, 9, -1, -1, -1},
    {1, 4, 6, 9, 0, 2, 8, 10},
    {2, 5, 7, 10, 1, 3, 9, 11},
    {3, 6, 11, 2, 10, -1, -1, -1},
    {4, 9, 12, 5, 13, -1, -1, -1},
    {5, 8, 10, 13, 4, 6, 12, 14},
    {6, 9, 11, 14, 5, 7, 13, 15},
    {7, 10, 15, 6, 14, -1, -1, -1},
    {8, 13, 9, -1, -1, -1, -1, -1},
    {9, 12, 14, 8, 10, -1, -1, -1},
    {10, 13, 15, 9, 11, -1, -1, -1},
    {11, 14, 10, -1, -1, -1, -1, -1},
};

// ============================================================================
// FAST implicit-GEMM 3x3 SAME conv (NCHW), K = Cin*9 multiple of 8.
// BM=128, BN in {128,64}, BK=8, 256 threads, 8x(BN/16) per-thread microtile,
// double-buffered smem, register-staged global loads, incremental im2col.
// ============================================================================
template<int Cin, int Cout, int H, int W, int BN, bool RELU>
__global__ __launch_bounds__(256, 2) void conv_fast(
    const float* __restrict__ in, const float* __restrict__ wgt,
    const float* __restrict__ bias, float* __restrict__ out)
{
    constexpr int K  = Cin * 9;
    constexpr int HW = H * W;
    constexpr int NK = K / 8;          // K is a multiple of 8 for Cin in {64,128,256,512}
    constexpr int TN = BN / 16;        // 8 or 4 output cols per thread
    constexpr int NS = BN / 32;        // B-gather slots per thread (4 or 2)

    __shared__ __align__(16) float As[2][8][128];
    __shared__ __align__(16) float Bs[2][8][BN];

    const int tid = threadIdx.x;
    const int m0  = blockIdx.y * 128;
    const int n0  = blockIdx.x * BN;
    const int tm  = tid >> 4;          // 0..15
    const int tn  = tid & 15;          // 0..15

    // ---- A (weights) load mapping: 2 threads per row, float4 each
    const int amm   = tid >> 1;                 // 0..127
    const int aks   = (tid & 1) * 4;            // 0 or 4
    const float* wptr = wgt + (m0 + amm) * K + aks;

    // ---- B (im2col) slot state
    int kks[NS], nns[NS];
    int f[NS], base2[NS], sy0[NS], sx0[NS];
    #pragma unroll
    for (int s = 0; s < NS; s++) {
        int lin = tid + s * 256;
        kks[s] = lin / BN;
        nns[s] = lin % BN;
        int gn = n0 + nns[s];
        int b  = gn / HW;
        int p  = gn % HW;
        int y0 = p / W;
        int x0 = p % W;
        sy0[s] = y0; sx0[s] = x0;
        f[s]   = kks[s];                     // gk starts at kk (<8<9 so ci=0)
        base2[s] = b * Cin * HW + y0 * W + x0 - W - 1;
    }

    float acc[8][TN];
    #pragma unroll
    for (int r = 0; r < 8; r++)
        #pragma unroll
        for (int c = 0; c < TN; c++) acc[r][c] = 0.f;

    float4 ra;
    float  rb[NS];

    // ---- prologue: load k-tile 0 into regs, store to smem buf 0
    ra = *(const float4*)wptr; wptr += 8;
    #pragma unroll
    for (int s = 0; s < NS; s++) {
        int dy = (f[s] * 11) >> 5;
        int dx = f[s] - 3 * dy;
        int y = sy0[s] + dy - 1, x = sx0[s] + dx - 1;
        float v = 0.f;
        if ((unsigned)y < (unsigned)H && (unsigned)x < (unsigned)W)
            v = __ldg(in + base2[s] + dy * W + dx);
        rb[s] = v;
        f[s] += 8; if (f[s] >= 9) { f[s] -= 9; base2[s] += HW; }
    }
    As[0][aks + 0][amm] = ra.x;
    As[0][aks + 1][amm] = ra.y;
    As[0][aks + 2][amm] = ra.z;
    As[0][aks + 3][amm] = ra.w;
    #pragma unroll
    for (int s = 0; s < NS; s++) Bs[0][kks[s]][nns[s]] = rb[s];
    __syncthreads();

    int buf = 0;
    for (int kt = 0; kt < NK; kt++) {
        const bool more = (kt + 1 < NK);
        if (more) {
            ra = *(const float4*)wptr; wptr += 8;
            #pragma unroll
            for (int s = 0; s < NS; s++) {
                int dy = (f[s] * 11) >> 5;
                int dx = f[s] - 3 * dy;
                int y = sy0[s] + dy - 1, x = sx0[s] + dx - 1;
                float v = 0.f;
                if ((unsigned)y < (unsigned)H && (unsigned)x < (unsigned)W)
                    v = __ldg(in + base2[s] + dy * W + dx);
                rb[s] = v;
                f[s] += 8; if (f[s] >= 9) { f[s] -= 9; base2[s] += HW; }
            }
        }

        #pragma unroll
        for (int kk = 0; kk < 8; kk++) {
            float4 a0 = *(const float4*)&As[buf][kk][tm * 4];
            float4 a1 = *(const float4*)&As[buf][kk][tm * 4 + 64];
            float av[8] = {a0.x, a0.y, a0.z, a0.w, a1.x, a1.y, a1.z, a1.w};
            float bv[TN];
            {
                float4 b0 = *(const float4*)&Bs[buf][kk][tn * 4];
                bv[0] = b0.x; bv[1] = b0.y; bv[2] = b0.z; bv[3] = b0.w;
                if (TN == 8) {
                    float4 b1 = *(const float4*)&Bs[buf][kk][tn * 4 + BN / 2];
                    bv[4] = b1.x; bv[5] = b1.y; bv[6] = b1.z; bv[7] = b1.w;
                }
            }
            #pragma unroll
            for (int r = 0; r < 8; r++)
                #pragma unroll
                for (int c = 0; c < TN; c++)
                    acc[r][c] = fmaf(av[r], bv[c], acc[r][c]);
        }

        if (more) {
            int nb = buf ^ 1;
            As[nb][aks + 0][amm] = ra.x;
            As[nb][aks + 1][amm] = ra.y;
            As[nb][aks + 2][amm] = ra.z;
            As[nb][aks + 3][amm] = ra.w;
            #pragma unroll
            for (int s = 0; s < NS; s++) Bs[nb][kks[s]][nns[s]] = rb[s];
            __syncthreads();
            buf = nb;
        }
    }

    // ---- epilogue: bias (+relu), float4 stores (HW multiple of 4, aligned)
    #pragma unroll
    for (int r = 0; r < 8; r++) {
        int co = m0 + tm * 4 + (r < 4 ? r : 60 + r);
        float bval = bias[co];
        #pragma unroll
        for (int cb = 0; cb < TN / 4; cb++) {
            int gn = n0 + tn * 4 + cb * (BN / 2);
            int b  = gn / HW;
            int p  = gn % HW;
            float4 v;
            v.x = acc[r][cb * 4 + 0] + bval;
            v.y = acc[r][cb * 4 + 1] + bval;
            v.z = acc[r][cb * 4 + 2] + bval;
            v.w = acc[r][cb * 4 + 3] + bval;
            if (RELU) {
                v.x = fmaxf(v.x, 0.f); v.y = fmaxf(v.y, 0.f);
                v.z = fmaxf(v.z, 0.f); v.w = fmaxf(v.w, 0.f);
            }
            *(float4*)&out[(b * Cout + co) * HW + p] = v;
        }
    }
}

// ---------------- generic implicit-GEMM (kept for conv1, K=27) -------------
__global__ __launch_bounds__(256) void conv3x3_gemm(
    const float* __restrict__ in, const float* __restrict__ wgt,
    const float* __restrict__ bias, float* __restrict__ out,
    int Cin, int Cout, int H, int W, int hwsh, int wsh, int do_relu)
{
    const int K = Cin * 9;
    const int HW = H * W;
    __shared__ __align__(16) float As[16][68];
    __shared__ __align__(16) float Bs[16][68];

    const int tid = threadIdx.x;
    const int m0 = blockIdx.y * 64;
    const int n0 = blockIdx.x * 64;
    const int tm = tid >> 4;
    const int tn = tid & 15;

    float acc[4][4] = {};

    for (int k0 = 0; k0 < K; k0 += 16) {
        #pragma unroll
        for (int i = 0; i < 4; i++) {
            int lin = tid + i * 256;
            int kk = lin & 15;
            int mm = lin >> 4;
            int gm = m0 + mm, gk = k0 + kk;
            As[kk][mm] = (gk < K) ? wgt[gm * K + gk] : 0.f;
        }
        #pragma unroll
        for (int i = 0; i < 4; i++) {
            int lin = tid + i * 256;
            int nn = lin & 63;
            int kk = lin >> 6;
            int gk = k0 + kk;
            float v = 0.f;
            if (gk < K) {
                int ci = gk / 9;
                int ff = gk - ci * 9;
                int gn = n0 + nn;
                int b  = gn >> hwsh;
                int p  = gn & (HW - 1);
                int y  = (p >> wsh) + ff / 3 - 1;
                int x  = (p & (W - 1)) + ff % 3 - 1;
                if ((unsigned)y < (unsigned)H && (unsigned)x < (unsigned)W)
                    v = in[((b * Cin + ci) * H + y) * W + x];
            }
            Bs[kk][nn] = v;
        }
        __syncthreads();

        #pragma unroll
        for (int kk = 0; kk < 16; kk++) {
            float4 a4 = *(const float4*)&As[kk][tm * 4];
            float4 b4 = *(const float4*)&Bs[kk][tn * 4];
            float av[4] = {a4.x, a4.y, a4.z, a4.w};
            float bv[4] = {b4.x, b4.y, b4.z, b4.w};
            #pragma unroll
            for (int i = 0; i < 4; i++)
                #pragma unroll
                for (int j = 0; j < 4; j++)
                    acc[i][j] = fmaf(av[i], bv[j], acc[i][j]);
        }
        __syncthreads();
    }

    #pragma unroll
    for (int i = 0; i < 4; i++) {
        int co = m0 + tm * 4 + i;
        float bval = bias[co];
        #pragma unroll
        for (int j = 0; j < 4; j++) {
            int gn = n0 + tn * 4 + j;
            int b  = gn >> hwsh;
            int p  = gn & (HW - 1);
            float v = acc[i][j] + bval;
            if (do_relu) v = fmaxf(v, 0.f);
            out[(b * Cout + co) * HW + p] = v;
        }
    }
}

// ---------------- BatchNorm stats (training-mode) ---------------------------
__global__ void bn_stats(const float* __restrict__ x, float* __restrict__ mean,
                         float* __restrict__ var, int C, int HW, int hwsh)
{
    int c = blockIdx.x;
    __shared__ double ss[256], sq[256];
    double s = 0.0, q = 0.0;
    int cnt = BATCH * HW;
    for (int j = threadIdx.x; j < cnt; j += 256) {
        int b = j >> hwsh;
        int p = j & (HW - 1);
        float v = x[(b * C + c) * HW + p];
        s += (double)v;
        q += (double)v * (double)v;
    }
    ss[threadIdx.x] = s; sq[threadIdx.x] = q;
    __syncthreads();
    for (int st = 128; st > 0; st >>= 1) {
        if (threadIdx.x < st) {
            ss[threadIdx.x] += ss[threadIdx.x + st];
            sq[threadIdx.x] += sq[threadIdx.x + st];
        }
        __syncthreads();
    }
    if (threadIdx.x == 0) {
        double m = ss[0] / cnt;
        mean[c] = (float)m;
        var[c]  = (float)(sq[0] / cnt - m * m);
    }
}

// ---------------- fused BN-apply + ReLU + MaxPool(3,2,1) --------------------
// in: [B, C, H, H] conv output; out: [B, C, H/2, H/2]
__global__ void bn_relu_pool(const float* __restrict__ in, float* __restrict__ out,
                             const float* __restrict__ g, const float* __restrict__ bta,
                             const float* __restrict__ mean, const float* __restrict__ var,
                             int total, int H, int owsh, int cmask)
{
    int OW = H >> 1;
    for (int i = blockIdx.x * blockDim.x + threadIdx.x; i < total;
         i += gridDim.x * blockDim.x) {
        int ox = i & (OW - 1);
        int oy = (i >> owsh) & (OW - 1);
        int bc = i >> (2 * owsh);
        int c  = bc & cmask;
        float scale = g[c] * rsqrtf(var[c] + 1e-5f);
        float shift = bta[c] - mean[c] * scale;
        const float* src = in + (long long)bc * H * H;
        float m = 0.f;   // relu output is >= 0 and window is non-empty
        #pragma unroll
        for (int dy = 0; dy < 3; dy++) {
            int y = 2 * oy - 1 + dy;
            if ((unsigned)y >= (unsigned)H) continue;
            #pragma unroll
            for (int dx = 0; dx < 3; dx++) {
                int x = 2 * ox - 1 + dx;
                if ((unsigned)x >= (unsigned)H) continue;
                float v = fmaf(src[y * H + x], scale, shift);
                m = fmaxf(m, v);
            }
        }
        out[i] = m;
    }
}

// ---------------- MaxPool2d(kernel=3, stride=2, padding=1) -----------------
__global__ void maxpool3s2(const float* __restrict__ in, float* __restrict__ out,
                           int total, int H, int W, int owsh)
{
    int OW = W >> 1;
    for (int i = blockIdx.x * blockDim.x + threadIdx.x; i < total;
         i += gridDim.x * blockDim.x) {
        int ox = i & (OW - 1);
        int t  = i >> owsh;
        int oy = t & (OW - 1);
        int bc = t >> owsh;
        const float* src = in + (long long)bc * H * W;
        float m = -INFINITY;
        #pragma unroll
        for (int dy = 0; dy < 3; dy++) {
            int y = 2 * oy - 1 + dy;
            if ((unsigned)y >= (unsigned)H) continue;
            #pragma unroll
            for (int dx = 0; dx < 3; dx++) {
                int x = 2 * ox - 1 + dx;
                if ((unsigned)x >= (unsigned)W) continue;
                m = fmaxf(m, src[y * W + x]);
            }
        }
        out[i] = m;
    }
}

// ---------------- MLP stage 1: X[16,128,592] @ W1[16,592,600] + b1, tanh ----
__global__ __launch_bounds__(256) void gemm_bias_tanh(
    const float* __restrict__ A, const float* __restrict__ Bw,
    const float* __restrict__ bias, float* __restrict__ C)
{
    const int M = 128, N = 600, K = 592;
    const int node = blockIdx.z;
    A    += node * M * K;
    Bw   += node * K * N;
    bias += node * N;
    C    += node * M * N;

    __shared__ __align__(16) float As[16][68];
    __shared__ __align__(16) float Bs[16][68];

    const int tid = threadIdx.x;
    const int m0 = blockIdx.y * 64;
    const int n0 = blockIdx.x * 64;
    const int tm = tid >> 4;
    const int tn = tid & 15;

    float acc[4][4] = {};

    for (int k0 = 0; k0 < K; k0 += 16) {
        #pragma unroll
        for (int i = 0; i < 4; i++) {
            int lin = tid + i * 256;
            int kk = lin & 15;
            int mm = lin >> 4;
            As[kk][mm] = A[(m0 + mm) * K + k0 + kk];
        }
        #pragma unroll
        for (int i = 0; i < 4; i++) {
            int lin = tid + i * 256;
            int nn = lin & 63;
            int kk = lin >> 6;
            int gn = n0 + nn;
            Bs[kk][nn] = (gn < N) ? Bw[(k0 + kk) * N + gn] : 0.f;
        }
        __syncthreads();
        #pragma unroll
        for (int kk = 0; kk < 16; kk++) {
            float4 a4 = *(const float4*)&As[kk][tm * 4];
            float4 b4 = *(const float4*)&Bs[kk][tn * 4];
            float av[4] = {a4.x, a4.y, a4.z, a4.w};
            float bv[4] = {b4.x, b4.y, b4.z, b4.w};
            #pragma unroll
            for (int i = 0; i < 4; i++)
                #pragma unroll
                for (int j = 0; j < 4; j++)
                    acc[i][j] = fmaf(av[i], bv[j], acc[i][j]);
        }
        __syncthreads();
    }

    #pragma unroll
    for (int i = 0; i < 4; i++) {
        int m = m0 + tm * 4 + i;
        #pragma unroll
        for (int j = 0; j < 4; j++) {
            int gn = n0 + tn * 4 + j;
            if (gn < N)
                C[m * N + gn] = tanhf(acc[i][j] + bias[gn]);
        }
    }
}

// ---------------- MLP stage 2 + softmax: one warp per (node, b) ------------
__global__ void mlp2_softmax(const float* __restrict__ h, const float* __restrict__ W2,
                             const float* __restrict__ b2, float* __restrict__ out)
{
    int nb = blockIdx.x;
    int node = nb >> 7;
    int b    = nb & 127;
    int lane = threadIdx.x;

    const float* hrow = h  + (node * 128 + b) * 600;
    const float* w    = W2 + node * 600 * 10;

    float acc[10];
    #pragma unroll
    for (int o = 0; o < 10; o++) acc[o] = 0.f;

    for (int i = lane; i < 600; i += 32) {
        float hv = hrow[i];
        const float* wr = w + i * 10;
        #pragma unroll
        for (int o = 0; o < 10; o++)
            acc[o] = fmaf(hv, wr[o], acc[o]);
    }
    #pragma unroll
    for (int o = 0; o < 10; o++)
        #pragma unroll
        for (int s = 16; s > 0; s >>= 1)
            acc[o] += __shfl_down_sync(0xffffffffu, acc[o], s);

    if (lane == 0) {
        float lg[10];
        float mx = -INFINITY;
        #pragma unroll
        for (int o = 0; o < 10; o++) {
            lg[o] = acc[o] + b2[node * 10 + o];
            mx = fmaxf(mx, lg[o]);
        }
        float se = 0.f;
        #pragma unroll
        for (int o = 0; o < 10; o++) { lg[o] = expf(lg[o] - mx); se += lg[o]; }
        float inv = 1.f / se;
        #pragma unroll
        for (int o = 0; o < 10; o++)
            out[(node * 128 + b) * 10 + o] = lg[o] * inv;
    }
}

// ---------------- head glue kernels ----------------------------------------
__global__ void build_X1(const float* __restrict__ conv7, float* __restrict__ X, int total)
{
    for (int i = blockIdx.x * blockDim.x + threadIdx.x; i < total;
         i += gridDim.x * blockDim.x) {
        int c = i % 592;
        int t = i / 592;
        int b = t & 127;
        int n = t >> 7;
        X[i] = (c < 80) ? 0.f : conv7[((b * 512 + (c - 80)) << 4) + n];
    }
}

__global__ void build_X2(const float* __restrict__ P1, float* __restrict__ X, int total)
{
    for (int i = blockIdx.x * blockDim.x + threadIdx.x; i < total;
         i += gridDim.x * blockDim.x) {
        int j = i % 80;
        int t = i / 80;
        int b = t & 127;
        int n = t >> 7;
        int s   = j / 10;
        int cls = j - s * 10;
        int nb  = c_nidx[n][s];
        float v = (nb >= 0) ? P1[(nb * 128 + b) * 10 + cls] : 0.f;
        X[(n * 128 + b) * 592 + j] = v;
    }
}

__global__ void final_mean_sq(const float* __restrict__ preds2, float* __restrict__ out)
{
    int t = blockIdx.x * blockDim.x + threadIdx.x;
    if (t >= 1280) return;
    int b = t / 10, c = t - (t / 10) * 10;
    float s = 0.f;
    #pragma unroll
    for (int n = 0; n < 16; n++)
        s += preds2[(n * 128 + b) * 10 + c];
    s *= (1.f / 16.f);
    out[t] = s * s;
}

// ---------------- launcher ---------------------------------------------------
extern "C" void kernel_launch(void* const* d_in, const int* in_sizes, int n_in,
                              void* d_out, int out_size)
{
    const float* x     = (const float*)d_in[0];
    const float* cw1   = (const float*)d_in[1];
    const float* cb1   = (const float*)d_in[2];
    const float* bn1g  = (const float*)d_in[3];
    const float* bn1b  = (const float*)d_in[4];
    const float* cw2   = (const float*)d_in[5];
    const float* cb2   = (const float*)d_in[6];
    const float* bn2g  = (const float*)d_in[7];
    const float* bn2b  = (const float*)d_in[8];
    const float* cw3   = (const float*)d_in[9];
    const float* cb3   = (const float*)d_in[10];
    const float* cw4   = (const float*)d_in[11];
    const float* cb4   = (const float*)d_in[12];
    const float* cw5   = (const float*)d_in[13];
    const float* cb5   = (const float*)d_in[14];
    const float* cw6   = (const float*)d_in[15];
    const float* cb6   = (const float*)d_in[16];
    const float* cw7   = (const float*)d_in[17];
    const float* cb7   = (const float*)d_in[18];
    const float* W1    = (const float*)d_in[19];
    const float* b1    = (const float*)d_in[20];
    const float* W2    = (const float*)d_in[21];
    const float* b2    = (const float*)d_in[22];
    float* out = (float*)d_out;

    float *A, *Bb, *X, *H, *P1, *mean, *var;
    cudaGetSymbolAddress((void**)&A,    g_A);
    cudaGetSymbolAddress((void**)&Bb,   g_B);
    cudaGetSymbolAddress((void**)&X,    g_X);
    cudaGetSymbolAddress((void**)&H,    g_H);
    cudaGetSymbolAddress((void**)&P1,   g_P1);
    cudaGetSymbolAddress((void**)&mean, g_mean);
    cudaGetSymbolAddress((void**)&var,  g_var);

    // ---- conv1 (3->64, 64x64) + BN + ReLU + pool -> 32x32
    conv3x3_gemm<<<dim3(524288 / 64, 1), 256>>>(x, cw1, cb1, A, 3, 64, 64, 64, 12, 6, 0);
    bn_stats<<<64, 256>>>(A, mean, var, 64, 4096, 12);
    bn_relu_pool<<<32768, 256>>>(A, Bb, bn1g, bn1b, mean, var, 8388608, 64, 5, 63);

    // ---- conv2 (64->128, 32x32) + BN + ReLU + pool -> 16x16
    conv_fast<64, 128, 32, 32, 128, false><<<dim3(1024, 1), 256>>>(Bb, cw2, cb2, A);
    bn_stats<<<128, 256>>>(A, mean, var, 128, 1024, 10);
    bn_relu_pool<<<16384, 256>>>(A, Bb, bn2g, bn2b, mean, var, 4194304, 32, 4, 127);

    // ---- conv3 (128->256, 16x16) relu
    conv_fast<128, 256, 16, 16, 128, true><<<dim3(256, 2), 256>>>(Bb, cw3, cb3, A);
    // ---- conv4 (256->256, 16x16) relu + pool -> 8x8
    conv_fast<256, 256, 16, 16, 128, true><<<dim3(256, 2), 256>>>(A, cw4, cb4, Bb);
    maxpool3s2<<<4096, 256>>>(Bb, A, 2097152, 16, 16, 3);

    // ---- conv5 (256->512, 8x8) relu
    conv_fast<256, 512, 8, 8, 128, true><<<dim3(64, 4), 256>>>(A, cw5, cb5, Bb);
    // ---- conv6 (512->512, 8x8) relu + pool -> 4x4
    conv_fast<512, 512, 8, 8, 128, true><<<dim3(64, 4), 256>>>(Bb, cw6, cb6, A);
    maxpool3s2<<<2048, 256>>>(A, Bb, 1048576, 8, 8, 2);

    // ---- conv7 (512->512, 4x4) relu  -> feats source in A
    conv_fast<512, 512, 4, 4, 64, true><<<dim3(32, 4), 256>>>(Bb, cw7, cb7, A);

    // ---- head: pass 1 (zero neighbor slots)
    build_X1<<<4736, 256>>>(A, X, 16 * 128 * 592);
    gemm_bias_tanh<<<dim3(10, 2, 16), 256>>>(X, W1, b1, H);
    mlp2_softmax<<<2048, 32>>>(H, W2, b2, P1);

    // ---- head: pass 2 (gathered neighbor predictions)
    build_X2<<<640, 256>>>(P1, X, 16 * 128 * 80);
    gemm_bias_tanh<<<dim3(10, 2, 16), 256>>>(X, W1, b1, H);
    mlp2_softmax<<<2048, 32>>>(H, W2, b2, out + 1280);

    // ---- squared mean over nodes -> out[0:1280]
    final_mean_sq<<<5, 256>>>(out + 1280, out);
}

// round 3
// speedup vs baseline: 1.3004x; 1.0661x over previous
#include <cuda_runtime.h>
#include <math.h>

#define BATCH 128

typedef unsigned long long ull;

// ---------------- f32x2 packed-FMA helpers (Blackwell; PTX-only path) ------
__device__ __forceinline__ void fma2(ull& d, ull a, ull b) {
    asm("fma.rn.f32x2 %0, %1, %2, %0;" : "+l"(d) : "l"(a), "l"(b));
}
__device__ __forceinline__ ull bcast2(float x) {
    ull r;
    asm("mov.b64 %0, {%1, %1};" : "=l"(r) : "f"(x));
    return r;
}
__device__ __forceinline__ ull pack2(float lo, float hi) {
    ull r;
    asm("mov.b64 %0, {%1, %2};" : "=l"(r) : "f"(lo), "f"(hi));
    return r;
}
union F4U { float4 v; ull u[2]; };
union UF2 { ull u; float f[2]; };

// ---------------- scratch (static device globals; no runtime allocation) ----
__device__ float g_A[33554432];            // 134 MB max: conv1 out [128,64,64,64]
__device__ float g_B[8388608];             // 33.5 MB max
__device__ float g_X[16 * 128 * 592];
__device__ float g_H[16 * 128 * 600];
__device__ float g_P1[16 * 128 * 10];
__device__ float g_mean[128];
__device__ float g_var[128];
__device__ double g_stat[128];             // conv1 BN stats accumulators

__device__ const int c_nidx[16][8] = {
    {1, 4, 5, -1, -1, -1, -1, -1},
    {0, 2, 5, 4, 6, -1, -1, -1},
    {1, 3, 6, 5, 7, -1, -1, -1},
    {2, 7, 6, -1, -1, -1, -1, -1},
    {0, 5, 8, 1, 9, -1, -1, -1},
    {1, 4, 6, 9, 0, 2, 8, 10},
    {2, 5, 7, 10, 1, 3, 9, 11},
    {3, 6, 11, 2, 10, -1, -1, -1},
    {4, 9, 12, 5, 13, -1, -1, -1},
    {5, 8, 10, 13, 4, 6, 12, 14},
    {6, 9, 11, 14, 5, 7, 13, 15},
    {7, 10, 15, 6, 14, -1, -1, -1},
    {8, 13, 9, -1, -1, -1, -1, -1},
    {9, 12, 14, 8, 10, -1, -1, -1},
    {10, 13, 15, 9, 11, -1, -1, -1},
    {11, 14, 10, -1, -1, -1, -1, -1},
};

// ============================================================================
// FAST implicit-GEMM 3x3 SAME conv (NCHW), f32x2 packed accumulation.
// BM=128, BN in {128,64}, BK=8, 256 threads, double-buffered smem.
// ============================================================================
template<int Cin, int Cout, int H, int W, int BN, bool RELU>
__global__ __launch_bounds__(256, 2) void conv_fast(
    const float* __restrict__ in, const float* __restrict__ wgt,
    const float* __restrict__ bias, float* __restrict__ out)
{
    constexpr int K  = Cin * 9;
    constexpr int HW = H * W;
    constexpr int NK = K / 8;
    constexpr int TN = BN / 16;        // 8 or 4 output cols per thread
    constexpr int NS = BN / 32;        // B-gather slots per thread

    __shared__ __align__(16) float As[2][8][128];
    __shared__ __align__(16) float Bs[2][8][BN];

    const int tid = threadIdx.x;
    const int m0  = blockIdx.y * 128;
    const int n0  = blockIdx.x * BN;
    const int tm  = tid >> 4;
    const int tn  = tid & 15;

    const int amm = tid >> 1;
    const int aks = (tid & 1) * 4;
    const float* wptr = wgt + (m0 + amm) * K + aks;

    int kks[NS], nns[NS];
    int f[NS], base2[NS], sy0[NS], sx0[NS];
    #pragma unroll
    for (int s = 0; s < NS; s++) {
        int lin = tid + s * 256;
        kks[s] = lin / BN;
        nns[s] = lin % BN;
        int gn = n0 + nns[s];
        int b  = gn / HW;
        int p  = gn % HW;
        int y0 = p / W;
        int x0 = p % W;
        sy0[s] = y0; sx0[s] = x0;
        f[s]   = kks[s];
        base2[s] = b * Cin * HW + y0 * W + x0 - W - 1;
    }

    ull acc2[4][TN];                    // row-pairs x cols, packed f32x2
    #pragma unroll
    for (int r = 0; r < 4; r++)
        #pragma unroll
        for (int c = 0; c < TN; c++) acc2[r][c] = 0ull;

    float4 ra;
    float  rb[NS];

    // prologue
    ra = *(const float4*)wptr; wptr += 8;
    #pragma unroll
    for (int s = 0; s < NS; s++) {
        int dy = (f[s] * 11) >> 5;
        int dx = f[s] - 3 * dy;
        int y = sy0[s] + dy - 1, x = sx0[s] + dx - 1;
        float v = 0.f;
        if ((unsigned)y < (unsigned)H && (unsigned)x < (unsigned)W)
            v = __ldg(in + base2[s] + dy * W + dx);
        rb[s] = v;
        f[s] += 8; if (f[s] >= 9) { f[s] -= 9; base2[s] += HW; }
    }
    As[0][aks + 0][amm] = ra.x;
    As[0][aks + 1][amm] = ra.y;
    As[0][aks + 2][amm] = ra.z;
    As[0][aks + 3][amm] = ra.w;
    #pragma unroll
    for (int s = 0; s < NS; s++) Bs[0][kks[s]][nns[s]] = rb[s];
    __syncthreads();

    int buf = 0;
    for (int kt = 0; kt < NK; kt++) {
        const bool more = (kt + 1 < NK);
        if (more) {
            ra = *(const float4*)wptr; wptr += 8;
            #pragma unroll
            for (int s = 0; s < NS; s++) {
                int dy = (f[s] * 11) >> 5;
                int dx = f[s] - 3 * dy;
                int y = sy0[s] + dy - 1, x = sx0[s] + dx - 1;
                float v = 0.f;
                if ((unsigned)y < (unsigned)H && (unsigned)x < (unsigned)W)
                    v = __ldg(in + base2[s] + dy * W + dx);
                rb[s] = v;
                f[s] += 8; if (f[s] >= 9) { f[s] -= 9; base2[s] += HW; }
            }
        }

        #pragma unroll
        for (int kk = 0; kk < 8; kk++) {
            F4U a0, a1;
            a0.v = *(const float4*)&As[buf][kk][tm * 4];
            a1.v = *(const float4*)&As[buf][kk][tm * 4 + 64];
            ull ap[4] = {a0.u[0], a0.u[1], a1.u[0], a1.u[1]};
            float bv[TN];
            {
                float4 b0 = *(const float4*)&Bs[buf][kk][tn * 4];
                bv[0] = b0.x; bv[1] = b0.y; bv[2] = b0.z; bv[3] = b0.w;
                if (TN == 8) {
                    float4 b1 = *(const float4*)&Bs[buf][kk][tn * 4 + BN / 2];
                    bv[4] = b1.x; bv[5] = b1.y; bv[6] = b1.z; bv[7] = b1.w;
                }
            }
            #pragma unroll
            for (int c = 0; c < TN; c++) {
                ull b2 = bcast2(bv[c]);
                #pragma unroll
                for (int rp = 0; rp < 4; rp++)
                    fma2(acc2[rp][c], ap[rp], b2);
            }
        }

        if (more) {
            int nb = buf ^ 1;
            As[nb][aks + 0][amm] = ra.x;
            As[nb][aks + 1][amm] = ra.y;
            As[nb][aks + 2][amm] = ra.z;
            As[nb][aks + 3][amm] = ra.w;
            #pragma unroll
            for (int s = 0; s < NS; s++) Bs[nb][kks[s]][nns[s]] = rb[s];
            __syncthreads();
            buf = nb;
        }
    }

    // epilogue: bias (+relu), float4 stores
    #pragma unroll
    for (int rp = 0; rp < 4; rp++) {
        #pragma unroll
        for (int h = 0; h < 2; h++) {
            int r  = rp * 2 + h;
            int co = m0 + tm * 4 + (r < 4 ? r : 60 + r);
            float bval = bias[co];
            #pragma unroll
            for (int cb = 0; cb < TN / 4; cb++) {
                int gn = n0 + tn * 4 + cb * (BN / 2);
                int b  = gn / HW;
                int p  = gn % HW;
                float4 v;
                UF2 u0, u1, u2, u3;
                u0.u = acc2[rp][cb * 4 + 0];
                u1.u = acc2[rp][cb * 4 + 1];
                u2.u = acc2[rp][cb * 4 + 2];
                u3.u = acc2[rp][cb * 4 + 3];
                v.x = u0.f[h] + bval;
                v.y = u1.f[h] + bval;
                v.z = u2.f[h] + bval;
                v.w = u3.f[h] + bval;
                if (RELU) {
                    v.x = fmaxf(v.x, 0.f); v.y = fmaxf(v.y, 0.f);
                    v.z = fmaxf(v.z, 0.f); v.w = fmaxf(v.w, 0.f);
                }
                *(float4*)&out[(b * Cout + co) * HW + p] = v;
            }
        }
    }
}

// ============================================================================
// conv1 (3->64, 64x64 SAME) direct conv, fused BN-stat accumulation.
// grid = B*H blocks; block = 256 threads: x = tid&63, cog = tid>>6 (16 couts).
// ============================================================================
__global__ __launch_bounds__(256) void conv1_stats(
    const float* __restrict__ in, const float* __restrict__ wgt,
    const float* __restrict__ bias, float* __restrict__ out,
    double* __restrict__ stat)
{
    __shared__ __align__(16) float wT[27][64];     // transposed weights
    __shared__ float inr[3][3][66];                // 3 ch x 3 rows x (64+2 pad)
    __shared__ float ssum[64], ssq[64];

    const int tid = threadIdx.x;
    const int b   = blockIdx.x >> 6;
    const int y   = blockIdx.x & 63;
    const int x   = tid & 63;
    const int cog = tid >> 6;

    // load + transpose weights [64][27] -> [27][64]
    for (int i = tid; i < 1728; i += 256) {
        int co = i / 27, k = i - co * 27;
        wT[k][co] = wgt[i];
    }
    // load 3 input rows x 3 channels, zero-padded
    for (int i = tid; i < 594; i += 256) {
        int ci = i / 198, rem = i - ci * 198;
        int dy = rem / 66, xx = rem - dy * 66;
        int yy = y - 1 + dy, gx = xx - 1;
        float v = 0.f;
        if ((unsigned)yy < 64u && (unsigned)gx < 64u)
            v = in[(b * 3 + ci) * 4096 + yy * 64 + gx];
        inr[ci][dy][xx] = v;
    }
    if (tid < 64) { ssum[tid] = 0.f; ssq[tid] = 0.f; }
    __syncthreads();

    // gather this pixel's 27 inputs
    float iv[27];
    #pragma unroll
    for (int ci = 0; ci < 3; ci++)
        #pragma unroll
        for (int dy = 0; dy < 3; dy++)
            #pragma unroll
            for (int dx = 0; dx < 3; dx++)
                iv[ci * 9 + dy * 3 + dx] = inr[ci][dy][x + dx];

    // 16 couts per thread, packed f32x2 accumulation
    ull acc2[8];
    #pragma unroll
    for (int p = 0; p < 8; p++) {
        float2 bb = *(const float2*)&bias[cog * 16 + p * 2];
        acc2[p] = pack2(bb.x, bb.y);
    }
    #pragma unroll
    for (int k = 0; k < 27; k++) {
        ull v2 = bcast2(iv[k]);
        F4U w0, w1, w2, w3;
        w0.v = *(const float4*)&wT[k][cog * 16 + 0];
        w1.v = *(const float4*)&wT[k][cog * 16 + 4];
        w2.v = *(const float4*)&wT[k][cog * 16 + 8];
        w3.v = *(const float4*)&wT[k][cog * 16 + 12];
        fma2(acc2[0], w0.u[0], v2); fma2(acc2[1], w0.u[1], v2);
        fma2(acc2[2], w1.u[0], v2); fma2(acc2[3], w1.u[1], v2);
        fma2(acc2[4], w2.u[0], v2); fma2(acc2[5], w2.u[1], v2);
        fma2(acc2[6], w3.u[0], v2); fma2(acc2[7], w3.u[1], v2);
    }

    // store outputs + warp-reduce stats (all lanes in warp share co per j)
    const int lane = tid & 31;
    #pragma unroll
    for (int p = 0; p < 8; p++) {
        UF2 u; u.u = acc2[p];
        #pragma unroll
        for (int h = 0; h < 2; h++) {
            int co = cog * 16 + p * 2 + h;
            float val = u.f[h];
            out[(b * 64 + co) * 4096 + y * 64 + x] = val;
            float s = val, q = val * val;
            #pragma unroll
            for (int off = 16; off > 0; off >>= 1) {
                s += __shfl_down_sync(0xffffffffu, s, off);
                q += __shfl_down_sync(0xffffffffu, q, off);
            }
            if (lane == 0) {
                atomicAdd(&ssum[co], s);
                atomicAdd(&ssq[co], q);
            }
        }
    }
    __syncthreads();
    if (tid < 64) {
        atomicAdd(&stat[tid],      (double)ssum[tid]);
        atomicAdd(&stat[64 + tid], (double)ssq[tid]);
    }
}

__global__ void zero_stats(double* stat)
{
    if (threadIdx.x < 128) stat[threadIdx.x] = 0.0;
}

__global__ void finalize_stats(const double* __restrict__ stat,
                               float* __restrict__ mean, float* __restrict__ var)
{
    int c = threadIdx.x;
    if (c < 64) {
        double n = 524288.0;
        double m = stat[c] / n;
        mean[c] = (float)m;
        var[c]  = (float)(stat[64 + c] / n - m * m);
    }
}

// ---------------- BatchNorm stats (conv2) -----------------------------------
__global__ void bn_stats(const float* __restrict__ x, float* __restrict__ mean,
                         float* __restrict__ var, int C, int HW, int hwsh)
{
    int c = blockIdx.x;
    __shared__ double ss[256], sq[256];
    double s = 0.0, q = 0.0;
    int cnt = BATCH * HW;
    for (int j = threadIdx.x; j < cnt; j += 256) {
        int b = j >> hwsh;
        int p = j & (HW - 1);
        float v = x[(b * C + c) * HW + p];
        s += (double)v;
        q += (double)v * (double)v;
    }
    ss[threadIdx.x] = s; sq[threadIdx.x] = q;
    __syncthreads();
    for (int st = 128; st > 0; st >>= 1) {
        if (threadIdx.x < st) {
            ss[threadIdx.x] += ss[threadIdx.x + st];
            sq[threadIdx.x] += sq[threadIdx.x + st];
        }
        __syncthreads();
    }
    if (threadIdx.x == 0) {
        double m = ss[0] / cnt;
        mean[c] = (float)m;
        var[c]  = (float)(sq[0] / cnt - m * m);
    }
}

// ---------------- fused BN-apply + ReLU + MaxPool(3,2,1) --------------------
__global__ void bn_relu_pool(const float* __restrict__ in, float* __restrict__ out,
                             const float* __restrict__ g, const float* __restrict__ bta,
                             const float* __restrict__ mean, const float* __restrict__ var,
                             int total, int H, int owsh, int cmask)
{
    int OW = H >> 1;
    for (int i = blockIdx.x * blockDim.x + threadIdx.x; i < total;
         i += gridDim.x * blockDim.x) {
        int ox = i & (OW - 1);
        int oy = (i >> owsh) & (OW - 1);
        int bc = i >> (2 * owsh);
        int c  = bc & cmask;
        float scale = g[c] * rsqrtf(var[c] + 1e-5f);
        float shift = bta[c] - mean[c] * scale;
        const float* src = in + (long long)bc * H * H;
        float m = 0.f;
        #pragma unroll
        for (int dy = 0; dy < 3; dy++) {
            int y = 2 * oy - 1 + dy;
            if ((unsigned)y >= (unsigned)H) continue;
            #pragma unroll
            for (int dx = 0; dx < 3; dx++) {
                int x = 2 * ox - 1 + dx;
                if ((unsigned)x >= (unsigned)H) continue;
                float v = fmaf(src[y * H + x], scale, shift);
                m = fmaxf(m, v);
            }
        }
        out[i] = m;
    }
}

// ---------------- MaxPool2d(kernel=3, stride=2, padding=1) -----------------
__global__ void maxpool3s2(const float* __restrict__ in, float* __restrict__ out,
                           int total, int H, int W, int owsh)
{
    int OW = W >> 1;
    for (int i = blockIdx.x * blockDim.x + threadIdx.x; i < total;
         i += gridDim.x * blockDim.x) {
        int ox = i & (OW - 1);
        int t  = i >> owsh;
        int oy = t & (OW - 1);
        int bc = t >> owsh;
        const float* src = in + (long long)bc * H * W;
        float m = -INFINITY;
        #pragma unroll
        for (int dy = 0; dy < 3; dy++) {
            int y = 2 * oy - 1 + dy;
            if ((unsigned)y >= (unsigned)H) continue;
            #pragma unroll
            for (int dx = 0; dx < 3; dx++) {
                int x = 2 * ox - 1 + dx;
                if ((unsigned)x >= (unsigned)W) continue;
                m = fmaxf(m, src[y * W + x]);
            }
        }
        out[i] = m;
    }
}

// ---------------- MLP stage 1: X[16,128,592] @ W1[16,592,600] + b1, tanh ----
__global__ __launch_bounds__(256) void gemm_bias_tanh(
    const float* __restrict__ A, const float* __restrict__ Bw,
    const float* __restrict__ bias, float* __restrict__ C)
{
    const int M = 128, N = 600, K = 592;
    const int node = blockIdx.z;
    A    += node * M * K;
    Bw   += node * K * N;
    bias += node * N;
    C    += node * M * N;

    __shared__ __align__(16) float As[16][68];
    __shared__ __align__(16) float Bs[16][68];

    const int tid = threadIdx.x;
    const int m0 = blockIdx.y * 64;
    const int n0 = blockIdx.x * 64;
    const int tm = tid >> 4;
    const int tn = tid & 15;

    float acc[4][4] = {};

    for (int k0 = 0; k0 < K; k0 += 16) {
        #pragma unroll
        for (int i = 0; i < 4; i++) {
            int lin = tid + i * 256;
            int kk = lin & 15;
            int mm = lin >> 4;
            As[kk][mm] = A[(m0 + mm) * K + k0 + kk];
        }
        #pragma unroll
        for (int i = 0; i < 4; i++) {
            int lin = tid + i * 256;
            int nn = lin & 63;
            int kk = lin >> 6;
            int gn = n0 + nn;
            Bs[kk][nn] = (gn < N) ? Bw[(k0 + kk) * N + gn] : 0.f;
        }
        __syncthreads();
        #pragma unroll
        for (int kk = 0; kk < 16; kk++) {
            float4 a4 = *(const float4*)&As[kk][tm * 4];
            float4 b4 = *(const float4*)&Bs[kk][tn * 4];
            float av[4] = {a4.x, a4.y, a4.z, a4.w};
            float bv[4] = {b4.x, b4.y, b4.z, b4.w};
            #pragma unroll
            for (int i = 0; i < 4; i++)
                #pragma unroll
                for (int j = 0; j < 4; j++)
                    acc[i][j] = fmaf(av[i], bv[j], acc[i][j]);
        }
        __syncthreads();
    }

    #pragma unroll
    for (int i = 0; i < 4; i++) {
        int m = m0 + tm * 4 + i;
        #pragma unroll
        for (int j = 0; j < 4; j++) {
            int gn = n0 + tn * 4 + j;
            if (gn < N)
                C[m * N + gn] = tanhf(acc[i][j] + bias[gn]);
        }
    }
}

// ---------------- MLP stage 2 + softmax: one warp per (node, b) ------------
__global__ void mlp2_softmax(const float* __restrict__ h, const float* __restrict__ W2,
                             const float* __restrict__ b2, float* __restrict__ out)
{
    int nb = blockIdx.x;
    int node = nb >> 7;
    int b    = nb & 127;
    int lane = threadIdx.x;

    const float* hrow = h  + (node * 128 + b) * 600;
    const float* w    = W2 + node * 600 * 10;

    float acc[10];
    #pragma unroll
    for (int o = 0; o < 10; o++) acc[o] = 0.f;

    for (int i = lane; i < 600; i += 32) {
        float hv = hrow[i];
        const float* wr = w + i * 10;
        #pragma unroll
        for (int o = 0; o < 10; o++)
            acc[o] = fmaf(hv, wr[o], acc[o]);
    }
    #pragma unroll
    for (int o = 0; o < 10; o++)
        #pragma unroll
        for (int s = 16; s > 0; s >>= 1)
            acc[o] += __shfl_down_sync(0xffffffffu, acc[o], s);

    if (lane == 0) {
        float lg[10];
        float mx = -INFINITY;
        #pragma unroll
        for (int o = 0; o < 10; o++) {
            lg[o] = acc[o] + b2[node * 10 + o];
            mx = fmaxf(mx, lg[o]);
        }
        float se = 0.f;
        #pragma unroll
        for (int o = 0; o < 10; o++) { lg[o] = expf(lg[o] - mx); se += lg[o]; }
        float inv = 1.f / se;
        #pragma unroll
        for (int o = 0; o < 10; o++)
            out[(node * 128 + b) * 10 + o] = lg[o] * inv;
    }
}

// ---------------- head glue kernels ----------------------------------------
__global__ void build_X1(const float* __restrict__ conv7, float* __restrict__ X, int total)
{
    for (int i = blockIdx.x * blockDim.x + threadIdx.x; i < total;
         i += gridDim.x * blockDim.x) {
        int c = i % 592;
        int t = i / 592;
        int b = t & 127;
        int n = t >> 7;
        X[i] = (c < 80) ? 0.f : conv7[((b * 512 + (c - 80)) << 4) + n];
    }
}

__global__ void build_X2(const float* __restrict__ P1, float* __restrict__ X, int total)
{
    for (int i = blockIdx.x * blockDim.x + threadIdx.x; i < total;
         i += gridDim.x * blockDim.x) {
        int j = i % 80;
        int t = i / 80;
        int b = t & 127;
        int n = t >> 7;
        int s   = j / 10;
        int cls = j - s * 10;
        int nb  = c_nidx[n][s];
        float v = (nb >= 0) ? P1[(nb * 128 + b) * 10 + cls] : 0.f;
        X[(n * 128 + b) * 592 + j] = v;
    }
}

__global__ void final_mean_sq(const float* __restrict__ preds2, float* __restrict__ out)
{
    int t = blockIdx.x * blockDim.x + threadIdx.x;
    if (t >= 1280) return;
    int b = t / 10, c = t - (t / 10) * 10;
    float s = 0.f;
    #pragma unroll
    for (int n = 0; n < 16; n++)
        s += preds2[(n * 128 + b) * 10 + c];
    s *= (1.f / 16.f);
    out[t] = s * s;
}

// ---------------- launcher ---------------------------------------------------
extern "C" void kernel_launch(void* const* d_in, const int* in_sizes, int n_in,
                              void* d_out, int out_size)
{
    const float* x     = (const float*)d_in[0];
    const float* cw1   = (const float*)d_in[1];
    const float* cb1   = (const float*)d_in[2];
    const float* bn1g  = (const float*)d_in[3];
    const float* bn1b  = (const float*)d_in[4];
    const float* cw2   = (const float*)d_in[5];
    const float* cb2   = (const float*)d_in[6];
    const float* bn2g  = (const float*)d_in[7];
    const float* bn2b  = (const float*)d_in[8];
    const float* cw3   = (const float*)d_in[9];
    const float* cb3   = (const float*)d_in[10];
    const float* cw4   = (const float*)d_in[11];
    const float* cb4   = (const float*)d_in[12];
    const float* cw5   = (const float*)d_in[13];
    const float* cb5   = (const float*)d_in[14];
    const float* cw6   = (const float*)d_in[15];
    const float* cb6   = (const float*)d_in[16];
    const float* cw7   = (const float*)d_in[17];
    const float* cb7   = (const float*)d_in[18];
    const float* W1    = (const float*)d_in[19];
    const float* b1    = (const float*)d_in[20];
    const float* W2    = (const float*)d_in[21];
    const float* b2    = (const float*)d_in[22];
    float* out = (float*)d_out;

    float *A, *Bb, *X, *H, *P1, *mean, *var;
    double* stat;
    cudaGetSymbolAddress((void**)&A,    g_A);
    cudaGetSymbolAddress((void**)&Bb,   g_B);
    cudaGetSymbolAddress((void**)&X,    g_X);
    cudaGetSymbolAddress((void**)&H,    g_H);
    cudaGetSymbolAddress((void**)&P1,   g_P1);
    cudaGetSymbolAddress((void**)&mean, g_mean);
    cudaGetSymbolAddress((void**)&var,  g_var);
    cudaGetSymbolAddress((void**)&stat, g_stat);

    // ---- conv1 (3->64, 64x64) fused stats + BN + ReLU + pool -> 32x32
    zero_stats<<<1, 128>>>(stat);
    conv1_stats<<<8192, 256>>>(x, cw1, cb1, A, stat);
    finalize_stats<<<1, 64>>>(stat, mean, var);
    bn_relu_pool<<<32768, 256>>>(A, Bb, bn1g, bn1b, mean, var, 8388608, 64, 5, 63);

    // ---- conv2 (64->128, 32x32) + BN + ReLU + pool -> 16x16
    conv_fast<64, 128, 32, 32, 128, false><<<dim3(1024, 1), 256>>>(Bb, cw2, cb2, A);
    bn_stats<<<128, 256>>>(A, mean, var, 128, 1024, 10);
    bn_relu_pool<<<16384, 256>>>(A, Bb, bn2g, bn2b, mean, var, 4194304, 32, 4, 127);

    // ---- conv3 (128->256, 16x16) relu
    conv_fast<128, 256, 16, 16, 128, true><<<dim3(256, 2), 256>>>(Bb, cw3, cb3, A);
    // ---- conv4 (256->256, 16x16) relu + pool -> 8x8
    conv_fast<256, 256, 16, 16, 128, true><<<dim3(256, 2), 256>>>(A, cw4, cb4, Bb);
    maxpool3s2<<<4096, 256>>>(Bb, A, 2097152, 16, 16, 3);

    // ---- conv5 (256->512, 8x8) relu
    conv_fast<256, 512, 8, 8, 128, true><<<dim3(64, 4), 256>>>(A, cw5, cb5, Bb);
    // ---- conv6 (512->512, 8x8) relu + pool -> 4x4
    conv_fast<512, 512, 8, 8, 128, true><<<dim3(64, 4), 256>>>(Bb, cw6, cb6, A);
    maxpool3s2<<<2048, 256>>>(A, Bb, 1048576, 8, 8, 2);

    // ---- conv7 (512->512, 4x4) relu
    conv_fast<512, 512, 4, 4, 64, true><<<dim3(32, 4), 256>>>(Bb, cw7, cb7, A);

    // ---- head: pass 1
    build_X1<<<4736, 256>>>(A, X, 16 * 128 * 592);
    gemm_bias_tanh<<<dim3(10, 2, 16), 256>>>(X, W1, b1, H);
    mlp2_softmax<<<2048, 32>>>(H, W2, b2, P1);

    // ---- head: pass 2
    build_X2<<<640, 256>>>(P1, X, 16 * 128 * 80);
    gemm_bias_tanh<<<dim3(10, 2, 16), 256>>>(X, W1, b1, H);
    mlp2_softmax<<<2048, 32>>>(H, W2, b2, out + 1280);

    final_mean_sq<<<5, 256>>>(out + 1280, out);
}

// round 6
// speedup vs baseline: 1.8003x; 1.3844x over previous
#include <cuda_runtime.h>
#include <cuda_bf16.h>
#include <cstdint>
#include <math.h>

#define BATCH 128
typedef unsigned long long ull;

// ---------------- f32x2 packed helpers (conv1 direct kernel) ---------------
__device__ __forceinline__ void fma2(ull& d, ull a, ull b) {
    asm("fma.rn.f32x2 %0, %1, %2, %0;" : "+l"(d) : "l"(a), "l"(b));
}
__device__ __forceinline__ ull bcast2(float x) {
    ull r; asm("mov.b64 %0, {%1, %1};" : "=l"(r) : "f"(x)); return r;
}
__device__ __forceinline__ ull pack2(float lo, float hi) {
    ull r; asm("mov.b64 %0, {%1, %2};" : "=l"(r) : "f"(lo), "f"(hi)); return r;
}
union F4U { float4 v; ull u[2]; };
union UF2 { ull u; float f[2]; };

// ---------------- HMMA helpers (mma.sync, compute_103-legal) ---------------
__device__ __forceinline__ uint32_t smem_u32(const void* p) {
    uint32_t a;
    asm("{ .reg .u64 t; cvta.to.shared.u64 t, %1; cvt.u32.u64 %0, t; }" : "=r"(a) : "l"(p));
    return a;
}
#define LDMX4(R, ADDR) \
    asm volatile("ldmatrix.sync.aligned.m8n8.x4.shared.b16 {%0,%1,%2,%3}, [%4];" \
        : "=r"((R)[0]), "=r"((R)[1]), "=r"((R)[2]), "=r"((R)[3]) : "r"(ADDR))
#define LDMX2(R, ADDR) \
    asm volatile("ldmatrix.sync.aligned.m8n8.x2.shared.b16 {%0,%1}, [%2];" \
        : "=r"((R)[0]), "=r"((R)[1]) : "r"(ADDR))

__device__ __forceinline__ void mma_bf16(float* d, const uint32_t* a, const uint32_t* b) {
    asm volatile(
        "mma.sync.aligned.m16n8k16.row.col.f32.bf16.bf16.f32 "
        "{%0,%1,%2,%3}, {%4,%5,%6,%7}, {%8,%9}, {%0,%1,%2,%3};"
        : "+f"(d[0]), "+f"(d[1]), "+f"(d[2]), "+f"(d[3])
        : "r"(a[0]), "r"(a[1]), "r"(a[2]), "r"(a[3]), "r"(b[0]), "r"(b[1]));
}

__device__ __forceinline__ uint32_t packbf2(float x, float y) {
    __nv_bfloat162 t = __floats2bfloat162_rn(x, y);
    return *(uint32_t*)&t;
}

// ---------------- scratch --------------------------------------------------
__device__ float g_A[33554432];                 // 134 MB conv activations
__device__ float g_B[8388608];                  // 33.5 MB
__device__ float g_X[16 * 128 * 592];
__device__ float g_H[16 * 128 * 600];
__device__ float g_P1[16 * 128 * 10];
__device__ float g_mean[128];
__device__ float g_var[128];
__device__ double g_stat[256];

__device__ const int c_nidx[16][8] = {
    {1, 4, 5, -1, -1, -1, -1, -1},
    {0, 2, 5, 4, 6, -1, -1, -1},
    {1, 3, 6, 5, 7, -1, -1, -1},
    {2, 7, 6, -1, -1, -1, -1, -1},
    {0, 5, 8, 1, 9, -1, -1, -1},
    {1, 4, 6, 9, 0, 2, 8, 10},
    {2, 5, 7, 10, 1, 3, 9, 11},
    {3, 6, 11, 2, 10, -1, -1, -1},
    {4, 9, 12, 5, 13, -1, -1, -1},
    {5, 8, 10, 13, 4, 6, 12, 14},
    {6, 9, 11, 14, 5, 7, 13, 15},
    {7, 10, 15, 6, 14, -1, -1, -1},
    {8, 13, 9, -1, -1, -1, -1, -1},
    {9, 12, 14, 8, 10, -1, -1, -1},
    {10, 13, 15, 9, 11, -1, -1, -1},
    {11, 14, 10, -1, -1, -1, -1, -1},
};

// ============================================================================
// HMMA bf16x3 implicit-GEMM conv: D[Cout,N] = W[Cout,K] @ im2col[N,K]^T
// BM=128, BN=128, BK=32, 256 thr (8 warps 2Mx4N, warp tile 64x32).
// In-kernel fp32 -> (hi,lo) bf16 split; no materialized im2col.
// Smem tile layout: row-major [128 rows][32 cols bf16] = 64B rows,
// 16B chunk c at byte ((c ^ ((row>>1)&3))<<4) -> conflict-free ldmatrix.
// ============================================================================
static constexpr int HB_DSM = 65536 + 1024;     // 2 x (Ah,Al,Bh,Bl) + align slack

template<int Cin, int Cout, int H, int W, bool RELU>
__global__ __launch_bounds__(256, 1)
void conv_hmma(const float* __restrict__ in, const float* __restrict__ wgt,
               const float* __restrict__ bias, float* __restrict__ out)
{
    constexpr int K  = Cin * 9;
    constexpr int HW = H * W;
    constexpr int NC = K / 32;

    extern __shared__ char dsm_raw[];
    const uint32_t sb = (smem_u32(dsm_raw) + 1023u) & ~1023u;

    const int tid  = threadIdx.x;
    const int wid  = tid >> 5;
    const int lane = tid & 31;
    const int wm   = wid & 1;          // M half (64 rows each)
    const int wn   = wid >> 1;         // N quarter (32 cols each)
    const int n0   = blockIdx.x * 128;
    const int m0   = blockIdx.y * 128;

    // ---- loader state (each thread: one row, 16 k's per chunk)
    const int lr = tid >> 1;           // 0..127
    const int lh = tid & 1;            // 0 or 1 (k halves)
    // B (im2col) row state
    const int gn = n0 + lr;
    const int bidx = gn / HW;
    const int p    = gn & (HW - 1);
    const int y0   = p / W;
    const int x0   = p & (W - 1);
    const float* srcb = in + bidx * Cin * HW;
    const float* wp0  = wgt + (m0 + lr) * K + lh * 16;

    float acc[4][4][4];
    #pragma unroll
    for (int mt = 0; mt < 4; mt++)
        #pragma unroll
        for (int nt = 0; nt < 4; nt++)
            #pragma unroll
            for (int e = 0; e < 4; e++) acc[mt][nt][e] = 0.f;

    // smem offsets
    auto swz = [](int row, int ch) { return row * 64 + ((ch ^ ((row >> 1) & 3)) << 4); };
    const int c0 = 2 * lh;             // this thread's first 16B chunk

    // ---------------- tile loader ----------------
    auto load_tiles = [&](int s, int kc) {
        const uint32_t tb = sb + s * 32768;
        // A: weights, contiguous 16 floats
        {
            const float* wp = wp0 + kc * 32;
            float4 w0 = *(const float4*)(wp + 0);
            float4 w1 = *(const float4*)(wp + 4);
            float4 w2 = *(const float4*)(wp + 8);
            float4 w3 = *(const float4*)(wp + 12);
            float v[16] = {w0.x,w0.y,w0.z,w0.w, w1.x,w1.y,w1.z,w1.w,
                           w2.x,w2.y,w2.z,w2.w, w3.x,w3.y,w3.z,w3.w};
            float hi[16], lo[16];
            #pragma unroll
            for (int j = 0; j < 16; j++) {
                __nv_bfloat16 h = __float2bfloat16(v[j]);
                hi[j] = __bfloat162float(h);
                lo[j] = v[j] - hi[j];
            }
            uint4 H0 = { packbf2(hi[0],hi[1]), packbf2(hi[2],hi[3]),
                         packbf2(hi[4],hi[5]), packbf2(hi[6],hi[7]) };
            uint4 H1 = { packbf2(hi[8],hi[9]), packbf2(hi[10],hi[11]),
                         packbf2(hi[12],hi[13]), packbf2(hi[14],hi[15]) };
            uint4 L0 = { packbf2(lo[0],lo[1]), packbf2(lo[2],lo[3]),
                         packbf2(lo[4],lo[5]), packbf2(lo[6],lo[7]) };
            uint4 L1 = { packbf2(lo[8],lo[9]), packbf2(lo[10],lo[11]),
                         packbf2(lo[12],lo[13]), packbf2(lo[14],lo[15]) };
            asm volatile("st.shared.v4.b32 [%0], {%1,%2,%3,%4};" ::
                "r"(tb + swz(lr, c0)), "r"(H0.x), "r"(H0.y), "r"(H0.z), "r"(H0.w));
            asm volatile("st.shared.v4.b32 [%0], {%1,%2,%3,%4};" ::
                "r"(tb + swz(lr, c0 + 1)), "r"(H1.x), "r"(H1.y), "r"(H1.z), "r"(H1.w));
            asm volatile("st.shared.v4.b32 [%0], {%1,%2,%3,%4};" ::
                "r"(tb + 8192 + swz(lr, c0)), "r"(L0.x), "r"(L0.y), "r"(L0.z), "r"(L0.w));
            asm volatile("st.shared.v4.b32 [%0], {%1,%2,%3,%4};" ::
                "r"(tb + 8192 + swz(lr, c0 + 1)), "r"(L1.x), "r"(L1.y), "r"(L1.z), "r"(L1.w));
        }
        // B: im2col gather, 16 consecutive k
        {
            int k = kc * 32 + lh * 16;
            int ci = k / 9;
            int f  = k - 9 * ci;
            int cioff = ci * HW;
            float v[16];
            #pragma unroll
            for (int j = 0; j < 16; j++) {
                int dy = (f * 11) >> 5;
                int dx = f - 3 * dy;
                int y = y0 + dy - 1, x = x0 + dx - 1;
                v[j] = ((unsigned)y < (unsigned)H && (unsigned)x < (unsigned)W)
                         ? __ldg(srcb + cioff + y * W + x) : 0.f;
                f++; if (f == 9) { f = 0; cioff += HW; }
            }
            float hi[16], lo[16];
            #pragma unroll
            for (int j = 0; j < 16; j++) {
                __nv_bfloat16 h = __float2bfloat16(v[j]);
                hi[j] = __bfloat162float(h);
                lo[j] = v[j] - hi[j];
            }
            uint4 H0 = { packbf2(hi[0],hi[1]), packbf2(hi[2],hi[3]),
                         packbf2(hi[4],hi[5]), packbf2(hi[6],hi[7]) };
            uint4 H1 = { packbf2(hi[8],hi[9]), packbf2(hi[10],hi[11]),
                         packbf2(hi[12],hi[13]), packbf2(hi[14],hi[15]) };
            uint4 L0 = { packbf2(lo[0],lo[1]), packbf2(lo[2],lo[3]),
                         packbf2(lo[4],lo[5]), packbf2(lo[6],lo[7]) };
            uint4 L1 = { packbf2(lo[8],lo[9]), packbf2(lo[10],lo[11]),
                         packbf2(lo[12],lo[13]), packbf2(lo[14],lo[15]) };
            const uint32_t bb = tb + 16384;
            asm volatile("st.shared.v4.b32 [%0], {%1,%2,%3,%4};" ::
                "r"(bb + swz(lr, c0)), "r"(H0.x), "r"(H0.y), "r"(H0.z), "r"(H0.w));
            asm volatile("st.shared.v4.b32 [%0], {%1,%2,%3,%4};" ::
                "r"(bb + swz(lr, c0 + 1)), "r"(H1.x), "r"(H1.y), "r"(H1.z), "r"(H1.w));
            asm volatile("st.shared.v4.b32 [%0], {%1,%2,%3,%4};" ::
                "r"(bb + 8192 + swz(lr, c0)), "r"(L0.x), "r"(L0.y), "r"(L0.z), "r"(L0.w));
            asm volatile("st.shared.v4.b32 [%0], {%1,%2,%3,%4};" ::
                "r"(bb + 8192 + swz(lr, c0 + 1)), "r"(L1.x), "r"(L1.y), "r"(L1.z), "r"(L1.w));
        }
    };

    // ---------------- mainloop ----------------
    load_tiles(0, 0);
    __syncthreads();

    for (int kc = 0; kc < NC; kc++) {
        const int s = kc & 1;
        if (kc + 1 < NC) load_tiles(s ^ 1, kc + 1);

        const uint32_t aB = sb + s * 32768;
        const uint32_t bB = aB + 16384;

        #pragma unroll
        for (int ks = 0; ks < 2; ks++) {
            uint32_t ah[4][4], al[4][4], bh[4][2], bl[4][2];
            // A fragments (4 m-tiles, hi+lo)
            const int arow = wm * 64 + (lane & 7) + ((lane >> 3) & 1) * 8;
            const int ach  = ks * 2 + (lane >> 4);
            #pragma unroll
            for (int mt = 0; mt < 4; mt++) {
                int row = arow + mt * 16;
                uint32_t off = swz(row, ach);
                LDMX4(ah[mt], aB + off);
                LDMX4(al[mt], aB + 8192 + off);
            }
            // B fragments (4 n-tiles, hi+lo)
            const int bl15 = lane & 15;
            const int bch  = ks * 2 + ((bl15 >> 3) & 1);
            #pragma unroll
            for (int nt = 0; nt < 4; nt++) {
                int row = wn * 32 + nt * 8 + (bl15 & 7);
                uint32_t off = swz(row, bch);
                LDMX2(bh[nt], bB + off);
                LDMX2(bl[nt], bB + 8192 + off);
            }
            #pragma unroll
            for (int mt = 0; mt < 4; mt++)
                #pragma unroll
                for (int nt = 0; nt < 4; nt++) {
                    mma_bf16(acc[mt][nt], ah[mt], bh[nt]);
                    mma_bf16(acc[mt][nt], ah[mt], bl[nt]);
                    mma_bf16(acc[mt][nt], al[mt], bh[nt]);
                }
        }
        __syncthreads();
    }

    // ---------------- epilogue ----------------
    #pragma unroll
    for (int mt = 0; mt < 4; mt++) {
        #pragma unroll
        for (int nt = 0; nt < 4; nt++) {
            int r0 = m0 + wm * 64 + mt * 16 + (lane >> 2);
            int cc = n0 + wn * 32 + nt * 8 + ((lane & 3) << 1);
            int b  = cc / HW;
            int pp = cc & (HW - 1);
            #pragma unroll
            for (int hh = 0; hh < 2; hh++) {
                int row = r0 + hh * 8;
                float bv = bias[row];
                float2 v;
                v.x = acc[mt][nt][hh * 2 + 0] + bv;
                v.y = acc[mt][nt][hh * 2 + 1] + bv;
                if (RELU) { v.x = fmaxf(v.x, 0.f); v.y = fmaxf(v.y, 0.f); }
                *(float2*)&out[(b * Cout + row) * HW + pp] = v;
            }
        }
    }
}

// ============================================================================
// conv1 (3->64, 64x64 SAME) direct conv (fp32, f32x2 accumulation)
// ============================================================================
__global__ __launch_bounds__(256) void conv1_direct(
    const float* __restrict__ in, const float* __restrict__ wgt,
    const float* __restrict__ bias, float* __restrict__ out)
{
    __shared__ __align__(16) float wT[27][64];
    __shared__ float inr[3][3][66];

    const int tid = threadIdx.x;
    const int b   = blockIdx.x >> 6;
    const int y   = blockIdx.x & 63;
    const int x   = tid & 63;
    const int cog = tid >> 6;

    for (int i = tid; i < 1728; i += 256) {
        int co = i / 27, k = i - co * 27;
        wT[k][co] = wgt[i];
    }
    for (int i = tid; i < 594; i += 256) {
        int ci = i / 198, rem = i - ci * 198;
        int dy = rem / 66, xx = rem - dy * 66;
        int yy = y - 1 + dy, gx = xx - 1;
        float v = 0.f;
        if ((unsigned)yy < 64u && (unsigned)gx < 64u)
            v = in[(b * 3 + ci) * 4096 + yy * 64 + gx];
        inr[ci][dy][xx] = v;
    }
    __syncthreads();

    float iv[27];
    #pragma unroll
    for (int ci = 0; ci < 3; ci++)
        #pragma unroll
        for (int dy = 0; dy < 3; dy++)
            #pragma unroll
            for (int dx = 0; dx < 3; dx++)
                iv[ci * 9 + dy * 3 + dx] = inr[ci][dy][x + dx];

    ull acc2[8];
    #pragma unroll
    for (int p = 0; p < 8; p++) {
        float2 bb = *(const float2*)&bias[cog * 16 + p * 2];
        acc2[p] = pack2(bb.x, bb.y);
    }
    #pragma unroll
    for (int k = 0; k < 27; k++) {
        ull v2 = bcast2(iv[k]);
        F4U w0, w1, w2, w3;
        w0.v = *(const float4*)&wT[k][cog * 16 + 0];
        w1.v = *(const float4*)&wT[k][cog * 16 + 4];
        w2.v = *(const float4*)&wT[k][cog * 16 + 8];
        w3.v = *(const float4*)&wT[k][cog * 16 + 12];
        fma2(acc2[0], w0.u[0], v2); fma2(acc2[1], w0.u[1], v2);
        fma2(acc2[2], w1.u[0], v2); fma2(acc2[3], w1.u[1], v2);
        fma2(acc2[4], w2.u[0], v2); fma2(acc2[5], w2.u[1], v2);
        fma2(acc2[6], w3.u[0], v2); fma2(acc2[7], w3.u[1], v2);
    }

    #pragma unroll
    for (int p = 0; p < 8; p++) {
        UF2 u; u.u = acc2[p];
        #pragma unroll
        for (int h = 0; h < 2; h++) {
            int co = cog * 16 + p * 2 + h;
            out[(b * 64 + co) * 4096 + y * 64 + x] = u.f[h];
        }
    }
}

// ---------------- BN stats: slab-parallel, double atomics -------------------
__global__ void zero_stats(double* stat)
{
    if (threadIdx.x < 256) stat[threadIdx.x] = 0.0;
}

__global__ void bn_stats_slab(const float* __restrict__ x, double* __restrict__ stat,
                              int C, int HW, int hwsh)
{
    int c  = blockIdx.x;
    int b0 = blockIdx.y * 8;
    __shared__ double ss[256], sq[256];
    double s = 0.0, q = 0.0;
    int elems = 8 * HW;
    for (int j = threadIdx.x; j < elems; j += 256) {
        int b = b0 + (j >> hwsh);
        int p = j & (HW - 1);
        float v = x[(b * C + c) * HW + p];
        s += (double)v;
        q += (double)v * (double)v;
    }
    ss[threadIdx.x] = s; sq[threadIdx.x] = q;
    __syncthreads();
    for (int st = 128; st > 0; st >>= 1) {
        if (threadIdx.x < st) {
            ss[threadIdx.x] += ss[threadIdx.x + st];
            sq[threadIdx.x] += sq[threadIdx.x + st];
        }
        __syncthreads();
    }
    if (threadIdx.x == 0) {
        atomicAdd(&stat[c],     ss[0]);
        atomicAdd(&stat[C + c], sq[0]);
    }
}

__global__ void finalize_stats(const double* __restrict__ stat,
                               float* __restrict__ mean, float* __restrict__ var,
                               int C, double inv)
{
    int c = threadIdx.x;
    if (c < C) {
        double m = stat[c] * inv;
        mean[c] = (float)m;
        var[c]  = (float)(stat[C + c] * inv - m * m);
    }
}

// ---------------- fused BN-apply + ReLU + MaxPool(3,2,1) --------------------
__global__ void bn_relu_pool(const float* __restrict__ in, float* __restrict__ out,
                             const float* __restrict__ g, const float* __restrict__ bta,
                             const float* __restrict__ mean, const float* __restrict__ var,
                             int total, int H, int owsh, int cmask)
{
    int OW = H >> 1;
    for (int i = blockIdx.x * blockDim.x + threadIdx.x; i < total;
         i += gridDim.x * blockDim.x) {
        int ox = i & (OW - 1);
        int oy = (i >> owsh) & (OW - 1);
        int bc = i >> (2 * owsh);
        int c  = bc & cmask;
        float scale = g[c] * rsqrtf(var[c] + 1e-5f);
        float shift = bta[c] - mean[c] * scale;
        const float* src = in + (long long)bc * H * H;
        float m = 0.f;
        #pragma unroll
        for (int dy = 0; dy < 3; dy++) {
            int y = 2 * oy - 1 + dy;
            if ((unsigned)y >= (unsigned)H) continue;
            #pragma unroll
            for (int dx = 0; dx < 3; dx++) {
                int x = 2 * ox - 1 + dx;
                if ((unsigned)x >= (unsigned)H) continue;
                float v = fmaf(src[y * H + x], scale, shift);
                m = fmaxf(m, v);
            }
        }
        out[i] = m;
    }
}

// ---------------- MaxPool2d(3,2,1) ------------------------------------------
__global__ void maxpool3s2(const float* __restrict__ in, float* __restrict__ out,
                           int total, int H, int W, int owsh)
{
    int OW = W >> 1;
    for (int i = blockIdx.x * blockDim.x + threadIdx.x; i < total;
         i += gridDim.x * blockDim.x) {
        int ox = i & (OW - 1);
        int t  = i >> owsh;
        int oy = t & (OW - 1);
        int bc = t >> owsh;
        const float* src = in + (long long)bc * H * W;
        float m = -INFINITY;
        #pragma unroll
        for (int dy = 0; dy < 3; dy++) {
            int y = 2 * oy - 1 + dy;
            if ((unsigned)y >= (unsigned)H) continue;
            #pragma unroll
            for (int dx = 0; dx < 3; dx++) {
                int x = 2 * ox - 1 + dx;
                if ((unsigned)x >= (unsigned)W) continue;
                m = fmaxf(m, src[y * W + x]);
            }
        }
        out[i] = m;
    }
}

// ---------------- MLP stage 1: X @ W1 + b1, tanh ----------------------------
__global__ __launch_bounds__(256) void gemm_bias_tanh(
    const float* __restrict__ A, const float* __restrict__ Bw,
    const float* __restrict__ bias, float* __restrict__ C)
{
    const int M = 128, N = 600, K = 592;
    const int node = blockIdx.z;
    A    += node * M * K;
    Bw   += node * K * N;
    bias += node * N;
    C    += node * M * N;

    __shared__ __align__(16) float As[16][68];
    __shared__ __align__(16) float Bs[16][68];

    const int tid = threadIdx.x;
    const int m0 = blockIdx.y * 64;
    const int n0 = blockIdx.x * 64;
    const int tm = tid >> 4;
    const int tn = tid & 15;

    float acc[4][4] = {};

    for (int k0 = 0; k0 < K; k0 += 16) {
        #pragma unroll
        for (int i = 0; i < 4; i++) {
            int lin = tid + i * 256;
            int kk = lin & 15;
            int mm = lin >> 4;
            As[kk][mm] = A[(m0 + mm) * K + k0 + kk];
        }
        #pragma unroll
        for (int i = 0; i < 4; i++) {
            int lin = tid + i * 256;
            int nn = lin & 63;
            int kk = lin >> 6;
            int gn = n0 + nn;
            Bs[kk][nn] = (gn < N) ? Bw[(k0 + kk) * N + gn] : 0.f;
        }
        __syncthreads();
        #pragma unroll
        for (int kk = 0; kk < 16; kk++) {
            float4 a4 = *(const float4*)&As[kk][tm * 4];
            float4 b4 = *(const float4*)&Bs[kk][tn * 4];
            float av[4] = {a4.x, a4.y, a4.z, a4.w};
            float bv[4] = {b4.x, b4.y, b4.z, b4.w};
            #pragma unroll
            for (int i = 0; i < 4; i++)
                #pragma unroll
                for (int j = 0; j < 4; j++)
                    acc[i][j] = fmaf(av[i], bv[j], acc[i][j]);
        }
        __syncthreads();
    }

    #pragma unroll
    for (int i = 0; i < 4; i++) {
        int m = m0 + tm * 4 + i;
        #pragma unroll
        for (int j = 0; j < 4; j++) {
            int gn = n0 + tn * 4 + j;
            if (gn < N)
                C[m * N + gn] = tanhf(acc[i][j] + bias[gn]);
        }
    }
}

// ---------------- MLP stage 2 + softmax --------------------------------------
__global__ void mlp2_softmax(const float* __restrict__ h, const float* __restrict__ W2,
                             const float* __restrict__ b2, float* __restrict__ out)
{
    int nb = blockIdx.x;
    int node = nb >> 7;
    int b    = nb & 127;
    int lane = threadIdx.x;

    const float* hrow = h  + (node * 128 + b) * 600;
    const float* w    = W2 + node * 600 * 10;

    float acc[10];
    #pragma unroll
    for (int o = 0; o < 10; o++) acc[o] = 0.f;

    for (int i = lane; i < 600; i += 32) {
        float hv = hrow[i];
        const float* wr = w + i * 10;
        #pragma unroll
        for (int o = 0; o < 10; o++)
            acc[o] = fmaf(hv, wr[o], acc[o]);
    }
    #pragma unroll
    for (int o = 0; o < 10; o++)
        #pragma unroll
        for (int s = 16; s > 0; s >>= 1)
            acc[o] += __shfl_down_sync(0xffffffffu, acc[o], s);

    if (lane == 0) {
        float lg[10];
        float mx = -INFINITY;
        #pragma unroll
        for (int o = 0; o < 10; o++) {
            lg[o] = acc[o] + b2[node * 10 + o];
            mx = fmaxf(mx, lg[o]);
        }
        float se = 0.f;
        #pragma unroll
        for (int o = 0; o < 10; o++) { lg[o] = expf(lg[o] - mx); se += lg[o]; }
        float inv = 1.f / se;
        #pragma unroll
        for (int o = 0; o < 10; o++)
            out[(node * 128 + b) * 10 + o] = lg[o] * inv;
    }
}

// ---------------- head glue ---------------------------------------------------
__global__ void build_X1(const float* __restrict__ conv7, float* __restrict__ X, int total)
{
    for (int i = blockIdx.x * blockDim.x + threadIdx.x; i < total;
         i += gridDim.x * blockDim.x) {
        int c = i % 592;
        int t = i / 592;
        int b = t & 127;
        int n = t >> 7;
        X[i] = (c < 80) ? 0.f : conv7[((b * 512 + (c - 80)) << 4) + n];
    }
}

__global__ void build_X2(const float* __restrict__ P1, float* __restrict__ X, int total)
{
    for (int i = blockIdx.x * blockDim.x + threadIdx.x; i < total;
         i += gridDim.x * blockDim.x) {
        int j = i % 80;
        int t = i / 80;
        int b = t & 127;
        int n = t >> 7;
        int s   = j / 10;
        int cls = j - s * 10;
        int nb  = c_nidx[n][s];
        float v = (nb >= 0) ? P1[(nb * 128 + b) * 10 + cls] : 0.f;
        X[(n * 128 + b) * 592 + j] = v;
    }
}

__global__ void final_mean_sq(const float* __restrict__ preds2, float* __restrict__ out)
{
    int t = blockIdx.x * blockDim.x + threadIdx.x;
    if (t >= 1280) return;
    int b = t / 10, c = t - (t / 10) * 10;
    float s = 0.f;
    #pragma unroll
    for (int n = 0; n < 16; n++)
        s += preds2[(n * 128 + b) * 10 + c];
    s *= (1.f / 16.f);
    out[t] = s * s;
}

// ---------------- launcher -----------------------------------------------------
extern "C" void kernel_launch(void* const* d_in, const int* in_sizes, int n_in,
                              void* d_out, int out_size)
{
    const float* x     = (const float*)d_in[0];
    const float* cw1   = (const float*)d_in[1];
    const float* cb1   = (const float*)d_in[2];
    const float* bn1g  = (const float*)d_in[3];
    const float* bn1b  = (const float*)d_in[4];
    const float* cw2   = (const float*)d_in[5];
    const float* cb2   = (const float*)d_in[6];
    const float* bn2g  = (const float*)d_in[7];
    const float* bn2b  = (const float*)d_in[8];
    const float* cw3   = (const float*)d_in[9];
    const float* cb3   = (const float*)d_in[10];
    const float* cw4   = (const float*)d_in[11];
    const float* cb4   = (const float*)d_in[12];
    const float* cw5   = (const float*)d_in[13];
    const float* cb5   = (const float*)d_in[14];
    const float* cw6   = (const float*)d_in[15];
    const float* cb6   = (const float*)d_in[16];
    const float* cw7   = (const float*)d_in[17];
    const float* cb7   = (const float*)d_in[18];
    const float* W1    = (const float*)d_in[19];
    const float* b1    = (const float*)d_in[20];
    const float* W2    = (const float*)d_in[21];
    const float* b2    = (const float*)d_in[22];
    float* out = (float*)d_out;

    float *A, *Bb, *X, *H, *P1, *mean, *var;
    double* stat;
    cudaGetSymbolAddress((void**)&A,    g_A);
    cudaGetSymbolAddress((void**)&Bb,   g_B);
    cudaGetSymbolAddress((void**)&X,    g_X);
    cudaGetSymbolAddress((void**)&H,    g_H);
    cudaGetSymbolAddress((void**)&P1,   g_P1);
    cudaGetSymbolAddress((void**)&mean, g_mean);
    cudaGetSymbolAddress((void**)&var,  g_var);
    cudaGetSymbolAddress((void**)&stat, g_stat);

    cudaFuncSetAttribute(conv_hmma<64, 128, 32, 32, false>, cudaFuncAttributeMaxDynamicSharedMemorySize, HB_DSM);
    cudaFuncSetAttribute(conv_hmma<128, 256, 16, 16, true>, cudaFuncAttributeMaxDynamicSharedMemorySize, HB_DSM);
    cudaFuncSetAttribute(conv_hmma<256, 256, 16, 16, true>, cudaFuncAttributeMaxDynamicSharedMemorySize, HB_DSM);
    cudaFuncSetAttribute(conv_hmma<256, 512, 8, 8, true>,  cudaFuncAttributeMaxDynamicSharedMemorySize, HB_DSM);
    cudaFuncSetAttribute(conv_hmma<512, 512, 8, 8, true>,  cudaFuncAttributeMaxDynamicSharedMemorySize, HB_DSM);
    cudaFuncSetAttribute(conv_hmma<512, 512, 4, 4, true>,  cudaFuncAttributeMaxDynamicSharedMemorySize, HB_DSM);

    // ---- conv1 (3->64, 64x64) + BN + ReLU + pool -> 32x32
    conv1_direct<<<8192, 256>>>(x, cw1, cb1, A);
    zero_stats<<<1, 256>>>(stat);
    bn_stats_slab<<<dim3(64, 16), 256>>>(A, stat, 64, 4096, 12);
    finalize_stats<<<1, 128>>>(stat, mean, var, 64, 1.0 / 524288.0);
    bn_relu_pool<<<32768, 256>>>(A, Bb, bn1g, bn1b, mean, var, 8388608, 64, 5, 63);

    // ---- conv2 (64->128, 32x32): N=131072
    conv_hmma<64, 128, 32, 32, false><<<dim3(1024, 1), 256, HB_DSM>>>(Bb, cw2, cb2, A);
    zero_stats<<<1, 256>>>(stat);
    bn_stats_slab<<<dim3(128, 16), 256>>>(A, stat, 128, 1024, 10);
    finalize_stats<<<1, 128>>>(stat, mean, var, 128, 1.0 / 131072.0);
    bn_relu_pool<<<16384, 256>>>(A, Bb, bn2g, bn2b, mean, var, 4194304, 32, 4, 127);

    // ---- conv3 (128->256, 16x16): N=32768
    conv_hmma<128, 256, 16, 16, true><<<dim3(256, 2), 256, HB_DSM>>>(Bb, cw3, cb3, A);
    // ---- conv4 (256->256, 16x16): N=32768 + pool -> 8x8
    conv_hmma<256, 256, 16, 16, true><<<dim3(256, 2), 256, HB_DSM>>>(A, cw4, cb4, Bb);
    maxpool3s2<<<4096, 256>>>(Bb, A, 2097152, 16, 16, 3);

    // ---- conv5 (256->512, 8x8): N=8192
    conv_hmma<256, 512, 8, 8, true><<<dim3(64, 4), 256, HB_DSM>>>(A, cw5, cb5, Bb);
    // ---- conv6 (512->512, 8x8): N=8192 + pool -> 4x4
    conv_hmma<512, 512, 8, 8, true><<<dim3(64, 4), 256, HB_DSM>>>(Bb, cw6, cb6, A);
    maxpool3s2<<<2048, 256>>>(A, Bb, 1048576, 8, 8, 2);

    // ---- conv7 (512->512, 4x4): N=2048
    conv_hmma<512, 512, 4, 4, true><<<dim3(16, 4), 256, HB_DSM>>>(Bb, cw7, cb7, A);

    // ---- head: pass 1
    build_X1<<<4736, 256>>>(A, X, 16 * 128 * 592);
    gemm_bias_tanh<<<dim3(10, 2, 16), 256>>>(X, W1, b1, H);
    mlp2_softmax<<<2048, 32>>>(H, W2, b2, P1);

    // ---- head: pass 2
    build_X2<<<640, 256>>>(P1, X, 16 * 128 * 80);
    gemm_bias_tanh<<<dim3(10, 2, 16), 256>>>(X, W1, b1, H);
    mlp2_softmax<<<2048, 32>>>(H, W2, b2, out + 1280);

    final_mean_sq<<<5, 256>>>(out + 1280, out);
}

// round 7
// speedup vs baseline: 2.3145x; 1.2856x over previous
#include <cuda_runtime.h>
#include <cuda_bf16.h>
#include <cstdint>
#include <math.h>

#define BATCH 128
typedef unsigned long long ull;

// ---------------- f32x2 packed helpers (conv1 direct kernel) ---------------
__device__ __forceinline__ void fma2(ull& d, ull a, ull b) {
    asm("fma.rn.f32x2 %0, %1, %2, %0;" : "+l"(d) : "l"(a), "l"(b));
}
__device__ __forceinline__ ull bcast2(float x) {
    ull r; asm("mov.b64 %0, {%1, %1};" : "=l"(r) : "f"(x)); return r;
}
__device__ __forceinline__ ull pack2(float lo, float hi) {
    ull r; asm("mov.b64 %0, {%1, %2};" : "=l"(r) : "f"(lo), "f"(hi)); return r;
}
union F4U { float4 v; ull u[2]; };
union UF2 { ull u; float f[2]; };

// ---------------- HMMA helpers (mma.sync, compute_103-legal) ---------------
__device__ __forceinline__ uint32_t smem_u32(const void* p) {
    uint32_t a;
    asm("{ .reg .u64 t; cvta.to.shared.u64 t, %1; cvt.u32.u64 %0, t; }" : "=r"(a) : "l"(p));
    return a;
}
#define LDMX4(R, ADDR) \
    asm volatile("ldmatrix.sync.aligned.m8n8.x4.shared.b16 {%0,%1,%2,%3}, [%4];" \
        : "=r"((R)[0]), "=r"((R)[1]), "=r"((R)[2]), "=r"((R)[3]) : "r"(ADDR))
#define LDMX2(R, ADDR) \
    asm volatile("ldmatrix.sync.aligned.m8n8.x2.shared.b16 {%0,%1}, [%2];" \
        : "=r"((R)[0]), "=r"((R)[1]) : "r"(ADDR))

__device__ __forceinline__ void mma_bf16(float* d, const uint32_t* a, const uint32_t* b) {
    asm volatile(
        "mma.sync.aligned.m16n8k16.row.col.f32.bf16.bf16.f32 "
        "{%0,%1,%2,%3}, {%4,%5,%6,%7}, {%8,%9}, {%0,%1,%2,%3};"
        : "+f"(d[0]), "+f"(d[1]), "+f"(d[2]), "+f"(d[3])
        : "r"(a[0]), "r"(a[1]), "r"(a[2]), "r"(a[3]), "r"(b[0]), "r"(b[1]));
}

__device__ __forceinline__ uint32_t packbf2(float x, float y) {
    __nv_bfloat162 t = __floats2bfloat162_rn(x, y);
    return *(uint32_t*)&t;
}

// ---------------- scratch --------------------------------------------------
__device__ float g_A[33554432];                 // 134 MB conv activations
__device__ float g_B[8388608];                  // 33.5 MB
__device__ float g_X[16 * 128 * 592];
__device__ float g_H[16 * 128 * 600];
__device__ float g_P1[16 * 128 * 10];
__device__ float g_mean[128];
__device__ float g_var[128];
__device__ double g_stat[256];

__device__ const int c_nidx[16][8] = {
    {1, 4, 5, -1, -1, -1, -1, -1},
    {0, 2, 5, 4, 6, -1, -1, -1},
    {1, 3, 6, 5, 7, -1, -1, -1},
    {2, 7, 6, -1, -1, -1, -1, -1},
    {0, 5, 8, 1, 9, -1, -1, -1},
    {1, 4, 6, 9, 0, 2, 8, 10},
    {2, 5, 7, 10, 1, 3, 9, 11},
    {3, 6, 11, 2, 10, -1, -1, -1},
    {4, 9, 12, 5, 13, -1, -1, -1},
    {5, 8, 10, 13, 4, 6, 12, 14},
    {6, 9, 11, 14, 5, 7, 13, 15},
    {7, 10, 15, 6, 14, -1, -1, -1},
    {8, 13, 9, -1, -1, -1, -1, -1},
    {9, 12, 14, 8, 10, -1, -1, -1},
    {10, 13, 15, 9, 11, -1, -1, -1},
    {11, 14, 10, -1, -1, -1, -1, -1},
};

// ============================================================================
// HMMA bf16x3 implicit-GEMM conv: D[Cout,N] = W[Cout,K] @ im2col[N,K]^T
// BM=128, BN=128, BK=32, 256 thr (8 warps 2Mx4N, warp tile 64x32).
// In-kernel fp32 -> (hi,lo) bf16 split; no materialized im2col.
// 2 CTAs/SM: one CTA's loader phase overlaps the other's MMA phase.
// ============================================================================
static constexpr int HB_DSM = 65536 + 1024;     // 2 x (Ah,Al,Bh,Bl) + align slack

template<int Cin, int Cout, int H, int W, bool RELU>
__global__ __launch_bounds__(256, 2)
void conv_hmma(const float* __restrict__ in, const float* __restrict__ wgt,
               const float* __restrict__ bias, float* __restrict__ out)
{
    constexpr int K  = Cin * 9;
    constexpr int HW = H * W;
    constexpr int NC = K / 32;

    extern __shared__ char dsm_raw[];
    const uint32_t sb = (smem_u32(dsm_raw) + 1023u) & ~1023u;

    const int tid  = threadIdx.x;
    const int wid  = tid >> 5;
    const int lane = tid & 31;
    const int wm   = wid & 1;          // M half (64 rows each)
    const int wn   = wid >> 1;         // N quarter (32 cols each)
    const int n0   = blockIdx.x * 128;
    const int m0   = blockIdx.y * 128;

    // ---- loader state (each thread: one row, 16 k's per chunk)
    const int lr = tid >> 1;           // 0..127
    const int lh = tid & 1;            // 0 or 1 (k halves)
    const int gn = n0 + lr;
    const int bidx = gn / HW;
    const int p    = gn & (HW - 1);
    const int y0   = p / W;
    const int x0   = p & (W - 1);
    const float* srcb = in + bidx * Cin * HW;
    const float* wp0  = wgt + (m0 + lr) * K + lh * 16;

    float acc[4][4][4];
    #pragma unroll
    for (int mt = 0; mt < 4; mt++)
        #pragma unroll
        for (int nt = 0; nt < 4; nt++)
            #pragma unroll
            for (int e = 0; e < 4; e++) acc[mt][nt][e] = 0.f;

    auto swz = [](int row, int ch) { return row * 64 + ((ch ^ ((row >> 1) & 3)) << 4); };
    const int c0 = 2 * lh;

    // ---------------- tile loader ----------------
    auto load_tiles = [&](int s, int kc) {
        const uint32_t tb = sb + s * 32768;
        // A: weights, contiguous 16 floats
        {
            const float* wp = wp0 + kc * 32;
            float4 w0 = *(const float4*)(wp + 0);
            float4 w1 = *(const float4*)(wp + 4);
            float4 w2 = *(const float4*)(wp + 8);
            float4 w3 = *(const float4*)(wp + 12);
            float v[16] = {w0.x,w0.y,w0.z,w0.w, w1.x,w1.y,w1.z,w1.w,
                           w2.x,w2.y,w2.z,w2.w, w3.x,w3.y,w3.z,w3.w};
            float hi[16], lo[16];
            #pragma unroll
            for (int j = 0; j < 16; j++) {
                __nv_bfloat16 h = __float2bfloat16(v[j]);
                hi[j] = __bfloat162float(h);
                lo[j] = v[j] - hi[j];
            }
            uint4 H0 = { packbf2(hi[0],hi[1]), packbf2(hi[2],hi[3]),
                         packbf2(hi[4],hi[5]), packbf2(hi[6],hi[7]) };
            uint4 H1 = { packbf2(hi[8],hi[9]), packbf2(hi[10],hi[11]),
                         packbf2(hi[12],hi[13]), packbf2(hi[14],hi[15]) };
            uint4 L0 = { packbf2(lo[0],lo[1]), packbf2(lo[2],lo[3]),
                         packbf2(lo[4],lo[5]), packbf2(lo[6],lo[7]) };
            uint4 L1 = { packbf2(lo[8],lo[9]), packbf2(lo[10],lo[11]),
                         packbf2(lo[12],lo[13]), packbf2(lo[14],lo[15]) };
            asm volatile("st.shared.v4.b32 [%0], {%1,%2,%3,%4};" ::
                "r"(tb + swz(lr, c0)), "r"(H0.x), "r"(H0.y), "r"(H0.z), "r"(H0.w));
            asm volatile("st.shared.v4.b32 [%0], {%1,%2,%3,%4};" ::
                "r"(tb + swz(lr, c0 + 1)), "r"(H1.x), "r"(H1.y), "r"(H1.z), "r"(H1.w));
            asm volatile("st.shared.v4.b32 [%0], {%1,%2,%3,%4};" ::
                "r"(tb + 8192 + swz(lr, c0)), "r"(L0.x), "r"(L0.y), "r"(L0.z), "r"(L0.w));
            asm volatile("st.shared.v4.b32 [%0], {%1,%2,%3,%4};" ::
                "r"(tb + 8192 + swz(lr, c0 + 1)), "r"(L1.x), "r"(L1.y), "r"(L1.z), "r"(L1.w));
        }
        // B: im2col gather, 16 consecutive k
        {
            int k = kc * 32 + lh * 16;
            int ci = k / 9;
            int f  = k - 9 * ci;
            int cioff = ci * HW;
            float v[16];
            #pragma unroll
            for (int j = 0; j < 16; j++) {
                int dy = (f * 11) >> 5;
                int dx = f - 3 * dy;
                int y = y0 + dy - 1, x = x0 + dx - 1;
                v[j] = ((unsigned)y < (unsigned)H && (unsigned)x < (unsigned)W)
                         ? __ldg(srcb + cioff + y * W + x) : 0.f;
                f++; if (f == 9) { f = 0; cioff += HW; }
            }
            float hi[16], lo[16];
            #pragma unroll
            for (int j = 0; j < 16; j++) {
                __nv_bfloat16 h = __float2bfloat16(v[j]);
                hi[j] = __bfloat162float(h);
                lo[j] = v[j] - hi[j];
            }
            uint4 H0 = { packbf2(hi[0],hi[1]), packbf2(hi[2],hi[3]),
                         packbf2(hi[4],hi[5]), packbf2(hi[6],hi[7]) };
            uint4 H1 = { packbf2(hi[8],hi[9]), packbf2(hi[10],hi[11]),
                         packbf2(hi[12],hi[13]), packbf2(hi[14],hi[15]) };
            uint4 L0 = { packbf2(lo[0],lo[1]), packbf2(lo[2],lo[3]),
                         packbf2(lo[4],lo[5]), packbf2(lo[6],lo[7]) };
            uint4 L1 = { packbf2(lo[8],lo[9]), packbf2(lo[10],lo[11]),
                         packbf2(lo[12],lo[13]), packbf2(lo[14],lo[15]) };
            const uint32_t bb = tb + 16384;
            asm volatile("st.shared.v4.b32 [%0], {%1,%2,%3,%4};" ::
                "r"(bb + swz(lr, c0)), "r"(H0.x), "r"(H0.y), "r"(H0.z), "r"(H0.w));
            asm volatile("st.shared.v4.b32 [%0], {%1,%2,%3,%4};" ::
                "r"(bb + swz(lr, c0 + 1)), "r"(H1.x), "r"(H1.y), "r"(H1.z), "r"(H1.w));
            asm volatile("st.shared.v4.b32 [%0], {%1,%2,%3,%4};" ::
                "r"(bb + 8192 + swz(lr, c0)), "r"(L0.x), "r"(L0.y), "r"(L0.z), "r"(L0.w));
            asm volatile("st.shared.v4.b32 [%0], {%1,%2,%3,%4};" ::
                "r"(bb + 8192 + swz(lr, c0 + 1)), "r"(L1.x), "r"(L1.y), "r"(L1.z), "r"(L1.w));
        }
    };

    // ---------------- mainloop ----------------
    load_tiles(0, 0);
    __syncthreads();

    for (int kc = 0; kc < NC; kc++) {
        const int s = kc & 1;
        if (kc + 1 < NC) load_tiles(s ^ 1, kc + 1);

        const uint32_t aB = sb + s * 32768;
        const uint32_t bB = aB + 16384;

        #pragma unroll
        for (int ks = 0; ks < 2; ks++) {
            // B fragments first (held across the mt loop)
            uint32_t bh[4][2], bl[4][2];
            const int bl15 = lane & 15;
            const int bch  = ks * 2 + ((bl15 >> 3) & 1);
            #pragma unroll
            for (int nt = 0; nt < 4; nt++) {
                int row = wn * 32 + nt * 8 + (bl15 & 7);
                uint32_t off = swz(row, bch);
                LDMX2(bh[nt], bB + off);
                LDMX2(bl[nt], bB + 8192 + off);
            }
            // A fragments per m-tile, consumed immediately (register-lean)
            const int arow = wm * 64 + (lane & 7) + ((lane >> 3) & 1) * 8;
            const int ach  = ks * 2 + (lane >> 4);
            #pragma unroll
            for (int mt = 0; mt < 4; mt++) {
                uint32_t ah[4], al[4];
                int row = arow + mt * 16;
                uint32_t off = swz(row, ach);
                LDMX4(ah, aB + off);
                LDMX4(al, aB + 8192 + off);
                #pragma unroll
                for (int nt = 0; nt < 4; nt++) {
                    mma_bf16(acc[mt][nt], ah, bh[nt]);
                    mma_bf16(acc[mt][nt], ah, bl[nt]);
                    mma_bf16(acc[mt][nt], al, bh[nt]);
                }
            }
        }
        __syncthreads();
    }

    // ---------------- epilogue ----------------
    #pragma unroll
    for (int mt = 0; mt < 4; mt++) {
        #pragma unroll
        for (int nt = 0; nt < 4; nt++) {
            int r0 = m0 + wm * 64 + mt * 16 + (lane >> 2);
            int cc = n0 + wn * 32 + nt * 8 + ((lane & 3) << 1);
            int b  = cc / HW;
            int pp = cc & (HW - 1);
            #pragma unroll
            for (int hh = 0; hh < 2; hh++) {
                int row = r0 + hh * 8;
                float bv = bias[row];
                float2 v;
                v.x = acc[mt][nt][hh * 2 + 0] + bv;
                v.y = acc[mt][nt][hh * 2 + 1] + bv;
                if (RELU) { v.x = fmaxf(v.x, 0.f); v.y = fmaxf(v.y, 0.f); }
                *(float2*)&out[(b * Cout + row) * HW + pp] = v;
            }
        }
    }
}

// ============================================================================
// conv1 (3->64, 64x64 SAME) direct conv (fp32, f32x2 accumulation)
// ============================================================================
__global__ __launch_bounds__(256) void conv1_direct(
    const float* __restrict__ in, const float* __restrict__ wgt,
    const float* __restrict__ bias, float* __restrict__ out)
{
    __shared__ __align__(16) float wT[27][64];
    __shared__ float inr[3][3][66];

    const int tid = threadIdx.x;
    const int b   = blockIdx.x >> 6;
    const int y   = blockIdx.x & 63;
    const int x   = tid & 63;
    const int cog = tid >> 6;

    for (int i = tid; i < 1728; i += 256) {
        int co = i / 27, k = i - co * 27;
        wT[k][co] = wgt[i];
    }
    for (int i = tid; i < 594; i += 256) {
        int ci = i / 198, rem = i - ci * 198;
        int dy = rem / 66, xx = rem - dy * 66;
        int yy = y - 1 + dy, gx = xx - 1;
        float v = 0.f;
        if ((unsigned)yy < 64u && (unsigned)gx < 64u)
            v = in[(b * 3 + ci) * 4096 + yy * 64 + gx];
        inr[ci][dy][xx] = v;
    }
    __syncthreads();

    float iv[27];
    #pragma unroll
    for (int ci = 0; ci < 3; ci++)
        #pragma unroll
        for (int dy = 0; dy < 3; dy++)
            #pragma unroll
            for (int dx = 0; dx < 3; dx++)
                iv[ci * 9 + dy * 3 + dx] = inr[ci][dy][x + dx];

    ull acc2[8];
    #pragma unroll
    for (int p = 0; p < 8; p++) {
        float2 bb = *(const float2*)&bias[cog * 16 + p * 2];
        acc2[p] = pack2(bb.x, bb.y);
    }
    #pragma unroll
    for (int k = 0; k < 27; k++) {
        ull v2 = bcast2(iv[k]);
        F4U w0, w1, w2, w3;
        w0.v = *(const float4*)&wT[k][cog * 16 + 0];
        w1.v = *(const float4*)&wT[k][cog * 16 + 4];
        w2.v = *(const float4*)&wT[k][cog * 16 + 8];
        w3.v = *(const float4*)&wT[k][cog * 16 + 12];
        fma2(acc2[0], w0.u[0], v2); fma2(acc2[1], w0.u[1], v2);
        fma2(acc2[2], w1.u[0], v2); fma2(acc2[3], w1.u[1], v2);
        fma2(acc2[4], w2.u[0], v2); fma2(acc2[5], w2.u[1], v2);
        fma2(acc2[6], w3.u[0], v2); fma2(acc2[7], w3.u[1], v2);
    }

    #pragma unroll
    for (int p = 0; p < 8; p++) {
        UF2 u; u.u = acc2[p];
        #pragma unroll
        for (int h = 0; h < 2; h++) {
            int co = cog * 16 + p * 2 + h;
            out[(b * 64 + co) * 4096 + y * 64 + x] = u.f[h];
        }
    }
}

// ---------------- BN stats: slab-parallel, double atomics -------------------
__global__ void zero_stats(double* stat)
{
    if (threadIdx.x < 256) stat[threadIdx.x] = 0.0;
}

__global__ void bn_stats_slab(const float* __restrict__ x, double* __restrict__ stat,
                              int C, int HW, int hwsh)
{
    int c  = blockIdx.x;
    int b0 = blockIdx.y * 8;
    __shared__ double ss[256], sq[256];
    double s = 0.0, q = 0.0;
    int elems = 8 * HW;
    for (int j = threadIdx.x; j < elems; j += 256) {
        int b = b0 + (j >> hwsh);
        int p = j & (HW - 1);
        float v = x[(b * C + c) * HW + p];
        s += (double)v;
        q += (double)v * (double)v;
    }
    ss[threadIdx.x] = s; sq[threadIdx.x] = q;
    __syncthreads();
    for (int st = 128; st > 0; st >>= 1) {
        if (threadIdx.x < st) {
            ss[threadIdx.x] += ss[threadIdx.x + st];
            sq[threadIdx.x] += sq[threadIdx.x + st];
        }
        __syncthreads();
    }
    if (threadIdx.x == 0) {
        atomicAdd(&stat[c],     ss[0]);
        atomicAdd(&stat[C + c], sq[0]);
    }
}

__global__ void finalize_stats(const double* __restrict__ stat,
                               float* __restrict__ mean, float* __restrict__ var,
                               int C, double inv)
{
    int c = threadIdx.x;
    if (c < C) {
        double m = stat[c] * inv;
        mean[c] = (float)m;
        var[c]  = (float)(stat[C + c] * inv - m * m);
    }
}

// ---------------- fused BN-apply + ReLU + MaxPool(3,2,1) --------------------
__global__ void bn_relu_pool(const float* __restrict__ in, float* __restrict__ out,
                             const float* __restrict__ g, const float* __restrict__ bta,
                             const float* __restrict__ mean, const float* __restrict__ var,
                             int total, int H, int owsh, int cmask)
{
    int OW = H >> 1;
    for (int i = blockIdx.x * blockDim.x + threadIdx.x; i < total;
         i += gridDim.x * blockDim.x) {
        int ox = i & (OW - 1);
        int oy = (i >> owsh) & (OW - 1);
        int bc = i >> (2 * owsh);
        int c  = bc & cmask;
        float scale = g[c] * rsqrtf(var[c] + 1e-5f);
        float shift = bta[c] - mean[c] * scale;
        const float* src = in + (long long)bc * H * H;
        float m = 0.f;
        #pragma unroll
        for (int dy = 0; dy < 3; dy++) {
            int y = 2 * oy - 1 + dy;
            if ((unsigned)y >= (unsigned)H) continue;
            #pragma unroll
            for (int dx = 0; dx < 3; dx++) {
                int x = 2 * ox - 1 + dx;
                if ((unsigned)x >= (unsigned)H) continue;
                float v = fmaf(src[y * H + x], scale, shift);
                m = fmaxf(m, v);
            }
        }
        out[i] = m;
    }
}

// ---------------- MaxPool2d(3,2,1) ------------------------------------------
__global__ void maxpool3s2(const float* __restrict__ in, float* __restrict__ out,
                           int total, int H, int W, int owsh)
{
    int OW = W >> 1;
    for (int i = blockIdx.x * blockDim.x + threadIdx.x; i < total;
         i += gridDim.x * blockDim.x) {
        int ox = i & (OW - 1);
        int t  = i >> owsh;
        int oy = t & (OW - 1);
        int bc = t >> owsh;
        const float* src = in + (long long)bc * H * W;
        float m = -INFINITY;
        #pragma unroll
        for (int dy = 0; dy < 3; dy++) {
            int y = 2 * oy - 1 + dy;
            if ((unsigned)y >= (unsigned)H) continue;
            #pragma unroll
            for (int dx = 0; dx < 3; dx++) {
                int x = 2 * ox - 1 + dx;
                if ((unsigned)x >= (unsigned)W) continue;
                m = fmaxf(m, src[y * W + x]);
            }
        }
        out[i] = m;
    }
}

// ---------------- MLP stage 1: X @ W1 + b1, tanh ----------------------------
__global__ __launch_bounds__(256) void gemm_bias_tanh(
    const float* __restrict__ A, const float* __restrict__ Bw,
    const float* __restrict__ bias, float* __restrict__ C)
{
    const int M = 128, N = 600, K = 592;
    const int node = blockIdx.z;
    A    += node * M * K;
    Bw   += node * K * N;
    bias += node * N;
    C    += node * M * N;

    __shared__ __align__(16) float As[16][68];
    __shared__ __align__(16) float Bs[16][68];

    const int tid = threadIdx.x;
    const int m0 = blockIdx.y * 64;
    const int n0 = blockIdx.x * 64;
    const int tm = tid >> 4;
    const int tn = tid & 15;

    float acc[4][4] = {};

    for (int k0 = 0; k0 < K; k0 += 16) {
        #pragma unroll
        for (int i = 0; i < 4; i++) {
            int lin = tid + i * 256;
            int kk = lin & 15;
            int mm = lin >> 4;
            As[kk][mm] = A[(m0 + mm) * K + k0 + kk];
        }
        #pragma unroll
        for (int i = 0; i < 4; i++) {
            int lin = tid + i * 256;
            int nn = lin & 63;
            int kk = lin >> 6;
            int gn = n0 + nn;
            Bs[kk][nn] = (gn < N) ? Bw[(k0 + kk) * N + gn] : 0.f;
        }
        __syncthreads();
        #pragma unroll
        for (int kk = 0; kk < 16; kk++) {
            float4 a4 = *(const float4*)&As[kk][tm * 4];
            float4 b4 = *(const float4*)&Bs[kk][tn * 4];
            float av[4] = {a4.x, a4.y, a4.z, a4.w};
            float bv[4] = {b4.x, b4.y, b4.z, b4.w};
            #pragma unroll
            for (int i = 0; i < 4; i++)
                #pragma unroll
                for (int j = 0; j < 4; j++)
                    acc[i][j] = fmaf(av[i], bv[j], acc[i][j]);
        }
        __syncthreads();
    }

    #pragma unroll
    for (int i = 0; i < 4; i++) {
        int m = m0 + tm * 4 + i;
        #pragma unroll
        for (int j = 0; j < 4; j++) {
            int gn = n0 + tn * 4 + j;
            if (gn < N)
                C[m * N + gn] = tanhf(acc[i][j] + bias[gn]);
        }
    }
}

// ---------------- MLP stage 2 + softmax --------------------------------------
__global__ void mlp2_softmax(const float* __restrict__ h, const float* __restrict__ W2,
                             const float* __restrict__ b2, float* __restrict__ out)
{
    int nb = blockIdx.x;
    int node = nb >> 7;
    int b    = nb & 127;
    int lane = threadIdx.x;

    const float* hrow = h  + (node * 128 + b) * 600;
    const float* w    = W2 + node * 600 * 10;

    float acc[10];
    #pragma unroll
    for (int o = 0; o < 10; o++) acc[o] = 0.f;

    for (int i = lane; i < 600; i += 32) {
        float hv = hrow[i];
        const float* wr = w + i * 10;
        #pragma unroll
        for (int o = 0; o < 10; o++)
            acc[o] = fmaf(hv, wr[o], acc[o]);
    }
    #pragma unroll
    for (int o = 0; o < 10; o++)
        #pragma unroll
        for (int s = 16; s > 0; s >>= 1)
            acc[o] += __shfl_down_sync(0xffffffffu, acc[o], s);

    if (lane == 0) {
        float lg[10];
        float mx = -INFINITY;
        #pragma unroll
        for (int o = 0; o < 10; o++) {
            lg[o] = acc[o] + b2[node * 10 + o];
            mx = fmaxf(mx, lg[o]);
        }
        float se = 0.f;
        #pragma unroll
        for (int o = 0; o < 10; o++) { lg[o] = expf(lg[o] - mx); se += lg[o]; }
        float inv = 1.f / se;
        #pragma unroll
        for (int o = 0; o < 10; o++)
            out[(node * 128 + b) * 10 + o] = lg[o] * inv;
    }
}

// ---------------- head glue ---------------------------------------------------
__global__ void build_X1(const float* __restrict__ conv7, float* __restrict__ X, int total)
{
    for (int i = blockIdx.x * blockDim.x + threadIdx.x; i < total;
         i += gridDim.x * blockDim.x) {
        int c = i % 592;
        int t = i / 592;
        int b = t & 127;
        int n = t >> 7;
        X[i] = (c < 80) ? 0.f : conv7[((b * 512 + (c - 80)) << 4) + n];
    }
}

__global__ void build_X2(const float* __restrict__ P1, float* __restrict__ X, int total)
{
    for (int i = blockIdx.x * blockDim.x + threadIdx.x; i < total;
         i += gridDim.x * blockDim.x) {
        int j = i % 80;
        int t = i / 80;
        int b = t & 127;
        int n = t >> 7;
        int s   = j / 10;
        int cls = j - s * 10;
        int nb  = c_nidx[n][s];
        float v = (nb >= 0) ? P1[(nb * 128 + b) * 10 + cls] : 0.f;
        X[(n * 128 + b) * 592 + j] = v;
    }
}

__global__ void final_mean_sq(const float* __restrict__ preds2, float* __restrict__ out)
{
    int t = blockIdx.x * blockDim.x + threadIdx.x;
    if (t >= 1280) return;
    int b = t / 10, c = t - (t / 10) * 10;
    float s = 0.f;
    #pragma unroll
    for (int n = 0; n < 16; n++)
        s += preds2[(n * 128 + b) * 10 + c];
    s *= (1.f / 16.f);
    out[t] = s * s;
}

// ---------------- launcher -----------------------------------------------------
extern "C" void kernel_launch(void* const* d_in, const int* in_sizes, int n_in,
                              void* d_out, int out_size)
{
    const float* x     = (const float*)d_in[0];
    const float* cw1   = (const float*)d_in[1];
    const float* cb1   = (const float*)d_in[2];
    const float* bn1g  = (const float*)d_in[3];
    const float* bn1b  = (const float*)d_in[4];
    const float* cw2   = (const float*)d_in[5];
    const float* cb2   = (const float*)d_in[6];
    const float* bn2g  = (const float*)d_in[7];
    const float* bn2b  = (const float*)d_in[8];
    const float* cw3   = (const float*)d_in[9];
    const float* cb3   = (const float*)d_in[10];
    const float* cw4   = (const float*)d_in[11];
    const float* cb4   = (const float*)d_in[12];
    const float* cw5   = (const float*)d_in[13];
    const float* cb5   = (const float*)d_in[14];
    const float* cw6   = (const float*)d_in[15];
    const float* cb6   = (const float*)d_in[16];
    const float* cw7   = (const float*)d_in[17];
    const float* cb7   = (const float*)d_in[18];
    const float* W1    = (const float*)d_in[19];
    const float* b1    = (const float*)d_in[20];
    const float* W2    = (const float*)d_in[21];
    const float* b2    = (const float*)d_in[22];
    float* out = (float*)d_out;

    float *A, *Bb, *X, *H, *P1, *mean, *var;
    double* stat;
    cudaGetSymbolAddress((void**)&A,    g_A);
    cudaGetSymbolAddress((void**)&Bb,   g_B);
    cudaGetSymbolAddress((void**)&X,    g_X);
    cudaGetSymbolAddress((void**)&H,    g_H);
    cudaGetSymbolAddress((void**)&P1,   g_P1);
    cudaGetSymbolAddress((void**)&mean, g_mean);
    cudaGetSymbolAddress((void**)&var,  g_var);
    cudaGetSymbolAddress((void**)&stat, g_stat);

    cudaFuncSetAttribute(conv_hmma<64, 128, 32, 32, false>, cudaFuncAttributeMaxDynamicSharedMemorySize, HB_DSM);
    cudaFuncSetAttribute(conv_hmma<128, 256, 16, 16, true>, cudaFuncAttributeMaxDynamicSharedMemorySize, HB_DSM);
    cudaFuncSetAttribute(conv_hmma<256, 256, 16, 16, true>, cudaFuncAttributeMaxDynamicSharedMemorySize, HB_DSM);
    cudaFuncSetAttribute(conv_hmma<256, 512, 8, 8, true>,  cudaFuncAttributeMaxDynamicSharedMemorySize, HB_DSM);
    cudaFuncSetAttribute(conv_hmma<512, 512, 8, 8, true>,  cudaFuncAttributeMaxDynamicSharedMemorySize, HB_DSM);
    cudaFuncSetAttribute(conv_hmma<512, 512, 4, 4, true>,  cudaFuncAttributeMaxDynamicSharedMemorySize, HB_DSM);

    // ---- conv1 (3->64, 64x64) + BN + ReLU + pool -> 32x32
    conv1_direct<<<8192, 256>>>(x, cw1, cb1, A);
    zero_stats<<<1, 256>>>(stat);
    bn_stats_slab<<<dim3(64, 16), 256>>>(A, stat, 64, 4096, 12);
    finalize_stats<<<1, 128>>>(stat, mean, var, 64, 1.0 / 524288.0);
    bn_relu_pool<<<32768, 256>>>(A, Bb, bn1g, bn1b, mean, var, 8388608, 64, 5, 63);

    // ---- conv2 (64->128, 32x32): N=131072
    conv_hmma<64, 128, 32, 32, false><<<dim3(1024, 1), 256, HB_DSM>>>(Bb, cw2, cb2, A);
    zero_stats<<<1, 256>>>(stat);
    bn_stats_slab<<<dim3(128, 16), 256>>>(A, stat, 128, 1024, 10);
    finalize_stats<<<1, 128>>>(stat, mean, var, 128, 1.0 / 131072.0);
    bn_relu_pool<<<16384, 256>>>(A, Bb, bn2g, bn2b, mean, var, 4194304, 32, 4, 127);

    // ---- conv3 (128->256, 16x16): N=32768
    conv_hmma<128, 256, 16, 16, true><<<dim3(256, 2), 256, HB_DSM>>>(Bb, cw3, cb3, A);
    // ---- conv4 (256->256, 16x16): N=32768 + pool -> 8x8
    conv_hmma<256, 256, 16, 16, true><<<dim3(256, 2), 256, HB_DSM>>>(A, cw4, cb4, Bb);
    maxpool3s2<<<4096, 256>>>(Bb, A, 2097152, 16, 16, 3);

    // ---- conv5 (256->512, 8x8): N=8192
    conv_hmma<256, 512, 8, 8, true><<<dim3(64, 4), 256, HB_DSM>>>(A, cw5, cb5, Bb);
    // ---- conv6 (512->512, 8x8): N=8192 + pool -> 4x4
    conv_hmma<512, 512, 8, 8, true><<<dim3(64, 4), 256, HB_DSM>>>(Bb, cw6, cb6, A);
    maxpool3s2<<<2048, 256>>>(A, Bb, 1048576, 8, 8, 2);

    // ---- conv7 (512->512, 4x4): N=2048
    conv_hmma<512, 512, 4, 4, true><<<dim3(16, 4), 256, HB_DSM>>>(Bb, cw7, cb7, A);

    // ---- head: pass 1
    build_X1<<<4736, 256>>>(A, X, 16 * 128 * 592);
    gemm_bias_tanh<<<dim3(10, 2, 16), 256>>>(X, W1, b1, H);
    mlp2_softmax<<<2048, 32>>>(H, W2, b2, P1);

    // ---- head: pass 2
    build_X2<<<640, 256>>>(P1, X, 16 * 128 * 80);
    gemm_bias_tanh<<<dim3(10, 2, 16), 256>>>(X, W1, b1, H);
    mlp2_softmax<<<2048, 32>>>(H, W2, b2, out + 1280);

    final_mean_sq<<<5, 256>>>(out + 1280, out);
}

// round 8
// speedup vs baseline: 2.6144x; 1.1296x over previous
#include <cuda_runtime.h>
#include <cuda_bf16.h>
#include <cstdint>
#include <math.h>

#define BATCH 128
typedef unsigned long long ull;

// ---------------- f32x2 packed helpers (conv1 direct kernel) ---------------
__device__ __forceinline__ void fma2(ull& d, ull a, ull b) {
    asm("fma.rn.f32x2 %0, %1, %2, %0;" : "+l"(d) : "l"(a), "l"(b));
}
__device__ __forceinline__ ull bcast2(float x) {
    ull r; asm("mov.b64 %0, {%1, %1};" : "=l"(r) : "f"(x)); return r;
}
__device__ __forceinline__ ull pack2(float lo, float hi) {
    ull r; asm("mov.b64 %0, {%1, %2};" : "=l"(r) : "f"(lo), "f"(hi)); return r;
}
union F4U { float4 v; ull u[2]; };
union UF2 { ull u; float f[2]; };

// ---------------- HMMA helpers (mma.sync, compute_103-legal) ---------------
__device__ __forceinline__ uint32_t smem_u32(const void* p) {
    uint32_t a;
    asm("{ .reg .u64 t; cvta.to.shared.u64 t, %1; cvt.u32.u64 %0, t; }" : "=r"(a) : "l"(p));
    return a;
}
#define LDMX4(R, ADDR) \
    asm volatile("ldmatrix.sync.aligned.m8n8.x4.shared.b16 {%0,%1,%2,%3}, [%4];" \
        : "=r"((R)[0]), "=r"((R)[1]), "=r"((R)[2]), "=r"((R)[3]) : "r"(ADDR))

__device__ __forceinline__ void mma_bf16(float* d, const uint32_t* a, const uint32_t* b) {
    asm volatile(
        "mma.sync.aligned.m16n8k16.row.col.f32.bf16.bf16.f32 "
        "{%0,%1,%2,%3}, {%4,%5,%6,%7}, {%8,%9}, {%0,%1,%2,%3};"
        : "+f"(d[0]), "+f"(d[1]), "+f"(d[2]), "+f"(d[3])
        : "r"(a[0]), "r"(a[1]), "r"(a[2]), "r"(a[3]), "r"(b[0]), "r"(b[1]));
}

__device__ __forceinline__ uint32_t packbf2(float x, float y) {
    __nv_bfloat162 t = __floats2bfloat162_rn(x, y);
    return *(uint32_t*)&t;
}

// ---------------- scratch --------------------------------------------------
__device__ float g_A[33554432];                 // 134 MB conv activations
__device__ float g_B[8388608];                  // 33.5 MB
__device__ float g_X[16 * 128 * 592];
__device__ float g_H[16 * 128 * 600];
__device__ float g_P1[16 * 128 * 10];
__device__ float g_mean[128];
__device__ float g_var[128];
__device__ double g_stat[512];

__device__ const int c_nidx[16][8] = {
    {1, 4, 5, -1, -1, -1, -1, -1},
    {0, 2, 5, 4, 6, -1, -1, -1},
    {1, 3, 6, 5, 7, -1, -1, -1},
    {2, 7, 6, -1, -1, -1, -1, -1},
    {0, 5, 8, 1, 9, -1, -1, -1},
    {1, 4, 6, 9, 0, 2, 8, 10},
    {2, 5, 7, 10, 1, 3, 9, 11},
    {3, 6, 11, 2, 10, -1, -1, -1},
    {4, 9, 12, 5, 13, -1, -1, -1},
    {5, 8, 10, 13, 4, 6, 12, 14},
    {6, 9, 11, 14, 5, 7, 13, 15},
    {7, 10, 15, 6, 14, -1, -1, -1},
    {8, 13, 9, -1, -1, -1, -1, -1},
    {9, 12, 14, 8, 10, -1, -1, -1},
    {10, 13, 15, 9, 11, -1, -1, -1},
    {11, 14, 10, -1, -1, -1, -1, -1},
};

// ============================================================================
// HMMA bf16x3 implicit-GEMM conv: D[Cout,N] = W[Cout,K] @ im2col[N,K]^T
// BM=128, BN=128, BK=32, 256 thr (8 warps 2Mx4N), 2 CTAs/SM.
// KSPLIT>1: blockIdx.z handles K/KSPLIT; partial z written to
// out + z*Cout*BATCH*HW; bias added only by z==0; reduce happens downstream.
// ============================================================================
static constexpr int HB_DSM = 65536 + 1024;

template<int Cin, int Cout, int H, int W, bool RELU, int KSPLIT = 1>
__global__ __launch_bounds__(256, 2)
void conv_hmma(const float* __restrict__ in, const float* __restrict__ wgt,
               const float* __restrict__ bias, float* __restrict__ out)
{
    constexpr int K  = Cin * 9;
    constexpr int HW = H * W;
    constexpr int NC  = K / 32;
    constexpr int NCZ = NC / KSPLIT;

    extern __shared__ char dsm_raw[];
    const uint32_t sb = (smem_u32(dsm_raw) + 1023u) & ~1023u;

    const int tid  = threadIdx.x;
    const int wid  = tid >> 5;
    const int lane = tid & 31;
    const int wm   = wid & 1;
    const int wn   = wid >> 1;
    const int n0   = blockIdx.x * 128;
    const int m0   = blockIdx.y * 128;
    const int kc0  = (KSPLIT > 1) ? blockIdx.z * NCZ : 0;
    if (KSPLIT > 1) out += (size_t)blockIdx.z * Cout * (BATCH * HW);

    // ---- loader state
    const int lr = tid >> 1;
    const int lh = tid & 1;
    const int gn = n0 + lr;
    const int bidx = gn / HW;
    const int p    = gn & (HW - 1);
    const int y0   = p / W;
    const int x0   = p & (W - 1);
    const float* srcb = in + bidx * Cin * HW;
    const float* wp0  = wgt + (m0 + lr) * K + lh * 16;

    float acc[4][4][4];
    #pragma unroll
    for (int mt = 0; mt < 4; mt++)
        #pragma unroll
        for (int nt = 0; nt < 4; nt++)
            #pragma unroll
            for (int e = 0; e < 4; e++) acc[mt][nt][e] = 0.f;

    auto swz = [](int row, int ch) { return row * 64 + ((ch ^ ((row >> 1) & 3)) << 4); };
    const int c0 = 2 * lh;

    // ---------------- tile loader ----------------
    auto load_tiles = [&](int s, int kc) {
        const uint32_t tb = sb + s * 32768;
        // A: weights, contiguous 16 floats
        {
            const float* wp = wp0 + kc * 32;
            float4 w0 = *(const float4*)(wp + 0);
            float4 w1 = *(const float4*)(wp + 4);
            float4 w2 = *(const float4*)(wp + 8);
            float4 w3 = *(const float4*)(wp + 12);
            float v[16] = {w0.x,w0.y,w0.z,w0.w, w1.x,w1.y,w1.z,w1.w,
                           w2.x,w2.y,w2.z,w2.w, w3.x,w3.y,w3.z,w3.w};
            float hi[16], lo[16];
            #pragma unroll
            for (int j = 0; j < 16; j++) {
                __nv_bfloat16 h = __float2bfloat16(v[j]);
                hi[j] = __bfloat162float(h);
                lo[j] = v[j] - hi[j];
            }
            uint4 H0 = { packbf2(hi[0],hi[1]), packbf2(hi[2],hi[3]),
                         packbf2(hi[4],hi[5]), packbf2(hi[6],hi[7]) };
            uint4 H1 = { packbf2(hi[8],hi[9]), packbf2(hi[10],hi[11]),
                         packbf2(hi[12],hi[13]), packbf2(hi[14],hi[15]) };
            uint4 L0 = { packbf2(lo[0],lo[1]), packbf2(lo[2],lo[3]),
                         packbf2(lo[4],lo[5]), packbf2(lo[6],lo[7]) };
            uint4 L1 = { packbf2(lo[8],lo[9]), packbf2(lo[10],lo[11]),
                         packbf2(lo[12],lo[13]), packbf2(lo[14],lo[15]) };
            asm volatile("st.shared.v4.b32 [%0], {%1,%2,%3,%4};" ::
                "r"(tb + swz(lr, c0)), "r"(H0.x), "r"(H0.y), "r"(H0.z), "r"(H0.w));
            asm volatile("st.shared.v4.b32 [%0], {%1,%2,%3,%4};" ::
                "r"(tb + swz(lr, c0 + 1)), "r"(H1.x), "r"(H1.y), "r"(H1.z), "r"(H1.w));
            asm volatile("st.shared.v4.b32 [%0], {%1,%2,%3,%4};" ::
                "r"(tb + 8192 + swz(lr, c0)), "r"(L0.x), "r"(L0.y), "r"(L0.z), "r"(L0.w));
            asm volatile("st.shared.v4.b32 [%0], {%1,%2,%3,%4};" ::
                "r"(tb + 8192 + swz(lr, c0 + 1)), "r"(L1.x), "r"(L1.y), "r"(L1.z), "r"(L1.w));
        }
        // B: im2col gather, 16 consecutive k
        {
            int k = kc * 32 + lh * 16;
            int ci = k / 9;
            int f  = k - 9 * ci;
            int cioff = ci * HW;
            float v[16];
            #pragma unroll
            for (int j = 0; j < 16; j++) {
                int dy = (f * 11) >> 5;
                int dx = f - 3 * dy;
                int y = y0 + dy - 1, x = x0 + dx - 1;
                v[j] = ((unsigned)y < (unsigned)H && (unsigned)x < (unsigned)W)
                         ? __ldg(srcb + cioff + y * W + x) : 0.f;
                f++; if (f == 9) { f = 0; cioff += HW; }
            }
            float hi[16], lo[16];
            #pragma unroll
            for (int j = 0; j < 16; j++) {
                __nv_bfloat16 h = __float2bfloat16(v[j]);
                hi[j] = __bfloat162float(h);
                lo[j] = v[j] - hi[j];
            }
            uint4 H0 = { packbf2(hi[0],hi[1]), packbf2(hi[2],hi[3]),
                         packbf2(hi[4],hi[5]), packbf2(hi[6],hi[7]) };
            uint4 H1 = { packbf2(hi[8],hi[9]), packbf2(hi[10],hi[11]),
                         packbf2(hi[12],hi[13]), packbf2(hi[14],hi[15]) };
            uint4 L0 = { packbf2(lo[0],lo[1]), packbf2(lo[2],lo[3]),
                         packbf2(lo[4],lo[5]), packbf2(lo[6],lo[7]) };
            uint4 L1 = { packbf2(lo[8],lo[9]), packbf2(lo[10],lo[11]),
                         packbf2(lo[12],lo[13]), packbf2(lo[14],lo[15]) };
            const uint32_t bb = tb + 16384;
            asm volatile("st.shared.v4.b32 [%0], {%1,%2,%3,%4};" ::
                "r"(bb + swz(lr, c0)), "r"(H0.x), "r"(H0.y), "r"(H0.z), "r"(H0.w));
            asm volatile("st.shared.v4.b32 [%0], {%1,%2,%3,%4};" ::
                "r"(bb + swz(lr, c0 + 1)), "r"(H1.x), "r"(H1.y), "r"(H1.z), "r"(H1.w));
            asm volatile("st.shared.v4.b32 [%0], {%1,%2,%3,%4};" ::
                "r"(bb + 8192 + swz(lr, c0)), "r"(L0.x), "r"(L0.y), "r"(L0.z), "r"(L0.w));
            asm volatile("st.shared.v4.b32 [%0], {%1,%2,%3,%4};" ::
                "r"(bb + 8192 + swz(lr, c0 + 1)), "r"(L1.x), "r"(L1.y), "r"(L1.z), "r"(L1.w));
        }
    };

    // ---------------- mainloop ----------------
    load_tiles(0, kc0);
    __syncthreads();

    for (int j = 0; j < NCZ; j++) {
        const int s = j & 1;
        if (j + 1 < NCZ) load_tiles(s ^ 1, kc0 + j + 1);

        const uint32_t aB = sb + s * 32768;
        const uint32_t bB = aB + 16384;

        #pragma unroll
        for (int ks = 0; ks < 2; ks++) {
            // B fragments: one x4 ldmatrix serves 2 n-tiles
            uint32_t bh[4][2], bl[4][2];
            #pragma unroll
            for (int ntp = 0; ntp < 2; ntp++) {
                int row = wn * 32 + ntp * 16 + ((lane >> 4) & 1) * 8 + (lane & 7);
                int ch  = ks * 2 + ((lane >> 3) & 1);
                uint32_t off = swz(row, ch);
                uint32_t t4[4];
                LDMX4(t4, bB + off);
                bh[ntp*2][0] = t4[0]; bh[ntp*2][1] = t4[1];
                bh[ntp*2+1][0] = t4[2]; bh[ntp*2+1][1] = t4[3];
                LDMX4(t4, bB + 8192 + off);
                bl[ntp*2][0] = t4[0]; bl[ntp*2][1] = t4[1];
                bl[ntp*2+1][0] = t4[2]; bl[ntp*2+1][1] = t4[3];
            }
            // A fragments per m-tile, consumed immediately
            const int arow = wm * 64 + (lane & 7) + ((lane >> 3) & 1) * 8;
            const int ach  = ks * 2 + (lane >> 4);
            #pragma unroll
            for (int mt = 0; mt < 4; mt++) {
                uint32_t ah[4], al[4];
                int row = arow + mt * 16;
                uint32_t off = swz(row, ach);
                LDMX4(ah, aB + off);
                LDMX4(al, aB + 8192 + off);
                #pragma unroll
                for (int nt = 0; nt < 4; nt++) {
                    mma_bf16(acc[mt][nt], ah, bh[nt]);
                    mma_bf16(acc[mt][nt], ah, bl[nt]);
                    mma_bf16(acc[mt][nt], al, bh[nt]);
                }
            }
        }
        __syncthreads();
    }

    // ---------------- epilogue ----------------
    #pragma unroll
    for (int mt = 0; mt < 4; mt++) {
        #pragma unroll
        for (int nt = 0; nt < 4; nt++) {
            int r0 = m0 + wm * 64 + mt * 16 + (lane >> 2);
            int cc = n0 + wn * 32 + nt * 8 + ((lane & 3) << 1);
            int b  = cc / HW;
            int pp = cc & (HW - 1);
            #pragma unroll
            for (int hh = 0; hh < 2; hh++) {
                int row = r0 + hh * 8;
                float bv = (KSPLIT == 1 || blockIdx.z == 0) ? bias[row] : 0.f;
                float2 v;
                v.x = acc[mt][nt][hh * 2 + 0] + bv;
                v.y = acc[mt][nt][hh * 2 + 1] + bv;
                if (RELU) { v.x = fmaxf(v.x, 0.f); v.y = fmaxf(v.y, 0.f); }
                *(float2*)&out[(b * Cout + row) * HW + pp] = v;
            }
        }
    }
}

// ============================================================================
// conv1 (3->64, 64x64 SAME) direct conv (fp32, f32x2 accumulation)
// ============================================================================
__global__ __launch_bounds__(256) void conv1_direct(
    const float* __restrict__ in, const float* __restrict__ wgt,
    const float* __restrict__ bias, float* __restrict__ out)
{
    __shared__ __align__(16) float wT[27][64];
    __shared__ float inr[3][3][66];

    const int tid = threadIdx.x;
    const int b   = blockIdx.x >> 6;
    const int y   = blockIdx.x & 63;
    const int x   = tid & 63;
    const int cog = tid >> 6;

    for (int i = tid; i < 1728; i += 256) {
        int co = i / 27, k = i - co * 27;
        wT[k][co] = wgt[i];
    }
    for (int i = tid; i < 594; i += 256) {
        int ci = i / 198, rem = i - ci * 198;
        int dy = rem / 66, xx = rem - dy * 66;
        int yy = y - 1 + dy, gx = xx - 1;
        float v = 0.f;
        if ((unsigned)yy < 64u && (unsigned)gx < 64u)
            v = in[(b * 3 + ci) * 4096 + yy * 64 + gx];
        inr[ci][dy][xx] = v;
    }
    __syncthreads();

    float iv[27];
    #pragma unroll
    for (int ci = 0; ci < 3; ci++)
        #pragma unroll
        for (int dy = 0; dy < 3; dy++)
            #pragma unroll
            for (int dx = 0; dx < 3; dx++)
                iv[ci * 9 + dy * 3 + dx] = inr[ci][dy][x + dx];

    ull acc2[8];
    #pragma unroll
    for (int p = 0; p < 8; p++) {
        float2 bb = *(const float2*)&bias[cog * 16 + p * 2];
        acc2[p] = pack2(bb.x, bb.y);
    }
    #pragma unroll
    for (int k = 0; k < 27; k++) {
        ull v2 = bcast2(iv[k]);
        F4U w0, w1, w2, w3;
        w0.v = *(const float4*)&wT[k][cog * 16 + 0];
        w1.v = *(const float4*)&wT[k][cog * 16 + 4];
        w2.v = *(const float4*)&wT[k][cog * 16 + 8];
        w3.v = *(const float4*)&wT[k][cog * 16 + 12];
        fma2(acc2[0], w0.u[0], v2); fma2(acc2[1], w0.u[1], v2);
        fma2(acc2[2], w1.u[0], v2); fma2(acc2[3], w1.u[1], v2);
        fma2(acc2[4], w2.u[0], v2); fma2(acc2[5], w2.u[1], v2);
        fma2(acc2[6], w3.u[0], v2); fma2(acc2[7], w3.u[1], v2);
    }

    #pragma unroll
    for (int p = 0; p < 8; p++) {
        UF2 u; u.u = acc2[p];
        #pragma unroll
        for (int h = 0; h < 2; h++) {
            int co = cog * 16 + p * 2 + h;
            out[(b * 64 + co) * 4096 + y * 64 + x] = u.f[h];
        }
    }
}

// ---------------- BN stats ---------------------------------------------------
__global__ void zero_stats(double* stat)
{
    if (threadIdx.x < 512) stat[threadIdx.x] = 0.0;
}

__global__ void bn_stats_slab(const float* __restrict__ x, double* __restrict__ stat,
                              int C, int HW, int hwsh)
{
    int c  = blockIdx.x;
    int b0 = blockIdx.y * 8;
    __shared__ double ss[256], sq[256];
    double s = 0.0, q = 0.0;
    int elems = 8 * HW;
    for (int j = threadIdx.x; j < elems; j += 256) {
        int b = b0 + (j >> hwsh);
        int p = j & (HW - 1);
        float v = x[(b * C + c) * HW + p];
        s += (double)v;
        q += (double)v * (double)v;
    }
    ss[threadIdx.x] = s; sq[threadIdx.x] = q;
    __syncthreads();
    for (int st = 128; st > 0; st >>= 1) {
        if (threadIdx.x < st) {
            ss[threadIdx.x] += ss[threadIdx.x + st];
            sq[threadIdx.x] += sq[threadIdx.x + st];
        }
        __syncthreads();
    }
    if (threadIdx.x == 0) {
        atomicAdd(&stat[c],     ss[0]);
        atomicAdd(&stat[C + c], sq[0]);
    }
}

__global__ void finalize_stats(const double* __restrict__ stat,
                               float* __restrict__ mean, float* __restrict__ var,
                               int C, double inv)
{
    int c = threadIdx.x;
    if (c < C) {
        double m = stat[c] * inv;
        mean[c] = (float)m;
        var[c]  = (float)(stat[C + c] * inv - m * m);
    }
}

// ---------------- fused BN-apply + ReLU + MaxPool(3,2,1), 2 outputs/thread --
__global__ void bn_relu_pool2(const float* __restrict__ in, float* __restrict__ out,
                              const float* __restrict__ g, const float* __restrict__ bta,
                              const float* __restrict__ mean, const float* __restrict__ var,
                              int totalp, int H, int owsh, int cmask)
{
    int OW = H >> 1;
    for (int i = blockIdx.x * blockDim.x + threadIdx.x; i < totalp;
         i += gridDim.x * blockDim.x) {
        int oxp = i & ((1 << (owsh - 1)) - 1);
        int t   = i >> (owsh - 1);
        int oy  = t & (OW - 1);
        int bc  = t >> owsh;
        int c   = bc & cmask;
        float scale = g[c] * rsqrtf(var[c] + 1e-5f);
        float shift = bta[c] - mean[c] * scale;
        const float* src = in + (long long)bc * H * H;
        int xb = 4 * oxp - 1;
        float m0 = 0.f, m1 = 0.f;     // relu floor
        #pragma unroll
        for (int dy = 0; dy < 3; dy++) {
            int y = 2 * oy - 1 + dy;
            if ((unsigned)y >= (unsigned)H) continue;
            const float* row = src + y * H;
            float v[5];
            #pragma unroll
            for (int j = 0; j < 5; j++) {
                int x = xb + j;
                v[j] = ((unsigned)x < (unsigned)H) ? fmaf(row[x], scale, shift) : 0.f;
            }
            m0 = fmaxf(m0, fmaxf(fmaxf(v[0], v[1]), v[2]));
            m1 = fmaxf(m1, fmaxf(fmaxf(v[2], v[3]), v[4]));
        }
        float2 o; o.x = m0; o.y = m1;
        *(float2*)&out[(bc * OW + oy) * OW + 2 * oxp] = o;
    }
}

// ---------------- MaxPool2d(3,2,1) ------------------------------------------
__global__ void maxpool3s2(const float* __restrict__ in, float* __restrict__ out,
                           int total, int H, int W, int owsh)
{
    int OW = W >> 1;
    for (int i = blockIdx.x * blockDim.x + threadIdx.x; i < total;
         i += gridDim.x * blockDim.x) {
        int ox = i & (OW - 1);
        int t  = i >> owsh;
        int oy = t & (OW - 1);
        int bc = t >> owsh;
        const float* src = in + (long long)bc * H * W;
        float m = -INFINITY;
        #pragma unroll
        for (int dy = 0; dy < 3; dy++) {
            int y = 2 * oy - 1 + dy;
            if ((unsigned)y >= (unsigned)H) continue;
            #pragma unroll
            for (int dx = 0; dx < 3; dx++) {
                int x = 2 * ox - 1 + dx;
                if ((unsigned)x >= (unsigned)W) continue;
                m = fmaxf(m, src[y * W + x]);
            }
        }
        out[i] = m;
    }
}

// ---------------- MLP stage 1: X @ W1 + b1, tanh ----------------------------
__global__ __launch_bounds__(256) void gemm_bias_tanh(
    const float* __restrict__ A, const float* __restrict__ Bw,
    const float* __restrict__ bias, float* __restrict__ C)
{
    const int M = 128, N = 600, K = 592;
    const int node = blockIdx.z;
    A    += node * M * K;
    Bw   += node * K * N;
    bias += node * N;
    C    += node * M * N;

    __shared__ __align__(16) float As[16][68];
    __shared__ __align__(16) float Bs[16][68];

    const int tid = threadIdx.x;
    const int m0 = blockIdx.y * 64;
    const int n0 = blockIdx.x * 64;
    const int tm = tid >> 4;
    const int tn = tid & 15;

    float acc[4][4] = {};

    for (int k0 = 0; k0 < K; k0 += 16) {
        #pragma unroll
        for (int i = 0; i < 4; i++) {
            int lin = tid + i * 256;
            int kk = lin & 15;
            int mm = lin >> 4;
            As[kk][mm] = A[(m0 + mm) * K + k0 + kk];
        }
        #pragma unroll
        for (int i = 0; i < 4; i++) {
            int lin = tid + i * 256;
            int nn = lin & 63;
            int kk = lin >> 6;
            int gn = n0 + nn;
            Bs[kk][nn] = (gn < N) ? Bw[(k0 + kk) * N + gn] : 0.f;
        }
        __syncthreads();
        #pragma unroll
        for (int kk = 0; kk < 16; kk++) {
            float4 a4 = *(const float4*)&As[kk][tm * 4];
            float4 b4 = *(const float4*)&Bs[kk][tn * 4];
            float av[4] = {a4.x, a4.y, a4.z, a4.w};
            float bv[4] = {b4.x, b4.y, b4.z, b4.w};
            #pragma unroll
            for (int i = 0; i < 4; i++)
                #pragma unroll
                for (int j = 0; j < 4; j++)
                    acc[i][j] = fmaf(av[i], bv[j], acc[i][j]);
        }
        __syncthreads();
    }

    #pragma unroll
    for (int i = 0; i < 4; i++) {
        int m = m0 + tm * 4 + i;
        #pragma unroll
        for (int j = 0; j < 4; j++) {
            int gn = n0 + tn * 4 + j;
            if (gn < N)
                C[m * N + gn] = tanhf(acc[i][j] + bias[gn]);
        }
    }
}

// ---------------- MLP stage 2 + softmax --------------------------------------
__global__ void mlp2_softmax(const float* __restrict__ h, const float* __restrict__ W2,
                             const float* __restrict__ b2, float* __restrict__ out)
{
    int nb = blockIdx.x;
    int node = nb >> 7;
    int b    = nb & 127;
    int lane = threadIdx.x;

    const float* hrow = h  + (node * 128 + b) * 600;
    const float* w    = W2 + node * 600 * 10;

    float acc[10];
    #pragma unroll
    for (int o = 0; o < 10; o++) acc[o] = 0.f;

    for (int i = lane; i < 600; i += 32) {
        float hv = hrow[i];
        const float* wr = w + i * 10;
        #pragma unroll
        for (int o = 0; o < 10; o++)
            acc[o] = fmaf(hv, wr[o], acc[o]);
    }
    #pragma unroll
    for (int o = 0; o < 10; o++)
        #pragma unroll
        for (int s = 16; s > 0; s >>= 1)
            acc[o] += __shfl_down_sync(0xffffffffu, acc[o], s);

    if (lane == 0) {
        float lg[10];
        float mx = -INFINITY;
        #pragma unroll
        for (int o = 0; o < 10; o++) {
            lg[o] = acc[o] + b2[node * 10 + o];
            mx = fmaxf(mx, lg[o]);
        }
        float se = 0.f;
        #pragma unroll
        for (int o = 0; o < 10; o++) { lg[o] = expf(lg[o] - mx); se += lg[o]; }
        float inv = 1.f / se;
        #pragma unroll
        for (int o = 0; o < 10; o++)
            out[(node * 128 + b) * 10 + o] = lg[o] * inv;
    }
}

// ---------------- head glue ---------------------------------------------------
// conv7 comes as 4 split-K partials (stride 1048576 floats); sum + relu here.
__global__ void build_X1(const float* __restrict__ p, float* __restrict__ X, int total)
{
    for (int i = blockIdx.x * blockDim.x + threadIdx.x; i < total;
         i += gridDim.x * blockDim.x) {
        int c = i % 592;
        int t = i / 592;
        int b = t & 127;
        int n = t >> 7;
        float v = 0.f;
        if (c >= 80) {
            int idx = ((b * 512 + (c - 80)) << 4) + n;
            v = p[idx] + p[idx + 1048576] + p[idx + 2097152] + p[idx + 3145728];
            v = fmaxf(v, 0.f);
        }
        X[i] = v;
    }
}

__global__ void build_X2(const float* __restrict__ P1, float* __restrict__ X, int total)
{
    for (int i = blockIdx.x * blockDim.x + threadIdx.x; i < total;
         i += gridDim.x * blockDim.x) {
        int j = i % 80;
        int t = i / 80;
        int b = t & 127;
        int n = t >> 7;
        int s   = j / 10;
        int cls = j - s * 10;
        int nb  = c_nidx[n][s];
        float v = (nb >= 0) ? P1[(nb * 128 + b) * 10 + cls] : 0.f;
        X[(n * 128 + b) * 592 + j] = v;
    }
}

__global__ void final_mean_sq(const float* __restrict__ preds2, float* __restrict__ out)
{
    int t = blockIdx.x * blockDim.x + threadIdx.x;
    if (t >= 1280) return;
    int b = t / 10, c = t - (t / 10) * 10;
    float s = 0.f;
    #pragma unroll
    for (int n = 0; n < 16; n++)
        s += preds2[(n * 128 + b) * 10 + c];
    s *= (1.f / 16.f);
    out[t] = s * s;
}

// ---------------- launcher -----------------------------------------------------
extern "C" void kernel_launch(void* const* d_in, const int* in_sizes, int n_in,
                              void* d_out, int out_size)
{
    const float* x     = (const float*)d_in[0];
    const float* cw1   = (const float*)d_in[1];
    const float* cb1   = (const float*)d_in[2];
    const float* bn1g  = (const float*)d_in[3];
    const float* bn1b  = (const float*)d_in[4];
    const float* cw2   = (const float*)d_in[5];
    const float* cb2   = (const float*)d_in[6];
    const float* bn2g  = (const float*)d_in[7];
    const float* bn2b  = (const float*)d_in[8];
    const float* cw3   = (const float*)d_in[9];
    const float* cb3   = (const float*)d_in[10];
    const float* cw4   = (const float*)d_in[11];
    const float* cb4   = (const float*)d_in[12];
    const float* cw5   = (const float*)d_in[13];
    const float* cb5   = (const float*)d_in[14];
    const float* cw6   = (const float*)d_in[15];
    const float* cb6   = (const float*)d_in[16];
    const float* cw7   = (const float*)d_in[17];
    const float* cb7   = (const float*)d_in[18];
    const float* W1    = (const float*)d_in[19];
    const float* b1    = (const float*)d_in[20];
    const float* W2    = (const float*)d_in[21];
    const float* b2    = (const float*)d_in[22];
    float* out = (float*)d_out;

    float *A, *Bb, *X, *H, *P1, *mean, *var;
    double* stat;
    cudaGetSymbolAddress((void**)&A,    g_A);
    cudaGetSymbolAddress((void**)&Bb,   g_B);
    cudaGetSymbolAddress((void**)&X,    g_X);
    cudaGetSymbolAddress((void**)&H,    g_H);
    cudaGetSymbolAddress((void**)&P1,   g_P1);
    cudaGetSymbolAddress((void**)&mean, g_mean);
    cudaGetSymbolAddress((void**)&var,  g_var);
    cudaGetSymbolAddress((void**)&stat, g_stat);

    cudaFuncSetAttribute(conv_hmma<64, 128, 32, 32, false>, cudaFuncAttributeMaxDynamicSharedMemorySize, HB_DSM);
    cudaFuncSetAttribute(conv_hmma<128, 256, 16, 16, true>, cudaFuncAttributeMaxDynamicSharedMemorySize, HB_DSM);
    cudaFuncSetAttribute(conv_hmma<256, 256, 16, 16, true>, cudaFuncAttributeMaxDynamicSharedMemorySize, HB_DSM);
    cudaFuncSetAttribute(conv_hmma<256, 512, 8, 8, true>,  cudaFuncAttributeMaxDynamicSharedMemorySize, HB_DSM);
    cudaFuncSetAttribute(conv_hmma<512, 512, 8, 8, true>,  cudaFuncAttributeMaxDynamicSharedMemorySize, HB_DSM);
    cudaFuncSetAttribute(conv_hmma<512, 512, 4, 4, false, 4>, cudaFuncAttributeMaxDynamicSharedMemorySize, HB_DSM);

    // ---- zero both BN stat regions once
    zero_stats<<<1, 512>>>(stat);

    // ---- conv1 (3->64, 64x64) + BN + ReLU + pool -> 32x32
    conv1_direct<<<8192, 256>>>(x, cw1, cb1, A);
    bn_stats_slab<<<dim3(64, 16), 256>>>(A, stat, 64, 4096, 12);
    finalize_stats<<<1, 128>>>(stat, mean, var, 64, 1.0 / 524288.0);
    bn_relu_pool2<<<16384, 256>>>(A, Bb, bn1g, bn1b, mean, var, 4194304, 64, 5, 63);

    // ---- conv2 (64->128, 32x32): N=131072
    conv_hmma<64, 128, 32, 32, false><<<dim3(1024, 1), 256, HB_DSM>>>(Bb, cw2, cb2, A);
    bn_stats_slab<<<dim3(128, 16), 256>>>(A, stat + 128, 128, 1024, 10);
    finalize_stats<<<1, 128>>>(stat + 128, mean, var, 128, 1.0 / 131072.0);
    bn_relu_pool2<<<8192, 256>>>(A, Bb, bn2g, bn2b, mean, var, 2097152, 32, 4, 127);

    // ---- conv3 (128->256, 16x16): N=32768
    conv_hmma<128, 256, 16, 16, true><<<dim3(256, 2), 256, HB_DSM>>>(Bb, cw3, cb3, A);
    // ---- conv4 (256->256, 16x16): N=32768 + pool -> 8x8
    conv_hmma<256, 256, 16, 16, true><<<dim3(256, 2), 256, HB_DSM>>>(A, cw4, cb4, Bb);
    maxpool3s2<<<4096, 256>>>(Bb, A, 2097152, 16, 16, 3);

    // ---- conv5 (256->512, 8x8): N=8192
    conv_hmma<256, 512, 8, 8, true><<<dim3(64, 4), 256, HB_DSM>>>(A, cw5, cb5, Bb);
    // ---- conv6 (512->512, 8x8): N=8192 + pool -> 4x4
    conv_hmma<512, 512, 8, 8, true><<<dim3(64, 4), 256, HB_DSM>>>(Bb, cw6, cb6, A);
    maxpool3s2<<<2048, 256>>>(A, Bb, 1048576, 8, 8, 2);

    // ---- conv7 (512->512, 4x4): N=2048, split-K=4 -> partials in A
    conv_hmma<512, 512, 4, 4, false, 4><<<dim3(16, 4, 4), 256, HB_DSM>>>(Bb, cw7, cb7, A);

    // ---- head: pass 1 (build_X1 reduces split-K partials + relu)
    build_X1<<<4736, 256>>>(A, X, 16 * 128 * 592);
    gemm_bias_tanh<<<dim3(10, 2, 16), 256>>>(X, W1, b1, H);
    mlp2_softmax<<<2048, 32>>>(H, W2, b2, P1);

    // ---- head: pass 2
    build_X2<<<640, 256>>>(P1, X, 16 * 128 * 80);
    gemm_bias_tanh<<<dim3(10, 2, 16), 256>>>(X, W1, b1, H);
    mlp2_softmax<<<2048, 32>>>(H, W2, b2, out + 1280);

    final_mean_sq<<<5, 256>>>(out + 1280, out);
}

// round 9
// speedup vs baseline: 2.6800x; 1.0251x over previous
#include <cuda_runtime.h>
#include <cuda_bf16.h>
#include <cstdint>
#include <math.h>

#define BATCH 128
typedef unsigned long long ull;

// ---------------- f32x2 packed helpers (conv1 direct kernel) ---------------
__device__ __forceinline__ void fma2(ull& d, ull a, ull b) {
    asm("fma.rn.f32x2 %0, %1, %2, %0;" : "+l"(d) : "l"(a), "l"(b));
}
__device__ __forceinline__ ull bcast2(float x) {
    ull r; asm("mov.b64 %0, {%1, %1};" : "=l"(r) : "f"(x)); return r;
}
__device__ __forceinline__ ull pack2(float lo, float hi) {
    ull r; asm("mov.b64 %0, {%1, %2};" : "=l"(r) : "f"(lo), "f"(hi)); return r;
}
union F4U { float4 v; ull u[2]; };
union UF2 { ull u; float f[2]; };

// ---------------- HMMA helpers (mma.sync, compute_103-legal) ---------------
__device__ __forceinline__ uint32_t smem_u32(const void* p) {
    uint32_t a;
    asm("{ .reg .u64 t; cvta.to.shared.u64 t, %1; cvt.u32.u64 %0, t; }" : "=r"(a) : "l"(p));
    return a;
}
#define LDMX4(R, ADDR) \
    asm volatile("ldmatrix.sync.aligned.m8n8.x4.shared.b16 {%0,%1,%2,%3}, [%4];" \
        : "=r"((R)[0]), "=r"((R)[1]), "=r"((R)[2]), "=r"((R)[3]) : "r"(ADDR))

__device__ __forceinline__ void mma_bf16(float* d, const uint32_t* a, const uint32_t* b) {
    asm volatile(
        "mma.sync.aligned.m16n8k16.row.col.f32.bf16.bf16.f32 "
        "{%0,%1,%2,%3}, {%4,%5,%6,%7}, {%8,%9}, {%0,%1,%2,%3};"
        : "+f"(d[0]), "+f"(d[1]), "+f"(d[2]), "+f"(d[3])
        : "r"(a[0]), "r"(a[1]), "r"(a[2]), "r"(a[3]), "r"(b[0]), "r"(b[1]));
}

__device__ __forceinline__ uint32_t packbf2(float x, float y) {
    __nv_bfloat162 t = __floats2bfloat162_rn(x, y);
    return *(uint32_t*)&t;
}

// ---------------- scratch --------------------------------------------------
__device__ float g_A[33554432];                 // 134 MB conv activations
__device__ float g_B[8388608];                  // 33.5 MB
__device__ float g_X[16 * 128 * 592];           // F[16,128,512] + neigh[16,128,80]
__device__ float g_H[16 * 128 * 600];           // G
__device__ float g_P1[16 * 128 * 10];
__device__ float g_mean[128];
__device__ float g_var[128];
__device__ double g_stat[512];

__device__ const int c_nidx[16][8] = {
    {1, 4, 5, -1, -1, -1, -1, -1},
    {0, 2, 5, 4, 6, -1, -1, -1},
    {1, 3, 6, 5, 7, -1, -1, -1},
    {2, 7, 6, -1, -1, -1, -1, -1},
    {0, 5, 8, 1, 9, -1, -1, -1},
    {1, 4, 6, 9, 0, 2, 8, 10},
    {2, 5, 7, 10, 1, 3, 9, 11},
    {3, 6, 11, 2, 10, -1, -1, -1},
    {4, 9, 12, 5, 13, -1, -1, -1},
    {5, 8, 10, 13, 4, 6, 12, 14},
    {6, 9, 11, 14, 5, 7, 13, 15},
    {7, 10, 15, 6, 14, -1, -1, -1},
    {8, 13, 9, -1, -1, -1, -1, -1},
    {9, 12, 14, 8, 10, -1, -1, -1},
    {10, 13, 15, 9, 11, -1, -1, -1},
    {11, 14, 10, -1, -1, -1, -1, -1},
};

// ============================================================================
// HMMA bf16x3 implicit-GEMM conv (unchanged from R7 winner)
// ============================================================================
static constexpr int HB_DSM = 65536 + 1024;

template<int Cin, int Cout, int H, int W, bool RELU, int KSPLIT = 1>
__global__ __launch_bounds__(256, 2)
void conv_hmma(const float* __restrict__ in, const float* __restrict__ wgt,
               const float* __restrict__ bias, float* __restrict__ out)
{
    constexpr int K  = Cin * 9;
    constexpr int HW = H * W;
    constexpr int NC  = K / 32;
    constexpr int NCZ = NC / KSPLIT;

    extern __shared__ char dsm_raw[];
    const uint32_t sb = (smem_u32(dsm_raw) + 1023u) & ~1023u;

    const int tid  = threadIdx.x;
    const int wid  = tid >> 5;
    const int lane = tid & 31;
    const int wm   = wid & 1;
    const int wn   = wid >> 1;
    const int n0   = blockIdx.x * 128;
    const int m0   = blockIdx.y * 128;
    const int kc0  = (KSPLIT > 1) ? blockIdx.z * NCZ : 0;
    if (KSPLIT > 1) out += (size_t)blockIdx.z * Cout * (BATCH * HW);

    const int lr = tid >> 1;
    const int lh = tid & 1;
    const int gn = n0 + lr;
    const int bidx = gn / HW;
    const int p    = gn & (HW - 1);
    const int y0   = p / W;
    const int x0   = p & (W - 1);
    const float* srcb = in + bidx * Cin * HW;
    const float* wp0  = wgt + (m0 + lr) * K + lh * 16;

    float acc[4][4][4];
    #pragma unroll
    for (int mt = 0; mt < 4; mt++)
        #pragma unroll
        for (int nt = 0; nt < 4; nt++)
            #pragma unroll
            for (int e = 0; e < 4; e++) acc[mt][nt][e] = 0.f;

    auto swz = [](int row, int ch) { return row * 64 + ((ch ^ ((row >> 1) & 3)) << 4); };
    const int c0 = 2 * lh;

    auto load_tiles = [&](int s, int kc) {
        const uint32_t tb = sb + s * 32768;
        {
            const float* wp = wp0 + kc * 32;
            float4 w0 = *(const float4*)(wp + 0);
            float4 w1 = *(const float4*)(wp + 4);
            float4 w2 = *(const float4*)(wp + 8);
            float4 w3 = *(const float4*)(wp + 12);
            float v[16] = {w0.x,w0.y,w0.z,w0.w, w1.x,w1.y,w1.z,w1.w,
                           w2.x,w2.y,w2.z,w2.w, w3.x,w3.y,w3.z,w3.w};
            float hi[16], lo[16];
            #pragma unroll
            for (int j = 0; j < 16; j++) {
                __nv_bfloat16 h = __float2bfloat16(v[j]);
                hi[j] = __bfloat162float(h);
                lo[j] = v[j] - hi[j];
            }
            uint4 H0 = { packbf2(hi[0],hi[1]), packbf2(hi[2],hi[3]),
                         packbf2(hi[4],hi[5]), packbf2(hi[6],hi[7]) };
            uint4 H1 = { packbf2(hi[8],hi[9]), packbf2(hi[10],hi[11]),
                         packbf2(hi[12],hi[13]), packbf2(hi[14],hi[15]) };
            uint4 L0 = { packbf2(lo[0],lo[1]), packbf2(lo[2],lo[3]),
                         packbf2(lo[4],lo[5]), packbf2(lo[6],lo[7]) };
            uint4 L1 = { packbf2(lo[8],lo[9]), packbf2(lo[10],lo[11]),
                         packbf2(lo[12],lo[13]), packbf2(lo[14],lo[15]) };
            asm volatile("st.shared.v4.b32 [%0], {%1,%2,%3,%4};" ::
                "r"(tb + swz(lr, c0)), "r"(H0.x), "r"(H0.y), "r"(H0.z), "r"(H0.w));
            asm volatile("st.shared.v4.b32 [%0], {%1,%2,%3,%4};" ::
                "r"(tb + swz(lr, c0 + 1)), "r"(H1.x), "r"(H1.y), "r"(H1.z), "r"(H1.w));
            asm volatile("st.shared.v4.b32 [%0], {%1,%2,%3,%4};" ::
                "r"(tb + 8192 + swz(lr, c0)), "r"(L0.x), "r"(L0.y), "r"(L0.z), "r"(L0.w));
            asm volatile("st.shared.v4.b32 [%0], {%1,%2,%3,%4};" ::
                "r"(tb + 8192 + swz(lr, c0 + 1)), "r"(L1.x), "r"(L1.y), "r"(L1.z), "r"(L1.w));
        }
        {
            int k = kc * 32 + lh * 16;
            int ci = k / 9;
            int f  = k - 9 * ci;
            int cioff = ci * HW;
            float v[16];
            #pragma unroll
            for (int j = 0; j < 16; j++) {
                int dy = (f * 11) >> 5;
                int dx = f - 3 * dy;
                int y = y0 + dy - 1, x = x0 + dx - 1;
                v[j] = ((unsigned)y < (unsigned)H && (unsigned)x < (unsigned)W)
                         ? __ldg(srcb + cioff + y * W + x) : 0.f;
                f++; if (f == 9) { f = 0; cioff += HW; }
            }
            float hi[16], lo[16];
            #pragma unroll
            for (int j = 0; j < 16; j++) {
                __nv_bfloat16 h = __float2bfloat16(v[j]);
                hi[j] = __bfloat162float(h);
                lo[j] = v[j] - hi[j];
            }
            uint4 H0 = { packbf2(hi[0],hi[1]), packbf2(hi[2],hi[3]),
                         packbf2(hi[4],hi[5]), packbf2(hi[6],hi[7]) };
            uint4 H1 = { packbf2(hi[8],hi[9]), packbf2(hi[10],hi[11]),
                         packbf2(hi[12],hi[13]), packbf2(hi[14],hi[15]) };
            uint4 L0 = { packbf2(lo[0],lo[1]), packbf2(lo[2],lo[3]),
                         packbf2(lo[4],lo[5]), packbf2(lo[6],lo[7]) };
            uint4 L1 = { packbf2(lo[8],lo[9]), packbf2(lo[10],lo[11]),
                         packbf2(lo[12],lo[13]), packbf2(lo[14],lo[15]) };
            const uint32_t bb = tb + 16384;
            asm volatile("st.shared.v4.b32 [%0], {%1,%2,%3,%4};" ::
                "r"(bb + swz(lr, c0)), "r"(H0.x), "r"(H0.y), "r"(H0.z), "r"(H0.w));
            asm volatile("st.shared.v4.b32 [%0], {%1,%2,%3,%4};" ::
                "r"(bb + swz(lr, c0 + 1)), "r"(H1.x), "r"(H1.y), "r"(H1.z), "r"(H1.w));
            asm volatile("st.shared.v4.b32 [%0], {%1,%2,%3,%4};" ::
                "r"(bb + 8192 + swz(lr, c0)), "r"(L0.x), "r"(L0.y), "r"(L0.z), "r"(L0.w));
            asm volatile("st.shared.v4.b32 [%0], {%1,%2,%3,%4};" ::
                "r"(bb + 8192 + swz(lr, c0 + 1)), "r"(L1.x), "r"(L1.y), "r"(L1.z), "r"(L1.w));
        }
    };

    load_tiles(0, kc0);
    __syncthreads();

    for (int j = 0; j < NCZ; j++) {
        const int s = j & 1;
        if (j + 1 < NCZ) load_tiles(s ^ 1, kc0 + j + 1);

        const uint32_t aB = sb + s * 32768;
        const uint32_t bB = aB + 16384;

        #pragma unroll
        for (int ks = 0; ks < 2; ks++) {
            uint32_t bh[4][2], bl[4][2];
            #pragma unroll
            for (int ntp = 0; ntp < 2; ntp++) {
                int row = wn * 32 + ntp * 16 + ((lane >> 4) & 1) * 8 + (lane & 7);
                int ch  = ks * 2 + ((lane >> 3) & 1);
                uint32_t off = swz(row, ch);
                uint32_t t4[4];
                LDMX4(t4, bB + off);
                bh[ntp*2][0] = t4[0]; bh[ntp*2][1] = t4[1];
                bh[ntp*2+1][0] = t4[2]; bh[ntp*2+1][1] = t4[3];
                LDMX4(t4, bB + 8192 + off);
                bl[ntp*2][0] = t4[0]; bl[ntp*2][1] = t4[1];
                bl[ntp*2+1][0] = t4[2]; bl[ntp*2+1][1] = t4[3];
            }
            const int arow = wm * 64 + (lane & 7) + ((lane >> 3) & 1) * 8;
            const int ach  = ks * 2 + (lane >> 4);
            #pragma unroll
            for (int mt = 0; mt < 4; mt++) {
                uint32_t ah[4], al[4];
                int row = arow + mt * 16;
                uint32_t off = swz(row, ach);
                LDMX4(ah, aB + off);
                LDMX4(al, aB + 8192 + off);
                #pragma unroll
                for (int nt = 0; nt < 4; nt++) {
                    mma_bf16(acc[mt][nt], ah, bh[nt]);
                    mma_bf16(acc[mt][nt], ah, bl[nt]);
                    mma_bf16(acc[mt][nt], al, bh[nt]);
                }
            }
        }
        __syncthreads();
    }

    #pragma unroll
    for (int mt = 0; mt < 4; mt++) {
        #pragma unroll
        for (int nt = 0; nt < 4; nt++) {
            int r0 = m0 + wm * 64 + mt * 16 + (lane >> 2);
            int cc = n0 + wn * 32 + nt * 8 + ((lane & 3) << 1);
            int b  = cc / HW;
            int pp = cc & (HW - 1);
            #pragma unroll
            for (int hh = 0; hh < 2; hh++) {
                int row = r0 + hh * 8;
                float bv = (KSPLIT == 1 || blockIdx.z == 0) ? bias[row] : 0.f;
                float2 v;
                v.x = acc[mt][nt][hh * 2 + 0] + bv;
                v.y = acc[mt][nt][hh * 2 + 1] + bv;
                if (RELU) { v.x = fmaxf(v.x, 0.f); v.y = fmaxf(v.y, 0.f); }
                *(float2*)&out[(b * Cout + row) * HW + pp] = v;
            }
        }
    }
}

// ============================================================================
// conv1 (3->64, 64x64 SAME) direct conv (fp32, f32x2 accumulation)
// ============================================================================
__global__ __launch_bounds__(256) void conv1_direct(
    const float* __restrict__ in, const float* __restrict__ wgt,
    const float* __restrict__ bias, float* __restrict__ out)
{
    __shared__ __align__(16) float wT[27][64];
    __shared__ float inr[3][3][66];

    const int tid = threadIdx.x;
    const int b   = blockIdx.x >> 6;
    const int y   = blockIdx.x & 63;
    const int x   = tid & 63;
    const int cog = tid >> 6;

    for (int i = tid; i < 1728; i += 256) {
        int co = i / 27, k = i - co * 27;
        wT[k][co] = wgt[i];
    }
    for (int i = tid; i < 594; i += 256) {
        int ci = i / 198, rem = i - ci * 198;
        int dy = rem / 66, xx = rem - dy * 66;
        int yy = y - 1 + dy, gx = xx - 1;
        float v = 0.f;
        if ((unsigned)yy < 64u && (unsigned)gx < 64u)
            v = in[(b * 3 + ci) * 4096 + yy * 64 + gx];
        inr[ci][dy][xx] = v;
    }
    __syncthreads();

    float iv[27];
    #pragma unroll
    for (int ci = 0; ci < 3; ci++)
        #pragma unroll
        for (int dy = 0; dy < 3; dy++)
            #pragma unroll
            for (int dx = 0; dx < 3; dx++)
                iv[ci * 9 + dy * 3 + dx] = inr[ci][dy][x + dx];

    ull acc2[8];
    #pragma unroll
    for (int p = 0; p < 8; p++) {
        float2 bb = *(const float2*)&bias[cog * 16 + p * 2];
        acc2[p] = pack2(bb.x, bb.y);
    }
    #pragma unroll
    for (int k = 0; k < 27; k++) {
        ull v2 = bcast2(iv[k]);
        F4U w0, w1, w2, w3;
        w0.v = *(const float4*)&wT[k][cog * 16 + 0];
        w1.v = *(const float4*)&wT[k][cog * 16 + 4];
        w2.v = *(const float4*)&wT[k][cog * 16 + 8];
        w3.v = *(const float4*)&wT[k][cog * 16 + 12];
        fma2(acc2[0], w0.u[0], v2); fma2(acc2[1], w0.u[1], v2);
        fma2(acc2[2], w1.u[0], v2); fma2(acc2[3], w1.u[1], v2);
        fma2(acc2[4], w2.u[0], v2); fma2(acc2[5], w2.u[1], v2);
        fma2(acc2[6], w3.u[0], v2); fma2(acc2[7], w3.u[1], v2);
    }

    #pragma unroll
    for (int p = 0; p < 8; p++) {
        UF2 u; u.u = acc2[p];
        #pragma unroll
        for (int h = 0; h < 2; h++) {
            int co = cog * 16 + p * 2 + h;
            out[(b * 64 + co) * 4096 + y * 64 + x] = u.f[h];
        }
    }
}

// ---------------- BN stats ---------------------------------------------------
__global__ void zero_stats(double* stat)
{
    if (threadIdx.x < 512) stat[threadIdx.x] = 0.0;
}

__global__ void bn_stats_slab(const float* __restrict__ x, double* __restrict__ stat,
                              int C, int HW, int hwsh)
{
    int c  = blockIdx.x;
    int b0 = blockIdx.y * 8;
    __shared__ double ss[256], sq[256];
    double s = 0.0, q = 0.0;
    int elems = 8 * HW;
    for (int j = threadIdx.x; j < elems; j += 256) {
        int b = b0 + (j >> hwsh);
        int p = j & (HW - 1);
        float v = x[(b * C + c) * HW + p];
        s += (double)v;
        q += (double)v * (double)v;
    }
    ss[threadIdx.x] = s; sq[threadIdx.x] = q;
    __syncthreads();
    for (int st = 128; st > 0; st >>= 1) {
        if (threadIdx.x < st) {
            ss[threadIdx.x] += ss[threadIdx.x + st];
            sq[threadIdx.x] += sq[threadIdx.x + st];
        }
        __syncthreads();
    }
    if (threadIdx.x == 0) {
        atomicAdd(&stat[c],     ss[0]);
        atomicAdd(&stat[C + c], sq[0]);
    }
}

__global__ void finalize_stats(const double* __restrict__ stat,
                               float* __restrict__ mean, float* __restrict__ var,
                               int C, double inv)
{
    int c = threadIdx.x;
    if (c < C) {
        double m = stat[c] * inv;
        mean[c] = (float)m;
        var[c]  = (float)(stat[C + c] * inv - m * m);
    }
}

// ---------------- fused BN-apply + ReLU + MaxPool(3,2,1), 2 outputs/thread --
__global__ void bn_relu_pool2(const float* __restrict__ in, float* __restrict__ out,
                              const float* __restrict__ g, const float* __restrict__ bta,
                              const float* __restrict__ mean, const float* __restrict__ var,
                              int totalp, int H, int owsh, int cmask)
{
    int OW = H >> 1;
    for (int i = blockIdx.x * blockDim.x + threadIdx.x; i < totalp;
         i += gridDim.x * blockDim.x) {
        int oxp = i & ((1 << (owsh - 1)) - 1);
        int t   = i >> (owsh - 1);
        int oy  = t & (OW - 1);
        int bc  = t >> owsh;
        int c   = bc & cmask;
        float scale = g[c] * rsqrtf(var[c] + 1e-5f);
        float shift = bta[c] - mean[c] * scale;
        const float* src = in + (long long)bc * H * H;
        int xb = 4 * oxp - 1;
        float m0 = 0.f, m1 = 0.f;
        #pragma unroll
        for (int dy = 0; dy < 3; dy++) {
            int y = 2 * oy - 1 + dy;
            if ((unsigned)y >= (unsigned)H) continue;
            const float* row = src + y * H;
            float v[5];
            #pragma unroll
            for (int j = 0; j < 5; j++) {
                int x = xb + j;
                v[j] = ((unsigned)x < (unsigned)H) ? fmaf(row[x], scale, shift) : 0.f;
            }
            m0 = fmaxf(m0, fmaxf(fmaxf(v[0], v[1]), v[2]));
            m1 = fmaxf(m1, fmaxf(fmaxf(v[2], v[3]), v[4]));
        }
        float2 o; o.x = m0; o.y = m1;
        *(float2*)&out[(bc * OW + oy) * OW + 2 * oxp] = o;
    }
}

// ---------------- MaxPool2d(3,2,1) ------------------------------------------
__global__ void maxpool3s2(const float* __restrict__ in, float* __restrict__ out,
                           int total, int H, int W, int owsh)
{
    int OW = W >> 1;
    for (int i = blockIdx.x * blockDim.x + threadIdx.x; i < total;
         i += gridDim.x * blockDim.x) {
        int ox = i & (OW - 1);
        int t  = i >> owsh;
        int oy = t & (OW - 1);
        int bc = t >> owsh;
        const float* src = in + (long long)bc * H * W;
        float m = -INFINITY;
        #pragma unroll
        for (int dy = 0; dy < 3; dy++) {
            int y = 2 * oy - 1 + dy;
            if ((unsigned)y >= (unsigned)H) continue;
            #pragma unroll
            for (int dx = 0; dx < 3; dx++) {
                int x = 2 * ox - 1 + dx;
                if ((unsigned)x >= (unsigned)W) continue;
                m = fmaxf(m, src[y * W + x]);
            }
        }
        out[i] = m;
    }
}

// ---------------- head: G = F @ W1[80:592] + b1 (K=512, no tanh) -----------
__global__ __launch_bounds__(256) void gemm_feats(
    const float* __restrict__ A, const float* __restrict__ Bw,
    const float* __restrict__ bias, float* __restrict__ C)
{
    const int M = 128, N = 600, KA = 512;
    const int node = blockIdx.z;
    A    += node * M * KA;
    Bw   += node * 592 * N + 80 * N;     // rows 80..591
    bias += node * N;
    C    += node * M * N;

    __shared__ __align__(16) float As[16][68];
    __shared__ __align__(16) float Bs[16][68];

    const int tid = threadIdx.x;
    const int m0 = blockIdx.y * 64;
    const int n0 = blockIdx.x * 64;
    const int tm = tid >> 4;
    const int tn = tid & 15;

    float acc[4][4] = {};

    for (int k0 = 0; k0 < KA; k0 += 16) {
        #pragma unroll
        for (int i = 0; i < 4; i++) {
            int lin = tid + i * 256;
            int kk = lin & 15;
            int mm = lin >> 4;
            As[kk][mm] = A[(m0 + mm) * KA + k0 + kk];
        }
        #pragma unroll
        for (int i = 0; i < 4; i++) {
            int lin = tid + i * 256;
            int nn = lin & 63;
            int kk = lin >> 6;
            int gn = n0 + nn;
            Bs[kk][nn] = (gn < N) ? Bw[(k0 + kk) * N + gn] : 0.f;
        }
        __syncthreads();
        #pragma unroll
        for (int kk = 0; kk < 16; kk++) {
            float4 a4 = *(const float4*)&As[kk][tm * 4];
            float4 b4 = *(const float4*)&Bs[kk][tn * 4];
            float av[4] = {a4.x, a4.y, a4.z, a4.w};
            float bv[4] = {b4.x, b4.y, b4.z, b4.w};
            #pragma unroll
            for (int i = 0; i < 4; i++)
                #pragma unroll
                for (int j = 0; j < 4; j++)
                    acc[i][j] = fmaf(av[i], bv[j], acc[i][j]);
        }
        __syncthreads();
    }

    #pragma unroll
    for (int i = 0; i < 4; i++) {
        int m = m0 + tm * 4 + i;
        #pragma unroll
        for (int j = 0; j < 4; j++) {
            int gn = n0 + tn * 4 + j;
            if (gn < N)
                C[m * N + gn] = acc[i][j] + bias[gn];
        }
    }
}

// ---------------- head: G += neigh @ W1[0:80] (K=80) ------------------------
__global__ __launch_bounds__(256) void gemm_neigh_add(
    const float* __restrict__ A, const float* __restrict__ Bw,
    float* __restrict__ C)
{
    const int M = 128, N = 600, KA = 80;
    const int node = blockIdx.z;
    A  += node * M * KA;
    Bw += node * 592 * N;                // rows 0..79
    C  += node * M * N;

    __shared__ __align__(16) float As[16][68];
    __shared__ __align__(16) float Bs[16][68];

    const int tid = threadIdx.x;
    const int m0 = blockIdx.y * 64;
    const int n0 = blockIdx.x * 64;
    const int tm = tid >> 4;
    const int tn = tid & 15;

    float acc[4][4] = {};

    for (int k0 = 0; k0 < KA; k0 += 16) {
        #pragma unroll
        for (int i = 0; i < 4; i++) {
            int lin = tid + i * 256;
            int kk = lin & 15;
            int mm = lin >> 4;
            As[kk][mm] = A[(m0 + mm) * KA + k0 + kk];
        }
        #pragma unroll
        for (int i = 0; i < 4; i++) {
            int lin = tid + i * 256;
            int nn = lin & 63;
            int kk = lin >> 6;
            int gn = n0 + nn;
            Bs[kk][nn] = (gn < N) ? Bw[(k0 + kk) * N + gn] : 0.f;
        }
        __syncthreads();
        #pragma unroll
        for (int kk = 0; kk < 16; kk++) {
            float4 a4 = *(const float4*)&As[kk][tm * 4];
            float4 b4 = *(const float4*)&Bs[kk][tn * 4];
            float av[4] = {a4.x, a4.y, a4.z, a4.w};
            float bv[4] = {b4.x, b4.y, b4.z, b4.w};
            #pragma unroll
            for (int i = 0; i < 4; i++)
                #pragma unroll
                for (int j = 0; j < 4; j++)
                    acc[i][j] = fmaf(av[i], bv[j], acc[i][j]);
        }
        __syncthreads();
    }

    #pragma unroll
    for (int i = 0; i < 4; i++) {
        int m = m0 + tm * 4 + i;
        #pragma unroll
        for (int j = 0; j < 4; j++) {
            int gn = n0 + tn * 4 + j;
            if (gn < N)
                C[m * N + gn] += acc[i][j];
        }
    }
}

// ---------------- MLP stage 2 + softmax (tanh fused on load) ----------------
__global__ void mlp2_softmax_tanh(const float* __restrict__ h, const float* __restrict__ W2,
                                  const float* __restrict__ b2, float* __restrict__ out)
{
    int nb = blockIdx.x;
    int node = nb >> 7;
    int b    = nb & 127;
    int lane = threadIdx.x;

    const float* hrow = h  + (node * 128 + b) * 600;
    const float* w    = W2 + node * 600 * 10;

    float acc[10];
    #pragma unroll
    for (int o = 0; o < 10; o++) acc[o] = 0.f;

    for (int i = lane; i < 600; i += 32) {
        float hv = tanhf(hrow[i]);
        const float* wr = w + i * 10;
        #pragma unroll
        for (int o = 0; o < 10; o++)
            acc[o] = fmaf(hv, wr[o], acc[o]);
    }
    #pragma unroll
    for (int o = 0; o < 10; o++)
        #pragma unroll
        for (int s = 16; s > 0; s >>= 1)
            acc[o] += __shfl_down_sync(0xffffffffu, acc[o], s);

    if (lane == 0) {
        float lg[10];
        float mx = -INFINITY;
        #pragma unroll
        for (int o = 0; o < 10; o++) {
            lg[o] = acc[o] + b2[node * 10 + o];
            mx = fmaxf(mx, lg[o]);
        }
        float se = 0.f;
        #pragma unroll
        for (int o = 0; o < 10; o++) { lg[o] = expf(lg[o] - mx); se += lg[o]; }
        float inv = 1.f / se;
        #pragma unroll
        for (int o = 0; o < 10; o++)
            out[(node * 128 + b) * 10 + o] = lg[o] * inv;
    }
}

// ---------------- head glue ---------------------------------------------------
// F[n,b,cf] = relu(sum of conv7 split-K partials), cf in [0,512)
__global__ void build_F(const float* __restrict__ p, float* __restrict__ F, int total)
{
    for (int i = blockIdx.x * blockDim.x + threadIdx.x; i < total;
         i += gridDim.x * blockDim.x) {
        int cf = i & 511;
        int t  = i >> 9;
        int b  = t & 127;
        int n  = t >> 7;
        int idx = ((b * 512 + cf) << 4) + n;
        float v = p[idx] + p[idx + 1048576] + p[idx + 2097152] + p[idx + 3145728];
        F[i] = fmaxf(v, 0.f);
    }
}

__global__ void build_neigh(const float* __restrict__ P1, float* __restrict__ NG, int total)
{
    for (int i = blockIdx.x * blockDim.x + threadIdx.x; i < total;
         i += gridDim.x * blockDim.x) {
        int j = i % 80;
        int t = i / 80;
        int b = t & 127;
        int n = t >> 7;
        int s   = j / 10;
        int cls = j - s * 10;
        int nb  = c_nidx[n][s];
        float v = (nb >= 0) ? P1[(nb * 128 + b) * 10 + cls] : 0.f;
        NG[(n * 128 + b) * 80 + j] = v;
    }
}

__global__ void final_mean_sq(const float* __restrict__ preds2, float* __restrict__ out)
{
    int t = blockIdx.x * blockDim.x + threadIdx.x;
    if (t >= 1280) return;
    int b = t / 10, c = t - (t / 10) * 10;
    float s = 0.f;
    #pragma unroll
    for (int n = 0; n < 16; n++)
        s += preds2[(n * 128 + b) * 10 + c];
    s *= (1.f / 16.f);
    out[t] = s * s;
}

// ---------------- launcher -----------------------------------------------------
extern "C" void kernel_launch(void* const* d_in, const int* in_sizes, int n_in,
                              void* d_out, int out_size)
{
    const float* x     = (const float*)d_in[0];
    const float* cw1   = (const float*)d_in[1];
    const float* cb1   = (const float*)d_in[2];
    const float* bn1g  = (const float*)d_in[3];
    const float* bn1b  = (const float*)d_in[4];
    const float* cw2   = (const float*)d_in[5];
    const float* cb2   = (const float*)d_in[6];
    const float* bn2g  = (const float*)d_in[7];
    const float* bn2b  = (const float*)d_in[8];
    const float* cw3   = (const float*)d_in[9];
    const float* cb3   = (const float*)d_in[10];
    const float* cw4   = (const float*)d_in[11];
    const float* cb4   = (const float*)d_in[12];
    const float* cw5   = (const float*)d_in[13];
    const float* cb5   = (const float*)d_in[14];
    const float* cw6   = (const float*)d_in[15];
    const float* cb6   = (const float*)d_in[16];
    const float* cw7   = (const float*)d_in[17];
    const float* cb7   = (const float*)d_in[18];
    const float* W1    = (const float*)d_in[19];
    const float* b1    = (const float*)d_in[20];
    const float* W2    = (const float*)d_in[21];
    const float* b2    = (const float*)d_in[22];
    float* out = (float*)d_out;

    float *A, *Bb, *X, *G, *P1, *mean, *var;
    double* stat;
    cudaGetSymbolAddress((void**)&A,    g_A);
    cudaGetSymbolAddress((void**)&Bb,   g_B);
    cudaGetSymbolAddress((void**)&X,    g_X);
    cudaGetSymbolAddress((void**)&G,    g_H);
    cudaGetSymbolAddress((void**)&P1,   g_P1);
    cudaGetSymbolAddress((void**)&mean, g_mean);
    cudaGetSymbolAddress((void**)&var,  g_var);
    cudaGetSymbolAddress((void**)&stat, g_stat);

    float* F  = X;                 // 16*128*512 floats
    float* NG = X + 1048576;       // 16*128*80 floats

    cudaFuncSetAttribute(conv_hmma<64, 128, 32, 32, false>, cudaFuncAttributeMaxDynamicSharedMemorySize, HB_DSM);
    cudaFuncSetAttribute(conv_hmma<128, 256, 16, 16, true>, cudaFuncAttributeMaxDynamicSharedMemorySize, HB_DSM);
    cudaFuncSetAttribute(conv_hmma<256, 256, 16, 16, true>, cudaFuncAttributeMaxDynamicSharedMemorySize, HB_DSM);
    cudaFuncSetAttribute(conv_hmma<256, 512, 8, 8, true>,  cudaFuncAttributeMaxDynamicSharedMemorySize, HB_DSM);
    cudaFuncSetAttribute(conv_hmma<512, 512, 8, 8, true>,  cudaFuncAttributeMaxDynamicSharedMemorySize, HB_DSM);
    cudaFuncSetAttribute(conv_hmma<512, 512, 4, 4, false, 4>, cudaFuncAttributeMaxDynamicSharedMemorySize, HB_DSM);

    zero_stats<<<1, 512>>>(stat);

    // ---- conv1 (3->64, 64x64) + BN + ReLU + pool -> 32x32
    conv1_direct<<<8192, 256>>>(x, cw1, cb1, A);
    bn_stats_slab<<<dim3(64, 16), 256>>>(A, stat, 64, 4096, 12);
    finalize_stats<<<1, 128>>>(stat, mean, var, 64, 1.0 / 524288.0);
    bn_relu_pool2<<<16384, 256>>>(A, Bb, bn1g, bn1b, mean, var, 4194304, 64, 5, 63);

    // ---- conv2 (64->128, 32x32)
    conv_hmma<64, 128, 32, 32, false><<<dim3(1024, 1), 256, HB_DSM>>>(Bb, cw2, cb2, A);
    bn_stats_slab<<<dim3(128, 16), 256>>>(A, stat + 128, 128, 1024, 10);
    finalize_stats<<<1, 128>>>(stat + 128, mean, var, 128, 1.0 / 131072.0);
    bn_relu_pool2<<<8192, 256>>>(A, Bb, bn2g, bn2b, mean, var, 2097152, 32, 4, 127);

    // ---- conv3 / conv4 + pool
    conv_hmma<128, 256, 16, 16, true><<<dim3(256, 2), 256, HB_DSM>>>(Bb, cw3, cb3, A);
    conv_hmma<256, 256, 16, 16, true><<<dim3(256, 2), 256, HB_DSM>>>(A, cw4, cb4, Bb);
    maxpool3s2<<<4096, 256>>>(Bb, A, 2097152, 16, 16, 3);

    // ---- conv5 / conv6 + pool
    conv_hmma<256, 512, 8, 8, true><<<dim3(64, 4), 256, HB_DSM>>>(A, cw5, cb5, Bb);
    conv_hmma<512, 512, 8, 8, true><<<dim3(64, 4), 256, HB_DSM>>>(Bb, cw6, cb6, A);
    maxpool3s2<<<2048, 256>>>(A, Bb, 1048576, 8, 8, 2);

    // ---- conv7 split-K=4 -> partials in A
    conv_hmma<512, 512, 4, 4, false, 4><<<dim3(16, 4, 4), 256, HB_DSM>>>(Bb, cw7, cb7, A);

    // ---- head (restructured): shared feats GEMM computed once
    build_F<<<1024, 256>>>(A, F, 1048576);
    gemm_feats<<<dim3(10, 2, 16), 256>>>(F, W1, b1, G);

    // pass 1: tanh fused into mlp2
    mlp2_softmax_tanh<<<2048, 32>>>(G, W2, b2, P1);

    // pass 2: add neighbor contribution (K=80), then mlp2 again
    build_neigh<<<640, 256>>>(P1, NG, 163840);
    gemm_neigh_add<<<dim3(10, 2, 16), 256>>>(NG, W1, G);
    mlp2_softmax_tanh<<<2048, 32>>>(G, W2, b2, out + 1280);

    final_mean_sq<<<5, 256>>>(out + 1280, out);
}